// round 2
// baseline (speedup 1.0000x reference)
#include <cuda_runtime.h>
#include <math.h>

#define B_    8
#define N_    2304
#define C_    192
#define HW_   48
#define HD_   64
#define NMAX_ 2209   // 47*47

// ---------------- scratch (no allocation allowed; __device__ globals) ----------------
__device__ float g_q[B_ * N_ * C_];          // Q projection (B,N,192)
__device__ float g_xr[B_ * NMAX_ * C_];      // conv/LN/GELU activations (B,n,192)
__device__ float g_kv[B_ * NMAX_ * 128];     // K (cols 0..63) | V (cols 64..127)
__device__ float g_v2[B_ * NMAX_ * HD_];     // V + depthwise conv
__device__ float g_xcat[B_ * N_ * C_];       // concat of 3 branch outputs
__device__ float g_wt[C_ * C_ * 64];         // transposed conv weights [kyx][ci][co]

// =====================================================================================
// Generic GEMM: out[m, n0+j] = A[m,:K] @ W[:, n0+j] + bias[n0+j]
// A row-major lda=K ; W row-major ldw ; tiles 128x64, BK=16, 256 thr, 8x4 micro.
// =====================================================================================
__global__ __launch_bounds__(256) void gemm_kernel(
    const float* __restrict__ A, const float* __restrict__ W,
    const float* __restrict__ bias, float* __restrict__ out,
    int M, int K, int ldw, int ldc)
{
    __shared__ float As[16][132];
    __shared__ float Ws[16][68];
    const int tid = threadIdx.x;
    const int tx = tid & 15, ty = tid >> 4;
    const int m0 = blockIdx.x * 128;
    const int n0 = blockIdx.y * 64;

    float acc[8][4];
#pragma unroll
    for (int i = 0; i < 8; i++)
#pragma unroll
        for (int j = 0; j < 4; j++) acc[i][j] = 0.f;

    for (int k0 = 0; k0 < K; k0 += 16) {
#pragma unroll
        for (int i = 0; i < 8; i++) {
            int r = ty + i * 16;
            int m = m0 + r;
            As[tx][r] = (m < M) ? A[(size_t)m * K + (k0 + tx)] : 0.f;
        }
#pragma unroll
        for (int i = 0; i < 4; i++) {
            int e = tid + i * 256;
            int c = e >> 6, j = e & 63;
            Ws[c][j] = W[(size_t)(k0 + c) * ldw + (n0 + j)];
        }
        __syncthreads();
#pragma unroll
        for (int kk = 0; kk < 16; kk++) {
            float a[8], w[4];
#pragma unroll
            for (int i = 0; i < 8; i++) a[i] = As[kk][ty * 8 + i];
#pragma unroll
            for (int j = 0; j < 4; j++) w[j] = Ws[kk][tx * 4 + j];
#pragma unroll
            for (int i = 0; i < 8; i++)
#pragma unroll
                for (int j = 0; j < 4; j++) acc[i][j] += a[i] * w[j];
        }
        __syncthreads();
    }
#pragma unroll
    for (int i = 0; i < 8; i++) {
        int m = m0 + ty * 8 + i;
        if (m >= M) continue;
#pragma unroll
        for (int j = 0; j < 4; j++) {
            int col = n0 + tx * 4 + j;
            out[(size_t)m * ldc + col] = acc[i][j] + bias[col];
        }
    }
}

// =====================================================================================
// Weight transform: w[co][ci][ky][kx] (OIHW) -> wt[kyx][ci][co]  (coalesced B tiles)
// =====================================================================================
__global__ void wtrans_kernel(const float* __restrict__ w, float* __restrict__ wt, int ksz)
{
    int k2 = ksz * ksz;
    int total = C_ * C_ * k2;
    for (int idx = blockIdx.x * blockDim.x + threadIdx.x; idx < total;
         idx += gridDim.x * blockDim.x) {
        int co = idx % C_;
        int rest = idx / C_;
        int ci = rest % C_;
        int kyx = rest / C_;
        wt[idx] = w[((size_t)co * C_ + ci) * k2 + kyx];
    }
}

// =====================================================================================
// SR conv as implicit GEMM:
// out[b, p, co] = bias[co] + sum_{ky,kx,ci} x[b, (y+ky)*48 + (x+kx), ci] * wt[kyx][ci][co]
// x layout (B, N=H*W, C) with C contiguous. Valid conv, stride 1, output s x s.
// =====================================================================================
__global__ __launch_bounds__(256) void conv_gemm_kernel(
    const float* __restrict__ x, const float* __restrict__ wt,
    const float* __restrict__ bias, float* __restrict__ out,
    int s, int ksz)
{
    __shared__ float As[16][132];
    __shared__ float Ws[16][68];
    const int tid = threadIdx.x;
    const int tx = tid & 15, ty = tid >> 4;
    const int b = blockIdx.z;
    const int n = s * s;
    const int m0 = blockIdx.x * 128;
    const int n0 = blockIdx.y * 64;

    // per-load-row (r = ty + i*16) base offsets (constant over the K loop)
    int rowoff[8];
    bool valid[8];
#pragma unroll
    for (int i = 0; i < 8; i++) {
        int p = m0 + ty + i * 16;
        valid[i] = (p < n);
        int pp = valid[i] ? p : 0;
        int y = pp / s;
        int x0 = pp - y * s;
        rowoff[i] = (y * HW_ + x0) * C_;
    }
    const float* xb = x + (size_t)b * N_ * C_;

    float acc[8][4];
#pragma unroll
    for (int i = 0; i < 8; i++)
#pragma unroll
        for (int j = 0; j < 4; j++) acc[i][j] = 0.f;

    const int nk = ksz * ksz;
    for (int kyx = 0; kyx < nk; kyx++) {
        const int ky = kyx / ksz, kx = kyx - ky * ksz;
        const int koff = (ky * HW_ + kx) * C_ + tx;
        const float* wtk = wt + (size_t)kyx * C_ * C_ + n0;
        for (int ci0 = 0; ci0 < C_; ci0 += 16) {
#pragma unroll
            for (int i = 0; i < 8; i++) {
                int r = ty + i * 16;
                float v = 0.f;
                if (valid[i]) v = xb[rowoff[i] + koff + ci0];
                As[tx][r] = v;
            }
#pragma unroll
            for (int i = 0; i < 4; i++) {
                int e = tid + i * 256;
                int c = e >> 6, j = e & 63;
                Ws[c][j] = wtk[(size_t)(ci0 + c) * C_ + j];
            }
            __syncthreads();
#pragma unroll
            for (int kk = 0; kk < 16; kk++) {
                float a[8], w[4];
#pragma unroll
                for (int i = 0; i < 8; i++) a[i] = As[kk][ty * 8 + i];
#pragma unroll
                for (int j = 0; j < 4; j++) w[j] = Ws[kk][tx * 4 + j];
#pragma unroll
                for (int i = 0; i < 8; i++)
#pragma unroll
                    for (int j = 0; j < 4; j++) acc[i][j] += a[i] * w[j];
            }
            __syncthreads();
        }
    }
#pragma unroll
    for (int i = 0; i < 8; i++) {
        int p = m0 + ty * 8 + i;
        if (p >= n) continue;
#pragma unroll
        for (int j = 0; j < 4; j++) {
            int col = n0 + tx * 4 + j;
            out[((size_t)b * n + p) * C_ + col] = acc[i][j] + bias[col];
        }
    }
}

// =====================================================================================
// Fused LayerNorm + exact GELU (in-place on rows of length C=192). One warp per row.
// =====================================================================================
__global__ void ln_gelu_kernel(float* __restrict__ xr, const float* __restrict__ g,
                               const float* __restrict__ bb, int rows)
{
    int wid = (blockIdx.x * blockDim.x + threadIdx.x) >> 5;
    int lane = threadIdx.x & 31;
    if (wid >= rows) return;
    float* row = xr + (size_t)wid * C_;
    float s1 = 0.f, s2 = 0.f;
#pragma unroll
    for (int j = lane; j < C_; j += 32) {
        float v = row[j];
        s1 += v;
        s2 += v * v;
    }
#pragma unroll
    for (int o = 16; o; o >>= 1) {
        s1 += __shfl_xor_sync(0xffffffffu, s1, o);
        s2 += __shfl_xor_sync(0xffffffffu, s2, o);
    }
    float mu = s1 * (1.f / C_);
    float var = s2 * (1.f / C_) - mu * mu;
    float inv = rsqrtf(var + 1e-5f);
#pragma unroll
    for (int j = lane; j < C_; j += 32) {
        float v = (row[j] - mu) * inv * g[j] + bb[j];
        row[j] = 0.5f * v * (1.f + erff(v * 0.70710678118654752440f));
    }
}

// =====================================================================================
// Depthwise 3x3 (pad 1) on V + residual:  v2 = v + dwconv(v)
// V lives at g_kv[..., 64..127] (ld 128).
// =====================================================================================
__global__ void dwconv_kernel(const float* __restrict__ kv, const float* __restrict__ w,
                              const float* __restrict__ bias, float* __restrict__ v2, int s)
{
    int n = s * s;
    int total = B_ * n * HD_;
    int idx = blockIdx.x * blockDim.x + threadIdx.x;
    if (idx >= total) return;
    int hd = idx & 63;
    int p = (idx >> 6) % n;
    int b = idx / (n * 64);
    int y = p / s;
    int x0 = p - y * s;
    const float* vb = kv + (size_t)b * n * 128 + 64 + hd;
    float acc = bias[hd];
#pragma unroll
    for (int dy = -1; dy <= 1; dy++) {
#pragma unroll
        for (int dx = -1; dx <= 1; dx++) {
            int yy = y + dy, xx = x0 + dx;
            if (yy >= 0 && yy < s && xx >= 0 && xx < s)
                acc += w[hd * 9 + (dy + 1) * 3 + (dx + 1)] * vb[(size_t)(yy * s + xx) * 128];
        }
    }
    v2[idx] = acc + vb[(size_t)p * 128];
}

// =====================================================================================
// Flash attention: per (b, 64-query tile):  out = softmax(q_h @ K^T * scale) @ V2
// K chunks of 64. 256 threads, 4x4 micro-tile. Dynamic smem (4 * 64*65 floats).
// =====================================================================================
__global__ __launch_bounds__(256) void attn_kernel(
    const float* __restrict__ q, const float* __restrict__ kv,
    const float* __restrict__ v2, float* __restrict__ xcat,
    int nkv, int head)
{
    extern __shared__ float sm[];
    float (*qs)[65] = (float (*)[65])sm;
    float (*ks)[65] = (float (*)[65])(sm + 64 * 65);
    float (*vs)[65] = (float (*)[65])(sm + 2 * 64 * 65);
    float (*ps)[65] = (float (*)[65])(sm + 3 * 64 * 65);

    const int tid = threadIdx.x;
    const int tx = tid & 15, ty = tid >> 4;
    const int b = blockIdx.y;
    const int q0 = blockIdx.x * 64;
    const float scale = 0.07216878364870322056f;  // 1/sqrt(192)

#pragma unroll
    for (int i = 0; i < 16; i++) {
        int e = tid + i * 256;
        int r = e >> 6, d = e & 63;
        qs[r][d] = q[((size_t)b * N_ + q0 + r) * C_ + head * HD_ + d];
    }

    float m_i[4], l_i[4], o[4][4];
#pragma unroll
    for (int i = 0; i < 4; i++) {
        m_i[i] = -1e30f;
        l_i[i] = 0.f;
#pragma unroll
        for (int j = 0; j < 4; j++) o[i][j] = 0.f;
    }
    __syncthreads();

    const int nchunks = (nkv + 63) >> 6;
    for (int c0 = 0; c0 < nchunks; c0++) {
        int base = c0 * 64;
        int cs = nkv - base;
        if (cs > 64) cs = 64;
#pragma unroll
        for (int i = 0; i < 16; i++) {
            int e = tid + i * 256;
            int r = e >> 6, d = e & 63;
            if (r < cs) {
                size_t kidx = (size_t)b * nkv + base + r;
                ks[r][d] = kv[kidx * 128 + d];
                vs[r][d] = v2[kidx * 64 + d];
            } else {
                ks[r][d] = 0.f;
                vs[r][d] = 0.f;
            }
        }
        __syncthreads();

        float sacc[4][4];
#pragma unroll
        for (int i = 0; i < 4; i++)
#pragma unroll
            for (int j = 0; j < 4; j++) sacc[i][j] = 0.f;

        for (int d = 0; d < 64; d++) {
            float a[4], bb[4];
#pragma unroll
            for (int i = 0; i < 4; i++) a[i] = qs[ty * 4 + i][d];
#pragma unroll
            for (int j = 0; j < 4; j++) bb[j] = ks[tx * 4 + j][d];
#pragma unroll
            for (int i = 0; i < 4; i++)
#pragma unroll
                for (int j = 0; j < 4; j++) sacc[i][j] += a[i] * bb[j];
        }
#pragma unroll
        for (int i = 0; i < 4; i++)
#pragma unroll
            for (int j = 0; j < 4; j++) {
                float v = sacc[i][j] * scale;
                if (tx * 4 + j >= cs) v = -1e30f;
                sacc[i][j] = v;
            }

#pragma unroll
        for (int i = 0; i < 4; i++) {
            float mx = fmaxf(fmaxf(sacc[i][0], sacc[i][1]), fmaxf(sacc[i][2], sacc[i][3]));
#pragma unroll
            for (int off = 1; off < 16; off <<= 1)
                mx = fmaxf(mx, __shfl_xor_sync(0xffffffffu, mx, off));
            float mnew = fmaxf(m_i[i], mx);
            float alpha = __expf(m_i[i] - mnew);
            float rs = 0.f;
#pragma unroll
            for (int j = 0; j < 4; j++) {
                float p = __expf(sacc[i][j] - mnew);
                sacc[i][j] = p;
                rs += p;
            }
#pragma unroll
            for (int off = 1; off < 16; off <<= 1)
                rs += __shfl_xor_sync(0xffffffffu, rs, off);
            l_i[i] = l_i[i] * alpha + rs;
            m_i[i] = mnew;
#pragma unroll
            for (int j = 0; j < 4; j++) o[i][j] *= alpha;
        }

#pragma unroll
        for (int i = 0; i < 4; i++)
#pragma unroll
            for (int j = 0; j < 4; j++) ps[ty * 4 + i][tx * 4 + j] = sacc[i][j];
        __syncthreads();

        for (int jj = 0; jj < 64; jj++) {
            float pv[4], vv[4];
#pragma unroll
            for (int i = 0; i < 4; i++) pv[i] = ps[ty * 4 + i][jj];
#pragma unroll
            for (int j = 0; j < 4; j++) vv[j] = vs[jj][tx * 4 + j];
#pragma unroll
            for (int i = 0; i < 4; i++)
#pragma unroll
                for (int j = 0; j < 4; j++) o[i][j] += pv[i] * vv[j];
        }
        __syncthreads();
    }

#pragma unroll
    for (int i = 0; i < 4; i++) {
        float inv = 1.f / l_i[i];
#pragma unroll
        for (int j = 0; j < 4; j++)
            xcat[((size_t)b * N_ + q0 + ty * 4 + i) * C_ + head * HD_ + tx * 4 + j] =
                o[i][j] * inv;
    }
}

// =====================================================================================
// Host orchestration
// =====================================================================================
extern "C" void kernel_launch(void* const* d_in, const int* in_sizes, int n_in,
                              void* d_out, int out_size)
{
    const float* x   = (const float*)d_in[0];
    const float* Wq  = (const float*)d_in[1];
    const float* bq  = (const float*)d_in[2];
    const float* Wkv = (const float*)d_in[3];
    const float* bkv = (const float*)d_in[4];
    const float* Wo  = (const float*)d_in[23];
    const float* bo  = (const float*)d_in[24];

    float *q, *xr, *kvb, *v2, *xcat, *wt;
    cudaGetSymbolAddress((void**)&q, g_q);
    cudaGetSymbolAddress((void**)&xr, g_xr);
    cudaGetSymbolAddress((void**)&kvb, g_kv);
    cudaGetSymbolAddress((void**)&v2, g_v2);
    cudaGetSymbolAddress((void**)&xcat, g_xcat);
    cudaGetSymbolAddress((void**)&wt, g_wt);

    const int attn_smem = 4 * 64 * 65 * (int)sizeof(float);
    cudaFuncSetAttribute(attn_kernel, cudaFuncAttributeMaxDynamicSharedMemorySize, attn_smem);

    const int M = B_ * N_;  // 18432

    // Q projection
    gemm_kernel<<<dim3((M + 127) / 128, 3), 256>>>(x, Wq, bq, q, M, C_, C_, C_);

    const int ks_arr[3] = {8, 4, 2};
    for (int br = 0; br < 3; br++) {
        const float* srw = (const float*)d_in[5 + br * 6 + 0];
        const float* srb = (const float*)d_in[5 + br * 6 + 1];
        const float* lng = (const float*)d_in[5 + br * 6 + 2];
        const float* lnb = (const float*)d_in[5 + br * 6 + 3];
        const float* lcw = (const float*)d_in[5 + br * 6 + 4];
        const float* lcb = (const float*)d_in[5 + br * 6 + 5];
        int ksz = ks_arr[br];
        int s = HW_ - ksz + 1;
        int n = s * s;
        int rows = B_ * n;

        wtrans_kernel<<<256, 256>>>(srw, wt, ksz);
        conv_gemm_kernel<<<dim3((n + 127) / 128, 3, B_), 256>>>(x, wt, srb, xr, s, ksz);
        ln_gelu_kernel<<<(rows + 7) / 8, 256>>>(xr, lng, lnb, rows);
        gemm_kernel<<<dim3((rows + 127) / 128, 2), 256>>>(xr, Wkv, bkv, kvb, rows, C_, C_, 128);
        dwconv_kernel<<<(rows * HD_ + 255) / 256, 256>>>(kvb, lcw, lcb, v2, s);
        attn_kernel<<<dim3(N_ / 64, B_), 256, attn_smem>>>(q, kvb, v2, xcat, n, br);
    }

    // Output projection
    gemm_kernel<<<dim3((M + 127) / 128, 3), 256>>>(xcat, Wo, bo, (float*)d_out, M, C_, C_, C_);
}

// round 3
// speedup vs baseline: 1.5990x; 1.5990x over previous
#include <cuda_runtime.h>
#include <math.h>
#include <stdint.h>

#define B_    8
#define N_    2304
#define C_    192
#define HW_   48
#define HD_   64
#define NMAX_ 2209   // 47*47

// ---------------- scratch (no allocation allowed; __device__ globals) ----------------
__device__ float g_q[B_ * N_ * C_];          // Q projection (B,N,192)
__device__ float g_xr[B_ * NMAX_ * C_];      // conv/LN/GELU activations (B,n,192)
__device__ float g_kv[B_ * NMAX_ * 128];     // K (cols 0..63) | V (cols 64..127)
__device__ float g_v2[B_ * NMAX_ * HD_];     // V + depthwise conv
__device__ float g_xcat[B_ * N_ * C_];       // concat of 3 branch outputs
__device__ float g_wt[C_ * C_ * 64];         // transposed conv weights [kyx][ci][co]

// ---------------- tf32 helpers ----------------
__device__ __forceinline__ uint32_t f2tf(float v) {
    uint32_t r;
    asm("cvt.rna.tf32.f32 %0, %1;" : "=r"(r) : "f"(v));
    return r;
}

__device__ __forceinline__ void mma_tf32(float* d, const uint32_t* a, const uint32_t* b) {
    asm volatile(
        "mma.sync.aligned.m16n8k8.row.col.f32.tf32.tf32.f32 "
        "{%0,%1,%2,%3}, {%4,%5,%6,%7}, {%8,%9}, {%0,%1,%2,%3};"
        : "+f"(d[0]), "+f"(d[1]), "+f"(d[2]), "+f"(d[3])
        : "r"(a[0]), "r"(a[1]), "r"(a[2]), "r"(a[3]), "r"(b[0]), "r"(b[1]));
}

// =====================================================================================
// TF32 tensor-core GEMM: out[m, n0+j] = A[m,:K] @ W[:, n0+j] + bias[n0+j]
// Tiles 128x64, BK=16. 256 thr = 8 warps as 4(m) x 2(n), warp tile 32x32.
// =====================================================================================
__global__ __launch_bounds__(256) void gemm_tc_kernel(
    const float* __restrict__ A, const float* __restrict__ W,
    const float* __restrict__ bias, float* __restrict__ out,
    int M, int K, int ldw, int ldc)
{
    __shared__ uint32_t As[16][132];
    __shared__ uint32_t Ws[16][68];
    const int tid = threadIdx.x;
    const int tx = tid & 15, ty = tid >> 4;       // loader mapping
    const int warp = tid >> 5, lane = tid & 31;   // compute mapping
    const int wm = warp & 3, wn = warp >> 2;
    const int lr = lane >> 2, lc = lane & 3;
    const int m0 = blockIdx.x * 128;
    const int n0 = blockIdx.y * 64;

    float acc[2][4][4];
#pragma unroll
    for (int mi = 0; mi < 2; mi++)
#pragma unroll
        for (int ni = 0; ni < 4; ni++)
#pragma unroll
            for (int j = 0; j < 4; j++) acc[mi][ni][j] = 0.f;

    for (int k0 = 0; k0 < K; k0 += 16) {
#pragma unroll
        for (int i = 0; i < 8; i++) {
            int r = ty + i * 16;
            int m = m0 + r;
            As[tx][r] = (m < M) ? f2tf(A[(size_t)m * K + (k0 + tx)]) : 0u;
        }
#pragma unroll
        for (int i = 0; i < 4; i++) {
            int e = tid + i * 256;
            int c = e >> 6, j = e & 63;
            Ws[c][j] = f2tf(W[(size_t)(k0 + c) * ldw + (n0 + j)]);
        }
        __syncthreads();
#pragma unroll
        for (int ks = 0; ks < 16; ks += 8) {
            uint32_t af[2][4];
#pragma unroll
            for (int mi = 0; mi < 2; mi++) {
                int rr = wm * 32 + mi * 16 + lr;
                af[mi][0] = As[ks + lc][rr];
                af[mi][1] = As[ks + lc][rr + 8];
                af[mi][2] = As[ks + 4 + lc][rr];
                af[mi][3] = As[ks + 4 + lc][rr + 8];
            }
            uint32_t bf[4][2];
#pragma unroll
            for (int ni = 0; ni < 4; ni++) {
                int cc = wn * 32 + ni * 8 + lr;
                bf[ni][0] = Ws[ks + lc][cc];
                bf[ni][1] = Ws[ks + 4 + lc][cc];
            }
#pragma unroll
            for (int mi = 0; mi < 2; mi++)
#pragma unroll
                for (int ni = 0; ni < 4; ni++) mma_tf32(acc[mi][ni], af[mi], bf[ni]);
        }
        __syncthreads();
    }
#pragma unroll
    for (int mi = 0; mi < 2; mi++) {
        int row = m0 + wm * 32 + mi * 16 + lr;
#pragma unroll
        for (int ni = 0; ni < 4; ni++) {
            int col = n0 + wn * 32 + ni * 8 + lc * 2;
            float b0 = bias[col], b1 = bias[col + 1];
            if (row < M) {
                out[(size_t)row * ldc + col]     = acc[mi][ni][0] + b0;
                out[(size_t)row * ldc + col + 1] = acc[mi][ni][1] + b1;
            }
            if (row + 8 < M) {
                out[(size_t)(row + 8) * ldc + col]     = acc[mi][ni][2] + b0;
                out[(size_t)(row + 8) * ldc + col + 1] = acc[mi][ni][3] + b1;
            }
        }
    }
}

// =====================================================================================
// Weight transform: w[co][ci][ky][kx] (OIHW) -> wt[kyx][ci][co]
// =====================================================================================
__global__ void wtrans_kernel(const float* __restrict__ w, float* __restrict__ wt, int ksz)
{
    int k2 = ksz * ksz;
    int total = C_ * C_ * k2;
    for (int idx = blockIdx.x * blockDim.x + threadIdx.x; idx < total;
         idx += gridDim.x * blockDim.x) {
        int co = idx % C_;
        int rest = idx / C_;
        int ci = rest % C_;
        int kyx = rest / C_;
        wt[idx] = w[((size_t)co * C_ + ci) * k2 + kyx];
    }
}

// =====================================================================================
// SR conv as implicit GEMM on tensor cores (tf32).
// out[b, p, co] = bias[co] + sum_{ky,kx,ci} x[b, (y+ky)*48 + (x+kx), ci] * wt[kyx][ci][co]
// =====================================================================================
__global__ __launch_bounds__(256) void conv_tc_kernel(
    const float* __restrict__ x, const float* __restrict__ wt,
    const float* __restrict__ bias, float* __restrict__ out,
    int s, int ksz)
{
    __shared__ uint32_t As[16][132];
    __shared__ uint32_t Ws[16][68];
    const int tid = threadIdx.x;
    const int tx = tid & 15, ty = tid >> 4;
    const int warp = tid >> 5, lane = tid & 31;
    const int wm = warp & 3, wn = warp >> 2;
    const int lr = lane >> 2, lc = lane & 3;
    const int b = blockIdx.z;
    const int n = s * s;
    const int m0 = blockIdx.x * 128;
    const int n0 = blockIdx.y * 64;

    // per-load-row base offsets (constant over the K loop)
    int rowoff[8];
    bool valid[8];
#pragma unroll
    for (int i = 0; i < 8; i++) {
        int p = m0 + ty + i * 16;
        valid[i] = (p < n);
        int pp = valid[i] ? p : 0;
        int y = pp / s;
        int x0 = pp - y * s;
        rowoff[i] = (y * HW_ + x0) * C_;
    }
    const float* xb = x + (size_t)b * N_ * C_;

    float acc[2][4][4];
#pragma unroll
    for (int mi = 0; mi < 2; mi++)
#pragma unroll
        for (int ni = 0; ni < 4; ni++)
#pragma unroll
            for (int j = 0; j < 4; j++) acc[mi][ni][j] = 0.f;

    const int nk = ksz * ksz;
    for (int kyx = 0; kyx < nk; kyx++) {
        const int ky = kyx / ksz, kx = kyx - ky * ksz;
        const int koff = (ky * HW_ + kx) * C_ + tx;
        const float* wtk = wt + (size_t)kyx * C_ * C_ + n0;
        for (int ci0 = 0; ci0 < C_; ci0 += 16) {
#pragma unroll
            for (int i = 0; i < 8; i++) {
                int r = ty + i * 16;
                float v = 0.f;
                if (valid[i]) v = xb[rowoff[i] + koff + ci0];
                As[tx][r] = f2tf(v);
            }
#pragma unroll
            for (int i = 0; i < 4; i++) {
                int e = tid + i * 256;
                int c = e >> 6, j = e & 63;
                Ws[c][j] = f2tf(wtk[(size_t)(ci0 + c) * C_ + j]);
            }
            __syncthreads();
#pragma unroll
            for (int ks = 0; ks < 16; ks += 8) {
                uint32_t af[2][4];
#pragma unroll
                for (int mi = 0; mi < 2; mi++) {
                    int rr = wm * 32 + mi * 16 + lr;
                    af[mi][0] = As[ks + lc][rr];
                    af[mi][1] = As[ks + lc][rr + 8];
                    af[mi][2] = As[ks + 4 + lc][rr];
                    af[mi][3] = As[ks + 4 + lc][rr + 8];
                }
                uint32_t bf[4][2];
#pragma unroll
                for (int ni = 0; ni < 4; ni++) {
                    int cc = wn * 32 + ni * 8 + lr;
                    bf[ni][0] = Ws[ks + lc][cc];
                    bf[ni][1] = Ws[ks + 4 + lc][cc];
                }
#pragma unroll
                for (int mi = 0; mi < 2; mi++)
#pragma unroll
                    for (int ni = 0; ni < 4; ni++) mma_tf32(acc[mi][ni], af[mi], bf[ni]);
            }
            __syncthreads();
        }
    }
#pragma unroll
    for (int mi = 0; mi < 2; mi++) {
        int row = m0 + wm * 32 + mi * 16 + lr;
#pragma unroll
        for (int ni = 0; ni < 4; ni++) {
            int col = n0 + wn * 32 + ni * 8 + lc * 2;
            float b0 = bias[col], b1 = bias[col + 1];
            if (row < n) {
                float* o = out + ((size_t)b * n + row) * C_ + col;
                o[0] = acc[mi][ni][0] + b0;
                o[1] = acc[mi][ni][1] + b1;
            }
            if (row + 8 < n) {
                float* o = out + ((size_t)b * n + row + 8) * C_ + col;
                o[0] = acc[mi][ni][2] + b0;
                o[1] = acc[mi][ni][3] + b1;
            }
        }
    }
}

// =====================================================================================
// Fused LayerNorm + exact GELU (in-place on rows of length C=192). One warp per row.
// =====================================================================================
__global__ void ln_gelu_kernel(float* __restrict__ xr, const float* __restrict__ g,
                               const float* __restrict__ bb, int rows)
{
    int wid = (blockIdx.x * blockDim.x + threadIdx.x) >> 5;
    int lane = threadIdx.x & 31;
    if (wid >= rows) return;
    float* row = xr + (size_t)wid * C_;
    float s1 = 0.f, s2 = 0.f;
#pragma unroll
    for (int j = lane; j < C_; j += 32) {
        float v = row[j];
        s1 += v;
        s2 += v * v;
    }
#pragma unroll
    for (int o = 16; o; o >>= 1) {
        s1 += __shfl_xor_sync(0xffffffffu, s1, o);
        s2 += __shfl_xor_sync(0xffffffffu, s2, o);
    }
    float mu = s1 * (1.f / C_);
    float var = s2 * (1.f / C_) - mu * mu;
    float inv = rsqrtf(var + 1e-5f);
#pragma unroll
    for (int j = lane; j < C_; j += 32) {
        float v = (row[j] - mu) * inv * g[j] + bb[j];
        row[j] = 0.5f * v * (1.f + erff(v * 0.70710678118654752440f));
    }
}

// =====================================================================================
// Depthwise 3x3 (pad 1) on V + residual:  v2 = v + dwconv(v)
// =====================================================================================
__global__ void dwconv_kernel(const float* __restrict__ kv, const float* __restrict__ w,
                              const float* __restrict__ bias, float* __restrict__ v2, int s)
{
    int n = s * s;
    int total = B_ * n * HD_;
    int idx = blockIdx.x * blockDim.x + threadIdx.x;
    if (idx >= total) return;
    int hd = idx & 63;
    int p = (idx >> 6) % n;
    int b = idx / (n * 64);
    int y = p / s;
    int x0 = p - y * s;
    const float* vb = kv + (size_t)b * n * 128 + 64 + hd;
    float acc = bias[hd];
#pragma unroll
    for (int dy = -1; dy <= 1; dy++) {
#pragma unroll
        for (int dx = -1; dx <= 1; dx++) {
            int yy = y + dy, xx = x0 + dx;
            if (yy >= 0 && yy < s && xx >= 0 && xx < s)
                acc += w[hd * 9 + (dy + 1) * 3 + (dx + 1)] * vb[(size_t)(yy * s + xx) * 128];
        }
    }
    v2[idx] = acc + vb[(size_t)p * 128];
}

// =====================================================================================
// Flash attention (fp32): per (b, 64-query tile): out = softmax(q_h K^T * scale) V2
// =====================================================================================
__global__ __launch_bounds__(256) void attn_kernel(
    const float* __restrict__ q, const float* __restrict__ kv,
    const float* __restrict__ v2, float* __restrict__ xcat,
    int nkv, int head)
{
    extern __shared__ float sm[];
    float (*qs)[65] = (float (*)[65])sm;
    float (*ks)[65] = (float (*)[65])(sm + 64 * 65);
    float (*vs)[65] = (float (*)[65])(sm + 2 * 64 * 65);
    float (*ps)[65] = (float (*)[65])(sm + 3 * 64 * 65);

    const int tid = threadIdx.x;
    const int tx = tid & 15, ty = tid >> 4;
    const int b = blockIdx.y;
    const int q0 = blockIdx.x * 64;
    const float scale = 0.07216878364870322056f;  // 1/sqrt(192)

#pragma unroll
    for (int i = 0; i < 16; i++) {
        int e = tid + i * 256;
        int r = e >> 6, d = e & 63;
        qs[r][d] = q[((size_t)b * N_ + q0 + r) * C_ + head * HD_ + d];
    }

    float m_i[4], l_i[4], o[4][4];
#pragma unroll
    for (int i = 0; i < 4; i++) {
        m_i[i] = -1e30f;
        l_i[i] = 0.f;
#pragma unroll
        for (int j = 0; j < 4; j++) o[i][j] = 0.f;
    }
    __syncthreads();

    const int nchunks = (nkv + 63) >> 6;
    for (int c0 = 0; c0 < nchunks; c0++) {
        int base = c0 * 64;
        int cs = nkv - base;
        if (cs > 64) cs = 64;
#pragma unroll
        for (int i = 0; i < 16; i++) {
            int e = tid + i * 256;
            int r = e >> 6, d = e & 63;
            if (r < cs) {
                size_t kidx = (size_t)b * nkv + base + r;
                ks[r][d] = kv[kidx * 128 + d];
                vs[r][d] = v2[kidx * 64 + d];
            } else {
                ks[r][d] = 0.f;
                vs[r][d] = 0.f;
            }
        }
        __syncthreads();

        float sacc[4][4];
#pragma unroll
        for (int i = 0; i < 4; i++)
#pragma unroll
            for (int j = 0; j < 4; j++) sacc[i][j] = 0.f;

        for (int d = 0; d < 64; d++) {
            float a[4], bb[4];
#pragma unroll
            for (int i = 0; i < 4; i++) a[i] = qs[ty * 4 + i][d];
#pragma unroll
            for (int j = 0; j < 4; j++) bb[j] = ks[tx * 4 + j][d];
#pragma unroll
            for (int i = 0; i < 4; i++)
#pragma unroll
                for (int j = 0; j < 4; j++) sacc[i][j] += a[i] * bb[j];
        }
#pragma unroll
        for (int i = 0; i < 4; i++)
#pragma unroll
            for (int j = 0; j < 4; j++) {
                float v = sacc[i][j] * scale;
                if (tx * 4 + j >= cs) v = -1e30f;
                sacc[i][j] = v;
            }

#pragma unroll
        for (int i = 0; i < 4; i++) {
            float mx = fmaxf(fmaxf(sacc[i][0], sacc[i][1]), fmaxf(sacc[i][2], sacc[i][3]));
#pragma unroll
            for (int off = 1; off < 16; off <<= 1)
                mx = fmaxf(mx, __shfl_xor_sync(0xffffffffu, mx, off));
            float mnew = fmaxf(m_i[i], mx);
            float alpha = __expf(m_i[i] - mnew);
            float rs = 0.f;
#pragma unroll
            for (int j = 0; j < 4; j++) {
                float p = __expf(sacc[i][j] - mnew);
                sacc[i][j] = p;
                rs += p;
            }
#pragma unroll
            for (int off = 1; off < 16; off <<= 1)
                rs += __shfl_xor_sync(0xffffffffu, rs, off);
            l_i[i] = l_i[i] * alpha + rs;
            m_i[i] = mnew;
#pragma unroll
            for (int j = 0; j < 4; j++) o[i][j] *= alpha;
        }

#pragma unroll
        for (int i = 0; i < 4; i++)
#pragma unroll
            for (int j = 0; j < 4; j++) ps[ty * 4 + i][tx * 4 + j] = sacc[i][j];
        __syncthreads();

        for (int jj = 0; jj < 64; jj++) {
            float pv[4], vv[4];
#pragma unroll
            for (int i = 0; i < 4; i++) pv[i] = ps[ty * 4 + i][jj];
#pragma unroll
            for (int j = 0; j < 4; j++) vv[j] = vs[jj][tx * 4 + j];
#pragma unroll
            for (int i = 0; i < 4; i++)
#pragma unroll
                for (int j = 0; j < 4; j++) o[i][j] += pv[i] * vv[j];
        }
        __syncthreads();
    }

#pragma unroll
    for (int i = 0; i < 4; i++) {
        float inv = 1.f / l_i[i];
#pragma unroll
        for (int j = 0; j < 4; j++)
            xcat[((size_t)b * N_ + q0 + ty * 4 + i) * C_ + head * HD_ + tx * 4 + j] =
                o[i][j] * inv;
    }
}

// =====================================================================================
// Host orchestration
// =====================================================================================
extern "C" void kernel_launch(void* const* d_in, const int* in_sizes, int n_in,
                              void* d_out, int out_size)
{
    const float* x   = (const float*)d_in[0];
    const float* Wq  = (const float*)d_in[1];
    const float* bq  = (const float*)d_in[2];
    const float* Wkv = (const float*)d_in[3];
    const float* bkv = (const float*)d_in[4];
    const float* Wo  = (const float*)d_in[23];
    const float* bo  = (const float*)d_in[24];

    float *q, *xr, *kvb, *v2, *xcat, *wt;
    cudaGetSymbolAddress((void**)&q, g_q);
    cudaGetSymbolAddress((void**)&xr, g_xr);
    cudaGetSymbolAddress((void**)&kvb, g_kv);
    cudaGetSymbolAddress((void**)&v2, g_v2);
    cudaGetSymbolAddress((void**)&xcat, g_xcat);
    cudaGetSymbolAddress((void**)&wt, g_wt);

    const int attn_smem = 4 * 64 * 65 * (int)sizeof(float);
    cudaFuncSetAttribute(attn_kernel, cudaFuncAttributeMaxDynamicSharedMemorySize, attn_smem);

    const int M = B_ * N_;  // 18432

    // Q projection (tf32 TC)
    gemm_tc_kernel<<<dim3((M + 127) / 128, 3), 256>>>(x, Wq, bq, q, M, C_, C_, C_);

    const int ks_arr[3] = {8, 4, 2};
    for (int br = 0; br < 3; br++) {
        const float* srw = (const float*)d_in[5 + br * 6 + 0];
        const float* srb = (const float*)d_in[5 + br * 6 + 1];
        const float* lng = (const float*)d_in[5 + br * 6 + 2];
        const float* lnb = (const float*)d_in[5 + br * 6 + 3];
        const float* lcw = (const float*)d_in[5 + br * 6 + 4];
        const float* lcb = (const float*)d_in[5 + br * 6 + 5];
        int ksz = ks_arr[br];
        int s = HW_ - ksz + 1;
        int n = s * s;
        int rows = B_ * n;

        wtrans_kernel<<<256, 256>>>(srw, wt, ksz);
        conv_tc_kernel<<<dim3((n + 127) / 128, 3, B_), 256>>>(x, wt, srb, xr, s, ksz);
        ln_gelu_kernel<<<(rows + 7) / 8, 256>>>(xr, lng, lnb, rows);
        gemm_tc_kernel<<<dim3((rows + 127) / 128, 2), 256>>>(xr, Wkv, bkv, kvb, rows, C_, C_, 128);
        dwconv_kernel<<<(rows * HD_ + 255) / 256, 256>>>(kvb, lcw, lcb, v2, s);
        attn_kernel<<<dim3(N_ / 64, B_), 256, attn_smem>>>(q, kvb, v2, xcat, n, br);
    }

    // Output projection (tf32 TC)
    gemm_tc_kernel<<<dim3((M + 127) / 128, 3), 256>>>(xcat, Wo, bo, (float*)d_out, M, C_, C_, C_);
}

// round 5
// speedup vs baseline: 1.7866x; 1.1173x over previous
#include <cuda_runtime.h>
#include <math.h>
#include <stdint.h>

#define B_    8
#define N_    2304
#define C_    192
#define HW_   48
#define HD_   64
#define NMAX_ 2209   // 47*47

// ---------------- scratch (no allocation allowed; __device__ globals) ----------------
__device__ float g_q[B_ * N_ * C_];          // Q projection (B,N,192)
__device__ float g_xr[B_ * NMAX_ * C_];      // conv/LN/GELU activations (B,n,192)
__device__ float g_kv[B_ * NMAX_ * 128];     // K (cols 0..63) | V (cols 64..127)
__device__ float g_v2[B_ * NMAX_ * HD_];     // V + depthwise conv
__device__ float g_xcat[B_ * N_ * C_];       // concat of 3 branch outputs
__device__ float g_wt[C_ * C_ * 64];         // transposed conv weights [kyx][ci][co]

// ---------------- tf32 helpers ----------------
__device__ __forceinline__ uint32_t f2tf(float v) {
    uint32_t r;
    asm("cvt.rna.tf32.f32 %0, %1;" : "=r"(r) : "f"(v));
    return r;
}

__device__ __forceinline__ void mma_tf32(float* d, const uint32_t* a, const uint32_t* b) {
    asm volatile(
        "mma.sync.aligned.m16n8k8.row.col.f32.tf32.tf32.f32 "
        "{%0,%1,%2,%3}, {%4,%5,%6,%7}, {%8,%9}, {%0,%1,%2,%3};"
        : "+f"(d[0]), "+f"(d[1]), "+f"(d[2]), "+f"(d[3])
        : "r"(a[0]), "r"(a[1]), "r"(a[2]), "r"(a[3]), "r"(b[0]), "r"(b[1]));
}

// SMEM pads chosen so fragment LDS bank = (8*lc + lr) -> bijective, conflict-free
#define ALD 136
#define WLD 72

// =====================================================================================
// TF32 tensor-core GEMM: out[m, n0+j] = A[m,:K] @ W[:, n0+j] + bias[n0+j]
// Tiles 128x64, BK=16. 256 thr = 8 warps as 4(m) x 2(n), warp tile 32x32.
// =====================================================================================
__global__ __launch_bounds__(256) void gemm_tc_kernel(
    const float* __restrict__ A, const float* __restrict__ W,
    const float* __restrict__ bias, float* __restrict__ out,
    int M, int K, int ldw, int ldc)
{
    __shared__ uint32_t As[16][ALD];
    __shared__ uint32_t Ws[16][WLD];
    const int tid = threadIdx.x;
    const int tx = tid & 15, ty = tid >> 4;       // loader mapping
    const int warp = tid >> 5, lane = tid & 31;   // compute mapping
    const int wm = warp & 3, wn = warp >> 2;
    const int lr = lane >> 2, lc = lane & 3;
    const int m0 = blockIdx.x * 128;
    const int n0 = blockIdx.y * 64;

    float acc[2][4][4];
#pragma unroll
    for (int mi = 0; mi < 2; mi++)
#pragma unroll
        for (int ni = 0; ni < 4; ni++)
#pragma unroll
            for (int j = 0; j < 4; j++) acc[mi][ni][j] = 0.f;

    for (int k0 = 0; k0 < K; k0 += 16) {
#pragma unroll
        for (int i = 0; i < 8; i++) {
            int r = ty + i * 16;
            int m = m0 + r;
            As[tx][r] = (m < M) ? f2tf(A[(size_t)m * K + (k0 + tx)]) : 0u;
        }
#pragma unroll
        for (int i = 0; i < 4; i++) {
            int e = tid + i * 256;
            int c = e >> 6, j = e & 63;
            Ws[c][j] = f2tf(W[(size_t)(k0 + c) * ldw + (n0 + j)]);
        }
        __syncthreads();
#pragma unroll
        for (int ks = 0; ks < 16; ks += 8) {
            uint32_t af[2][4];
#pragma unroll
            for (int mi = 0; mi < 2; mi++) {
                int rr = wm * 32 + mi * 16 + lr;
                af[mi][0] = As[ks + lc][rr];
                af[mi][1] = As[ks + lc][rr + 8];
                af[mi][2] = As[ks + 4 + lc][rr];
                af[mi][3] = As[ks + 4 + lc][rr + 8];
            }
            uint32_t bf[4][2];
#pragma unroll
            for (int ni = 0; ni < 4; ni++) {
                int cc = wn * 32 + ni * 8 + lr;
                bf[ni][0] = Ws[ks + lc][cc];
                bf[ni][1] = Ws[ks + 4 + lc][cc];
            }
#pragma unroll
            for (int mi = 0; mi < 2; mi++)
#pragma unroll
                for (int ni = 0; ni < 4; ni++) mma_tf32(acc[mi][ni], af[mi], bf[ni]);
        }
        __syncthreads();
    }
#pragma unroll
    for (int mi = 0; mi < 2; mi++) {
        int row = m0 + wm * 32 + mi * 16 + lr;
#pragma unroll
        for (int ni = 0; ni < 4; ni++) {
            int col = n0 + wn * 32 + ni * 8 + lc * 2;
            float b0 = bias[col], b1 = bias[col + 1];
            if (row < M) {
                out[(size_t)row * ldc + col]     = acc[mi][ni][0] + b0;
                out[(size_t)row * ldc + col + 1] = acc[mi][ni][1] + b1;
            }
            if (row + 8 < M) {
                out[(size_t)(row + 8) * ldc + col]     = acc[mi][ni][2] + b0;
                out[(size_t)(row + 8) * ldc + col + 1] = acc[mi][ni][3] + b1;
            }
        }
    }
}

// =====================================================================================
// Weight transform: w[co][ci][ky][kx] (OIHW) -> wt[kyx][ci][co]
// =====================================================================================
__global__ void wtrans_kernel(const float* __restrict__ w, float* __restrict__ wt, int ksz)
{
    int k2 = ksz * ksz;
    int total = C_ * C_ * k2;
    for (int idx = blockIdx.x * blockDim.x + threadIdx.x; idx < total;
         idx += gridDim.x * blockDim.x) {
        int co = idx % C_;
        int rest = idx / C_;
        int ci = rest % C_;
        int kyx = rest / C_;
        wt[idx] = w[((size_t)co * C_ + ci) * k2 + kyx];
    }
}

// =====================================================================================
// SR conv as implicit GEMM on tensor cores (tf32).
// =====================================================================================
__global__ __launch_bounds__(256) void conv_tc_kernel(
    const float* __restrict__ x, const float* __restrict__ wt,
    const float* __restrict__ bias, float* __restrict__ out,
    int s, int ksz)
{
    __shared__ uint32_t As[16][ALD];
    __shared__ uint32_t Ws[16][WLD];
    const int tid = threadIdx.x;
    const int tx = tid & 15, ty = tid >> 4;
    const int warp = tid >> 5, lane = tid & 31;
    const int wm = warp & 3, wn = warp >> 2;
    const int lr = lane >> 2, lc = lane & 3;
    const int b = blockIdx.z;
    const int n = s * s;
    const int m0 = blockIdx.x * 128;
    const int n0 = blockIdx.y * 64;

    int rowoff[8];
    bool valid[8];
#pragma unroll
    for (int i = 0; i < 8; i++) {
        int p = m0 + ty + i * 16;
        valid[i] = (p < n);
        int pp = valid[i] ? p : 0;
        int y = pp / s;
        int x0 = pp - y * s;
        rowoff[i] = (y * HW_ + x0) * C_;
    }
    const float* xb = x + (size_t)b * N_ * C_;

    float acc[2][4][4];
#pragma unroll
    for (int mi = 0; mi < 2; mi++)
#pragma unroll
        for (int ni = 0; ni < 4; ni++)
#pragma unroll
            for (int j = 0; j < 4; j++) acc[mi][ni][j] = 0.f;

    const int nk = ksz * ksz;
    for (int kyx = 0; kyx < nk; kyx++) {
        const int ky = kyx / ksz, kx = kyx - ky * ksz;
        const int koff = (ky * HW_ + kx) * C_ + tx;
        const float* wtk = wt + (size_t)kyx * C_ * C_ + n0;
        for (int ci0 = 0; ci0 < C_; ci0 += 16) {
#pragma unroll
            for (int i = 0; i < 8; i++) {
                int r = ty + i * 16;
                float v = 0.f;
                if (valid[i]) v = xb[rowoff[i] + koff + ci0];
                As[tx][r] = f2tf(v);
            }
#pragma unroll
            for (int i = 0; i < 4; i++) {
                int e = tid + i * 256;
                int c = e >> 6, j = e & 63;
                Ws[c][j] = f2tf(wtk[(size_t)(ci0 + c) * C_ + j]);
            }
            __syncthreads();
#pragma unroll
            for (int ks = 0; ks < 16; ks += 8) {
                uint32_t af[2][4];
#pragma unroll
                for (int mi = 0; mi < 2; mi++) {
                    int rr = wm * 32 + mi * 16 + lr;
                    af[mi][0] = As[ks + lc][rr];
                    af[mi][1] = As[ks + lc][rr + 8];
                    af[mi][2] = As[ks + 4 + lc][rr];
                    af[mi][3] = As[ks + 4 + lc][rr + 8];
                }
                uint32_t bf[4][2];
#pragma unroll
                for (int ni = 0; ni < 4; ni++) {
                    int cc = wn * 32 + ni * 8 + lr;
                    bf[ni][0] = Ws[ks + lc][cc];
                    bf[ni][1] = Ws[ks + 4 + lc][cc];
                }
#pragma unroll
                for (int mi = 0; mi < 2; mi++)
#pragma unroll
                    for (int ni = 0; ni < 4; ni++) mma_tf32(acc[mi][ni], af[mi], bf[ni]);
            }
            __syncthreads();
        }
    }
#pragma unroll
    for (int mi = 0; mi < 2; mi++) {
        int row = m0 + wm * 32 + mi * 16 + lr;
#pragma unroll
        for (int ni = 0; ni < 4; ni++) {
            int col = n0 + wn * 32 + ni * 8 + lc * 2;
            float b0 = bias[col], b1 = bias[col + 1];
            if (row < n) {
                float* o = out + ((size_t)b * n + row) * C_ + col;
                o[0] = acc[mi][ni][0] + b0;
                o[1] = acc[mi][ni][1] + b1;
            }
            if (row + 8 < n) {
                float* o = out + ((size_t)b * n + row + 8) * C_ + col;
                o[0] = acc[mi][ni][2] + b0;
                o[1] = acc[mi][ni][3] + b1;
            }
        }
    }
}

// =====================================================================================
// Fused LayerNorm + exact GELU (in-place). One warp per row.
// =====================================================================================
__global__ void ln_gelu_kernel(float* __restrict__ xr, const float* __restrict__ g,
                               const float* __restrict__ bb, int rows)
{
    int wid = (blockIdx.x * blockDim.x + threadIdx.x) >> 5;
    int lane = threadIdx.x & 31;
    if (wid >= rows) return;
    float* row = xr + (size_t)wid * C_;
    float s1 = 0.f, s2 = 0.f;
#pragma unroll
    for (int j = lane; j < C_; j += 32) {
        float v = row[j];
        s1 += v;
        s2 += v * v;
    }
#pragma unroll
    for (int o = 16; o; o >>= 1) {
        s1 += __shfl_xor_sync(0xffffffffu, s1, o);
        s2 += __shfl_xor_sync(0xffffffffu, s2, o);
    }
    float mu = s1 * (1.f / C_);
    float var = s2 * (1.f / C_) - mu * mu;
    float inv = rsqrtf(var + 1e-5f);
#pragma unroll
    for (int j = lane; j < C_; j += 32) {
        float v = (row[j] - mu) * inv * g[j] + bb[j];
        row[j] = 0.5f * v * (1.f + erff(v * 0.70710678118654752440f));
    }
}

// =====================================================================================
// Depthwise 3x3 (pad 1) on V + residual:  v2 = v + dwconv(v)
// =====================================================================================
__global__ void dwconv_kernel(const float* __restrict__ kv, const float* __restrict__ w,
                              const float* __restrict__ bias, float* __restrict__ v2, int s)
{
    int n = s * s;
    int total = B_ * n * HD_;
    int idx = blockIdx.x * blockDim.x + threadIdx.x;
    if (idx >= total) return;
    int hd = idx & 63;
    int p = (idx >> 6) % n;
    int b = idx / (n * 64);
    int y = p / s;
    int x0 = p - y * s;
    const float* vb = kv + (size_t)b * n * 128 + 64 + hd;
    float acc = bias[hd];
#pragma unroll
    for (int dy = -1; dy <= 1; dy++) {
#pragma unroll
        for (int dx = -1; dx <= 1; dx++) {
            int yy = y + dy, xx = x0 + dx;
            if (yy >= 0 && yy < s && xx >= 0 && xx < s)
                acc += w[hd * 9 + (dy + 1) * 3 + (dx + 1)] * vb[(size_t)(yy * s + xx) * 128];
        }
    }
    v2[idx] = acc + vb[(size_t)p * 128];
}

// =====================================================================================
// Tensor-core flash attention (tf32 MMA, fp32 softmax). DYNAMIC smem (72 KB > 48 KB
// static limit). Block: 64 q-rows, 128 threads = 4 warps; warp wm owns rows
// [16*wm, 16*wm+16). Layout: qs[d][row], kst[d][key], vs[key][d], ps[key][row],
// all with ld=72 -> fragment LDS bank = 8*lc+lr, conflict-free.
// =====================================================================================
#define TLD 72
__global__ __launch_bounds__(128) void attn_tc_kernel(
    const float* __restrict__ q, const float* __restrict__ kv,
    const float* __restrict__ v2, float* __restrict__ xcat,
    int nkv, int head)
{
    extern __shared__ uint32_t smbuf[];
    uint32_t (*qs)[TLD]  = (uint32_t (*)[TLD])smbuf;
    uint32_t (*kst)[TLD] = (uint32_t (*)[TLD])(smbuf + 64 * TLD);
    uint32_t (*vs)[TLD]  = (uint32_t (*)[TLD])(smbuf + 2 * 64 * TLD);
    uint32_t (*ps)[TLD]  = (uint32_t (*)[TLD])(smbuf + 3 * 64 * TLD);

    const int tid = threadIdx.x;
    const int warp = tid >> 5, lane = tid & 31;
    const int wm = warp;
    const int lr = lane >> 2, lc = lane & 3;
    const int b = blockIdx.y;
    const int q0 = blockIdx.x * 64;
    const int rr = wm * 16 + lr;
    const float scale = 0.07216878364870322056f;  // 1/sqrt(192)

    // load Q tile, transposed to [d][row]
#pragma unroll
    for (int i = 0; i < 32; i++) {
        int e = tid + i * 128;
        int r = e >> 6, d = e & 63;
        qs[d][r] = f2tf(q[((size_t)b * N_ + q0 + r) * C_ + head * HD_ + d]);
    }

    float m_i[2], l_i[2], oacc[8][4];
    m_i[0] = m_i[1] = -1e30f;
    l_i[0] = l_i[1] = 0.f;
#pragma unroll
    for (int ni = 0; ni < 8; ni++)
#pragma unroll
        for (int j = 0; j < 4; j++) oacc[ni][j] = 0.f;

    __syncthreads();

    const int nchunks = (nkv + 63) >> 6;
    for (int c0 = 0; c0 < nchunks; c0++) {
        int base = c0 * 64;
        int cs = nkv - base;
        if (cs > 64) cs = 64;
        // load K (transposed [d][key]) and V ([key][d])
#pragma unroll
        for (int i = 0; i < 32; i++) {
            int e = tid + i * 128;
            int r = e >> 6, d = e & 63;
            if (r < cs) {
                size_t kidx = (size_t)b * nkv + base + r;
                kst[d][r] = f2tf(kv[kidx * 128 + d]);
                vs[r][d]  = f2tf(v2[kidx * 64 + d]);
            } else {
                kst[d][r] = 0u;
                vs[r][d]  = 0u;
            }
        }
        __syncthreads();

        // S = Q @ K^T  (warp: 16 rows x 64 cols)
        float sacc[8][4];
#pragma unroll
        for (int ni = 0; ni < 8; ni++)
#pragma unroll
            for (int j = 0; j < 4; j++) sacc[ni][j] = 0.f;
#pragma unroll
        for (int kk = 0; kk < 64; kk += 8) {
            uint32_t af[4];
            af[0] = qs[kk + lc][rr];
            af[1] = qs[kk + lc][rr + 8];
            af[2] = qs[kk + 4 + lc][rr];
            af[3] = qs[kk + 4 + lc][rr + 8];
#pragma unroll
            for (int ni = 0; ni < 8; ni++) {
                uint32_t bf[2];
                int cc = ni * 8 + lr;
                bf[0] = kst[kk + lc][cc];
                bf[1] = kst[kk + 4 + lc][cc];
                mma_tf32(sacc[ni], af, bf);
            }
        }

        // online softmax per row-half h (rows lr+8h within warp tile)
#pragma unroll
        for (int h = 0; h < 2; h++) {
            float mx = -1e30f;
#pragma unroll
            for (int ni = 0; ni < 8; ni++)
#pragma unroll
                for (int j = 0; j < 2; j++) {
                    float v = sacc[ni][2 * h + j] * scale;
                    if (ni * 8 + 2 * lc + j >= cs) v = -1e30f;
                    sacc[ni][2 * h + j] = v;
                    mx = fmaxf(mx, v);
                }
            mx = fmaxf(mx, __shfl_xor_sync(0xffffffffu, mx, 1));
            mx = fmaxf(mx, __shfl_xor_sync(0xffffffffu, mx, 2));
            float mnew = fmaxf(m_i[h], mx);
            float alpha = __expf(m_i[h] - mnew);
            float rs = 0.f;
#pragma unroll
            for (int ni = 0; ni < 8; ni++)
#pragma unroll
                for (int j = 0; j < 2; j++) {
                    float p = __expf(sacc[ni][2 * h + j] - mnew);
                    sacc[ni][2 * h + j] = p;
                    rs += p;
                }
            rs += __shfl_xor_sync(0xffffffffu, rs, 1);
            rs += __shfl_xor_sync(0xffffffffu, rs, 2);
            l_i[h] = l_i[h] * alpha + rs;
            m_i[h] = mnew;
#pragma unroll
            for (int ni = 0; ni < 8; ni++) {
                oacc[ni][2 * h]     *= alpha;
                oacc[ni][2 * h + 1] *= alpha;
            }
        }

        // write P to SMEM [key][row]; warp reads back only its own rows -> syncwarp
#pragma unroll
        for (int ni = 0; ni < 8; ni++) {
            int c = ni * 8 + 2 * lc;
            ps[c][rr]         = f2tf(sacc[ni][0]);
            ps[c + 1][rr]     = f2tf(sacc[ni][1]);
            ps[c][rr + 8]     = f2tf(sacc[ni][2]);
            ps[c + 1][rr + 8] = f2tf(sacc[ni][3]);
        }
        __syncwarp();

        // O += P @ V
#pragma unroll
        for (int kk = 0; kk < 64; kk += 8) {
            uint32_t af[4];
            af[0] = ps[kk + lc][rr];
            af[1] = ps[kk + lc][rr + 8];
            af[2] = ps[kk + 4 + lc][rr];
            af[3] = ps[kk + 4 + lc][rr + 8];
#pragma unroll
            for (int ni = 0; ni < 8; ni++) {
                uint32_t bf[2];
                int cc = ni * 8 + lr;
                bf[0] = vs[kk + lc][cc];
                bf[1] = vs[kk + 4 + lc][cc];
                mma_tf32(oacc[ni], af, bf);
            }
        }
        __syncthreads();
    }

    // epilogue: normalize and store
    float inv0 = 1.f / l_i[0], inv1 = 1.f / l_i[1];
#pragma unroll
    for (int ni = 0; ni < 8; ni++) {
        int col = head * HD_ + ni * 8 + 2 * lc;
        size_t r0 = (size_t)b * N_ + q0 + rr;
        xcat[r0 * C_ + col]           = oacc[ni][0] * inv0;
        xcat[r0 * C_ + col + 1]       = oacc[ni][1] * inv0;
        xcat[(r0 + 8) * C_ + col]     = oacc[ni][2] * inv1;
        xcat[(r0 + 8) * C_ + col + 1] = oacc[ni][3] * inv1;
    }
}

// =====================================================================================
// Host orchestration
// =====================================================================================
extern "C" void kernel_launch(void* const* d_in, const int* in_sizes, int n_in,
                              void* d_out, int out_size)
{
    const float* x   = (const float*)d_in[0];
    const float* Wq  = (const float*)d_in[1];
    const float* bq  = (const float*)d_in[2];
    const float* Wkv = (const float*)d_in[3];
    const float* bkv = (const float*)d_in[4];
    const float* Wo  = (const float*)d_in[23];
    const float* bo  = (const float*)d_in[24];

    float *q, *xr, *kvb, *v2, *xcat, *wt;
    cudaGetSymbolAddress((void**)&q, g_q);
    cudaGetSymbolAddress((void**)&xr, g_xr);
    cudaGetSymbolAddress((void**)&kvb, g_kv);
    cudaGetSymbolAddress((void**)&v2, g_v2);
    cudaGetSymbolAddress((void**)&xcat, g_xcat);
    cudaGetSymbolAddress((void**)&wt, g_wt);

    const int attn_smem = 4 * 64 * TLD * (int)sizeof(uint32_t);  // 73728 B
    cudaFuncSetAttribute(attn_tc_kernel, cudaFuncAttributeMaxDynamicSharedMemorySize,
                         attn_smem);

    const int M = B_ * N_;  // 18432

    // Q projection (tf32 TC)
    gemm_tc_kernel<<<dim3((M + 127) / 128, 3), 256>>>(x, Wq, bq, q, M, C_, C_, C_);

    const int ks_arr[3] = {8, 4, 2};
    for (int br = 0; br < 3; br++) {
        const float* srw = (const float*)d_in[5 + br * 6 + 0];
        const float* srb = (const float*)d_in[5 + br * 6 + 1];
        const float* lng = (const float*)d_in[5 + br * 6 + 2];
        const float* lnb = (const float*)d_in[5 + br * 6 + 3];
        const float* lcw = (const float*)d_in[5 + br * 6 + 4];
        const float* lcb = (const float*)d_in[5 + br * 6 + 5];
        int ksz = ks_arr[br];
        int s = HW_ - ksz + 1;
        int n = s * s;
        int rows = B_ * n;

        wtrans_kernel<<<256, 256>>>(srw, wt, ksz);
        conv_tc_kernel<<<dim3((n + 127) / 128, 3, B_), 256>>>(x, wt, srb, xr, s, ksz);
        ln_gelu_kernel<<<(rows + 7) / 8, 256>>>(xr, lng, lnb, rows);
        gemm_tc_kernel<<<dim3((rows + 127) / 128, 2), 256>>>(xr, Wkv, bkv, kvb, rows, C_, C_, 128);
        dwconv_kernel<<<(rows * HD_ + 255) / 256, 256>>>(kvb, lcw, lcb, v2, s);
        attn_tc_kernel<<<dim3(N_ / 64, B_), 128, attn_smem>>>(q, kvb, v2, xcat, n, br);
    }

    // Output projection (tf32 TC)
    gemm_tc_kernel<<<dim3((M + 127) / 128, 3), 256>>>(xcat, Wo, bo, (float*)d_out, M, C_, C_, C_);
}

// round 7
// speedup vs baseline: 2.0564x; 1.1511x over previous
#include <cuda_runtime.h>
#include <math.h>
#include <stdint.h>

#define B_    8
#define N_    2304
#define C_    192
#define HW_   48
#define HD_   64
#define NMAX_ 2209   // 47*47

// ---------------- scratch (no allocation allowed; __device__ globals) ----------------
__device__ float g_q[B_ * N_ * C_];
__device__ float g_xr[B_ * NMAX_ * C_];
__device__ float g_kv[B_ * NMAX_ * 128];     // K (cols 0..63) | V (cols 64..127)
__device__ float g_v2[B_ * NMAX_ * HD_];
__device__ float g_xcat[B_ * N_ * C_];
__device__ float g_wt[C_ * C_ * 64];         // [kyx][ci][co]

// ---------------- tf32 / cp.async helpers ----------------
__device__ __forceinline__ uint32_t f2tf(float v) {
    uint32_t r;
    asm("cvt.rna.tf32.f32 %0, %1;" : "=r"(r) : "f"(v));
    return r;
}
__device__ __forceinline__ uint32_t u2tf(uint32_t raw) {
    return f2tf(__uint_as_float(raw));
}
__device__ __forceinline__ void mma_tf32(float* d, const uint32_t* a, const uint32_t* b) {
    asm volatile(
        "mma.sync.aligned.m16n8k8.row.col.f32.tf32.tf32.f32 "
        "{%0,%1,%2,%3}, {%4,%5,%6,%7}, {%8,%9}, {%0,%1,%2,%3};"
        : "+f"(d[0]), "+f"(d[1]), "+f"(d[2]), "+f"(d[3])
        : "r"(a[0]), "r"(a[1]), "r"(a[2]), "r"(a[3]), "r"(b[0]), "r"(b[1]));
}
__device__ __forceinline__ void cp_async16(uint32_t dst, const float* src, uint32_t ssize) {
    asm volatile("cp.async.ca.shared.global [%0], [%1], 16, %2;"
                 :: "r"(dst), "l"(src), "r"(ssize) : "memory");
}
__device__ __forceinline__ void cp_commit() {
    asm volatile("cp.async.commit_group;" ::: "memory");
}
__device__ __forceinline__ void cp_wait1() {
    asm volatile("cp.async.wait_group 1;" ::: "memory");
}
__device__ __forceinline__ void cp_wait0() {
    asm volatile("cp.async.wait_group 0;" ::: "memory");
}

// A tile [128 rows][BK16 + pad4]: A-frag LDS bank = (20*lr + lc) % 32, bijective.
#define ALD2 20
// W tile [16][64 + pad8]: B-frag LDS bank = (8*lc + lr) % 32, bijective.
#define WLD 72
#define NSTAGE 3

// =====================================================================================
// TF32 TC GEMM, cp.async 3-stage pipeline. Tiles 128x64, BK=16.
// 256 thr = 8 warps (4m x 2n), warp tile 32x32.
// =====================================================================================
__global__ __launch_bounds__(256) void gemm_tc_kernel(
    const float* __restrict__ A, const float* __restrict__ W,
    const float* __restrict__ bias, float* __restrict__ out,
    int M, int K, int ldw, int ldc)
{
    __shared__ uint32_t As[NSTAGE][128][ALD2];
    __shared__ uint32_t Ws[NSTAGE][16][WLD];
    const int tid = threadIdx.x;
    const int warp = tid >> 5, lane = tid & 31;
    const int wm = warp & 3, wn = warp >> 2;
    const int lr = lane >> 2, lc = lane & 3;
    const int m0 = blockIdx.x * 128;
    const int n0 = blockIdx.y * 64;

    // prefetch thread mapping
    const int r0 = tid >> 2;            // 0..63 (rows r0 and r0+64)
    const int col4 = (tid & 3) * 4;     // 0,4,8,12 within BK
    const int kr = tid >> 4;            // 0..15 (W k-row)
    const int j4 = (tid & 15) * 4;      // 0..60 (W col)

    const int mA0 = m0 + r0, mA1 = m0 + r0 + 64;
    const uint32_t sz0 = (mA0 < M) ? 16u : 0u;
    const uint32_t sz1 = (mA1 < M) ? 16u : 0u;
    const float* aRow0 = A + (size_t)((mA0 < M) ? mA0 : 0) * K + col4;
    const float* aRow1 = A + (size_t)((mA1 < M) ? mA1 : 0) * K + col4;
    const float* wRow  = W + (size_t)kr * ldw + n0 + j4;

    const uint32_t asb = (uint32_t)__cvta_generic_to_shared(&As[0][0][0]);
    const uint32_t wsb = (uint32_t)__cvta_generic_to_shared(&Ws[0][0][0]);

    auto pf = [&](int kb, int s) {
        int k0 = kb * 16;
        cp_async16(asb + (uint32_t)(((s * 128 + r0) * ALD2 + col4) * 4), aRow0 + k0, sz0);
        cp_async16(asb + (uint32_t)(((s * 128 + r0 + 64) * ALD2 + col4) * 4), aRow1 + k0, sz1);
        cp_async16(wsb + (uint32_t)(((s * 16 + kr) * WLD + j4) * 4),
                   wRow + (size_t)k0 * ldw, 16u);
    };

    float acc[2][4][4];
#pragma unroll
    for (int mi = 0; mi < 2; mi++)
#pragma unroll
        for (int ni = 0; ni < 4; ni++)
#pragma unroll
            for (int j = 0; j < 4; j++) acc[mi][ni][j] = 0.f;

    const int KB = K / 16;
    pf(0, 0); cp_commit();
    if (KB > 1) { pf(1, 1); }
    cp_commit();

    int s = 0;
    for (int kb = 0; kb < KB; kb++) {
        if (kb + 1 < KB) cp_wait1(); else cp_wait0();
        __syncthreads();
        if (kb + 2 < KB) pf(kb + 2, (s + 2) % NSTAGE);
        cp_commit();
#pragma unroll
        for (int ks = 0; ks < 16; ks += 8) {
            uint32_t af[2][4];
#pragma unroll
            for (int mi = 0; mi < 2; mi++) {
                int rr = wm * 32 + mi * 16 + lr;
                af[mi][0] = u2tf(As[s][rr][ks + lc]);
                af[mi][1] = u2tf(As[s][rr + 8][ks + lc]);
                af[mi][2] = u2tf(As[s][rr][ks + 4 + lc]);
                af[mi][3] = u2tf(As[s][rr + 8][ks + 4 + lc]);
            }
            uint32_t bf[4][2];
#pragma unroll
            for (int ni = 0; ni < 4; ni++) {
                int cc = wn * 32 + ni * 8 + lr;
                bf[ni][0] = u2tf(Ws[s][ks + lc][cc]);
                bf[ni][1] = u2tf(Ws[s][ks + 4 + lc][cc]);
            }
#pragma unroll
            for (int mi = 0; mi < 2; mi++)
#pragma unroll
                for (int ni = 0; ni < 4; ni++) mma_tf32(acc[mi][ni], af[mi], bf[ni]);
        }
        s = (s + 1) % NSTAGE;
    }
#pragma unroll
    for (int mi = 0; mi < 2; mi++) {
        int row = m0 + wm * 32 + mi * 16 + lr;
#pragma unroll
        for (int ni = 0; ni < 4; ni++) {
            int col = n0 + wn * 32 + ni * 8 + lc * 2;
            float b0 = bias[col], b1 = bias[col + 1];
            if (row < M) {
                out[(size_t)row * ldc + col]     = acc[mi][ni][0] + b0;
                out[(size_t)row * ldc + col + 1] = acc[mi][ni][1] + b1;
            }
            if (row + 8 < M) {
                out[(size_t)(row + 8) * ldc + col]     = acc[mi][ni][2] + b0;
                out[(size_t)(row + 8) * ldc + col + 1] = acc[mi][ni][3] + b1;
            }
        }
    }
}

// =====================================================================================
// Weight transform: w[co][ci][ky][kx] (OIHW) -> wt[kyx][ci][co]
// =====================================================================================
__global__ void wtrans_kernel(const float* __restrict__ w, float* __restrict__ wt, int ksz)
{
    int k2 = ksz * ksz;
    int total = C_ * C_ * k2;
    for (int idx = blockIdx.x * blockDim.x + threadIdx.x; idx < total;
         idx += gridDim.x * blockDim.x) {
        int co = idx % C_;
        int rest = idx / C_;
        int ci = rest % C_;
        int kyx = rest / C_;
        wt[idx] = w[((size_t)co * C_ + ci) * k2 + kyx];
    }
}

// =====================================================================================
// SR conv as implicit GEMM on tensor cores, cp.async 3-stage pipeline.
// Flattened K: kb -> (kyx, ci0);  K_total = ksz*ksz*12 blocks of 16.
// =====================================================================================
__global__ __launch_bounds__(256) void conv_tc_kernel(
    const float* __restrict__ x, const float* __restrict__ wt,
    const float* __restrict__ bias, float* __restrict__ out,
    int s_, int ksz)
{
    __shared__ uint32_t As[NSTAGE][128][ALD2];
    __shared__ uint32_t Ws[NSTAGE][16][WLD];
    const int tid = threadIdx.x;
    const int warp = tid >> 5, lane = tid & 31;
    const int wm = warp & 3, wn = warp >> 2;
    const int lr = lane >> 2, lc = lane & 3;
    const int b = blockIdx.z;
    const int n = s_ * s_;
    const int m0 = blockIdx.x * 128;
    const int n0 = blockIdx.y * 64;

    const int r0 = tid >> 2;
    const int col4 = (tid & 3) * 4;
    const int kr = tid >> 4;
    const int j4 = (tid & 15) * 4;

    // per-thread A row offsets (rows r0 and r0+64 of the M-tile)
    int p0 = m0 + r0, p1 = m0 + r0 + 64;
    const uint32_t sz0 = (p0 < n) ? 16u : 0u;
    const uint32_t sz1 = (p1 < n) ? 16u : 0u;
    int pp0 = (p0 < n) ? p0 : 0, pp1 = (p1 < n) ? p1 : 0;
    const int rowoff0 = ((pp0 / s_) * HW_ + (pp0 % s_)) * C_;
    const int rowoff1 = ((pp1 / s_) * HW_ + (pp1 % s_)) * C_;
    const float* xb = x + (size_t)b * N_ * C_;

    const uint32_t asb = (uint32_t)__cvta_generic_to_shared(&As[0][0][0]);
    const uint32_t wsb = (uint32_t)__cvta_generic_to_shared(&Ws[0][0][0]);

    auto pf = [&](int kb, int st) {
        int kyx = kb / 12;
        int ci0 = (kb - kyx * 12) * 16;
        int ky = kyx / ksz, kx = kyx - ky * ksz;
        int koff = (ky * HW_ + kx) * C_ + ci0 + col4;
        cp_async16(asb + (uint32_t)(((st * 128 + r0) * ALD2 + col4) * 4),
                   xb + rowoff0 + koff, sz0);
        cp_async16(asb + (uint32_t)(((st * 128 + r0 + 64) * ALD2 + col4) * 4),
                   xb + rowoff1 + koff, sz1);
        cp_async16(wsb + (uint32_t)(((st * 16 + kr) * WLD + j4) * 4),
                   wt + (size_t)kyx * C_ * C_ + (size_t)(ci0 + kr) * C_ + n0 + j4, 16u);
    };

    float acc[2][4][4];
#pragma unroll
    for (int mi = 0; mi < 2; mi++)
#pragma unroll
        for (int ni = 0; ni < 4; ni++)
#pragma unroll
            for (int j = 0; j < 4; j++) acc[mi][ni][j] = 0.f;

    const int KB = ksz * ksz * 12;
    pf(0, 0); cp_commit();
    pf(1, 1); cp_commit();

    int st = 0;
    for (int kb = 0; kb < KB; kb++) {
        if (kb + 1 < KB) cp_wait1(); else cp_wait0();
        __syncthreads();
        if (kb + 2 < KB) pf(kb + 2, (st + 2) % NSTAGE);
        cp_commit();
#pragma unroll
        for (int ks = 0; ks < 16; ks += 8) {
            uint32_t af[2][4];
#pragma unroll
            for (int mi = 0; mi < 2; mi++) {
                int rr = wm * 32 + mi * 16 + lr;
                af[mi][0] = u2tf(As[st][rr][ks + lc]);
                af[mi][1] = u2tf(As[st][rr + 8][ks + lc]);
                af[mi][2] = u2tf(As[st][rr][ks + 4 + lc]);
                af[mi][3] = u2tf(As[st][rr + 8][ks + 4 + lc]);
            }
            uint32_t bf[4][2];
#pragma unroll
            for (int ni = 0; ni < 4; ni++) {
                int cc = wn * 32 + ni * 8 + lr;
                bf[ni][0] = u2tf(Ws[st][ks + lc][cc]);
                bf[ni][1] = u2tf(Ws[st][ks + 4 + lc][cc]);
            }
#pragma unroll
            for (int mi = 0; mi < 2; mi++)
#pragma unroll
                for (int ni = 0; ni < 4; ni++) mma_tf32(acc[mi][ni], af[mi], bf[ni]);
        }
        st = (st + 1) % NSTAGE;
    }
#pragma unroll
    for (int mi = 0; mi < 2; mi++) {
        int row = m0 + wm * 32 + mi * 16 + lr;
#pragma unroll
        for (int ni = 0; ni < 4; ni++) {
            int col = n0 + wn * 32 + ni * 8 + lc * 2;
            float b0 = bias[col], b1 = bias[col + 1];
            if (row < n) {
                float* o = out + ((size_t)b * n + row) * C_ + col;
                o[0] = acc[mi][ni][0] + b0;
                o[1] = acc[mi][ni][1] + b1;
            }
            if (row + 8 < n) {
                float* o = out + ((size_t)b * n + row + 8) * C_ + col;
                o[0] = acc[mi][ni][2] + b0;
                o[1] = acc[mi][ni][3] + b1;
            }
        }
    }
}

// =====================================================================================
// Fused LayerNorm + exact GELU (in-place). One warp per row.
// =====================================================================================
__global__ void ln_gelu_kernel(float* __restrict__ xr, const float* __restrict__ g,
                               const float* __restrict__ bb, int rows)
{
    int wid = (blockIdx.x * blockDim.x + threadIdx.x) >> 5;
    int lane = threadIdx.x & 31;
    if (wid >= rows) return;
    float* row = xr + (size_t)wid * C_;
    float s1 = 0.f, s2 = 0.f;
#pragma unroll
    for (int j = lane; j < C_; j += 32) {
        float v = row[j];
        s1 += v;
        s2 += v * v;
    }
#pragma unroll
    for (int o = 16; o; o >>= 1) {
        s1 += __shfl_xor_sync(0xffffffffu, s1, o);
        s2 += __shfl_xor_sync(0xffffffffu, s2, o);
    }
    float mu = s1 * (1.f / C_);
    float var = s2 * (1.f / C_) - mu * mu;
    float inv = rsqrtf(var + 1e-5f);
#pragma unroll
    for (int j = lane; j < C_; j += 32) {
        float v = (row[j] - mu) * inv * g[j] + bb[j];
        row[j] = 0.5f * v * (1.f + erff(v * 0.70710678118654752440f));
    }
}

// =====================================================================================
// Depthwise 3x3 (pad 1) on V + residual
// =====================================================================================
__global__ void dwconv_kernel(const float* __restrict__ kv, const float* __restrict__ w,
                              const float* __restrict__ bias, float* __restrict__ v2, int s)
{
    int n = s * s;
    int total = B_ * n * HD_;
    int idx = blockIdx.x * blockDim.x + threadIdx.x;
    if (idx >= total) return;
    int hd = idx & 63;
    int p = (idx >> 6) % n;
    int b = idx / (n * 64);
    int y = p / s;
    int x0 = p - y * s;
    const float* vb = kv + (size_t)b * n * 128 + 64 + hd;
    float acc = bias[hd];
#pragma unroll
    for (int dy = -1; dy <= 1; dy++) {
#pragma unroll
        for (int dx = -1; dx <= 1; dx++) {
            int yy = y + dy, xx = x0 + dx;
            if (yy >= 0 && yy < s && xx >= 0 && xx < s)
                acc += w[hd * 9 + (dy + 1) * 3 + (dx + 1)] * vb[(size_t)(yy * s + xx) * 128];
        }
    }
    v2[idx] = acc + vb[(size_t)p * 128];
}

// =====================================================================================
// Tensor-core flash attention (tf32 MMA, fp32 softmax), dynamic smem (72 KB).
// =====================================================================================
#define TLD 72
__global__ __launch_bounds__(128) void attn_tc_kernel(
    const float* __restrict__ q, const float* __restrict__ kv,
    const float* __restrict__ v2, float* __restrict__ xcat,
    int nkv, int head)
{
    extern __shared__ uint32_t smbuf[];
    uint32_t (*qs)[TLD]  = (uint32_t (*)[TLD])smbuf;
    uint32_t (*kst)[TLD] = (uint32_t (*)[TLD])(smbuf + 64 * TLD);
    uint32_t (*vs)[TLD]  = (uint32_t (*)[TLD])(smbuf + 2 * 64 * TLD);
    uint32_t (*ps)[TLD]  = (uint32_t (*)[TLD])(smbuf + 3 * 64 * TLD);

    const int tid = threadIdx.x;
    const int warp = tid >> 5, lane = tid & 31;
    const int wm = warp;
    const int lr = lane >> 2, lc = lane & 3;
    const int b = blockIdx.y;
    const int q0 = blockIdx.x * 64;
    const int rr = wm * 16 + lr;
    const float scale = 0.07216878364870322056f;  // 1/sqrt(192)

#pragma unroll
    for (int i = 0; i < 32; i++) {
        int e = tid + i * 128;
        int r = e >> 6, d = e & 63;
        qs[d][r] = f2tf(q[((size_t)b * N_ + q0 + r) * C_ + head * HD_ + d]);
    }

    float m_i[2], l_i[2], oacc[8][4];
    m_i[0] = m_i[1] = -1e30f;
    l_i[0] = l_i[1] = 0.f;
#pragma unroll
    for (int ni = 0; ni < 8; ni++)
#pragma unroll
        for (int j = 0; j < 4; j++) oacc[ni][j] = 0.f;

    __syncthreads();

    const int nchunks = (nkv + 63) >> 6;
    for (int c0 = 0; c0 < nchunks; c0++) {
        int base = c0 * 64;
        int cs = nkv - base;
        if (cs > 64) cs = 64;
#pragma unroll
        for (int i = 0; i < 32; i++) {
            int e = tid + i * 128;
            int r = e >> 6, d = e & 63;
            if (r < cs) {
                size_t kidx = (size_t)b * nkv + base + r;
                kst[d][r] = f2tf(kv[kidx * 128 + d]);
                vs[r][d]  = f2tf(v2[kidx * 64 + d]);
            } else {
                kst[d][r] = 0u;
                vs[r][d]  = 0u;
            }
        }
        __syncthreads();

        float sacc[8][4];
#pragma unroll
        for (int ni = 0; ni < 8; ni++)
#pragma unroll
            for (int j = 0; j < 4; j++) sacc[ni][j] = 0.f;
#pragma unroll
        for (int kk = 0; kk < 64; kk += 8) {
            uint32_t af[4];
            af[0] = qs[kk + lc][rr];
            af[1] = qs[kk + lc][rr + 8];
            af[2] = qs[kk + 4 + lc][rr];
            af[3] = qs[kk + 4 + lc][rr + 8];
#pragma unroll
            for (int ni = 0; ni < 8; ni++) {
                uint32_t bf[2];
                int cc = ni * 8 + lr;
                bf[0] = kst[kk + lc][cc];
                bf[1] = kst[kk + 4 + lc][cc];
                mma_tf32(sacc[ni], af, bf);
            }
        }

#pragma unroll
        for (int h = 0; h < 2; h++) {
            float mx = -1e30f;
#pragma unroll
            for (int ni = 0; ni < 8; ni++)
#pragma unroll
                for (int j = 0; j < 2; j++) {
                    float v = sacc[ni][2 * h + j] * scale;
                    if (ni * 8 + 2 * lc + j >= cs) v = -1e30f;
                    sacc[ni][2 * h + j] = v;
                    mx = fmaxf(mx, v);
                }
            mx = fmaxf(mx, __shfl_xor_sync(0xffffffffu, mx, 1));
            mx = fmaxf(mx, __shfl_xor_sync(0xffffffffu, mx, 2));
            float mnew = fmaxf(m_i[h], mx);
            float alpha = __expf(m_i[h] - mnew);
            float rs = 0.f;
#pragma unroll
            for (int ni = 0; ni < 8; ni++)
#pragma unroll
                for (int j = 0; j < 2; j++) {
                    float p = __expf(sacc[ni][2 * h + j] - mnew);
                    sacc[ni][2 * h + j] = p;
                    rs += p;
                }
            rs += __shfl_xor_sync(0xffffffffu, rs, 1);
            rs += __shfl_xor_sync(0xffffffffu, rs, 2);
            l_i[h] = l_i[h] * alpha + rs;
            m_i[h] = mnew;
#pragma unroll
            for (int ni = 0; ni < 8; ni++) {
                oacc[ni][2 * h]     *= alpha;
                oacc[ni][2 * h + 1] *= alpha;
            }
        }

#pragma unroll
        for (int ni = 0; ni < 8; ni++) {
            int c = ni * 8 + 2 * lc;
            ps[c][rr]         = f2tf(sacc[ni][0]);
            ps[c + 1][rr]     = f2tf(sacc[ni][1]);
            ps[c][rr + 8]     = f2tf(sacc[ni][2]);
            ps[c + 1][rr + 8] = f2tf(sacc[ni][3]);
        }
        __syncwarp();

#pragma unroll
        for (int kk = 0; kk < 64; kk += 8) {
            uint32_t af[4];
            af[0] = ps[kk + lc][rr];
            af[1] = ps[kk + lc][rr + 8];
            af[2] = ps[kk + 4 + lc][rr];
            af[3] = ps[kk + 4 + lc][rr + 8];
#pragma unroll
            for (int ni = 0; ni < 8; ni++) {
                uint32_t bf[2];
                int cc = ni * 8 + lr;
                bf[0] = vs[kk + lc][cc];
                bf[1] = vs[kk + 4 + lc][cc];
                mma_tf32(oacc[ni], af, bf);
            }
        }
        __syncthreads();
    }

    float inv0 = 1.f / l_i[0], inv1 = 1.f / l_i[1];
#pragma unroll
    for (int ni = 0; ni < 8; ni++) {
        int col = head * HD_ + ni * 8 + 2 * lc;
        size_t r0 = (size_t)b * N_ + q0 + rr;
        xcat[r0 * C_ + col]           = oacc[ni][0] * inv0;
        xcat[r0 * C_ + col + 1]       = oacc[ni][1] * inv0;
        xcat[(r0 + 8) * C_ + col]     = oacc[ni][2] * inv1;
        xcat[(r0 + 8) * C_ + col + 1] = oacc[ni][3] * inv1;
    }
}

// =====================================================================================
// Host orchestration
// =====================================================================================
extern "C" void kernel_launch(void* const* d_in, const int* in_sizes, int n_in,
                              void* d_out, int out_size)
{
    const float* x   = (const float*)d_in[0];
    const float* Wq  = (const float*)d_in[1];
    const float* bq  = (const float*)d_in[2];
    const float* Wkv = (const float*)d_in[3];
    const float* bkv = (const float*)d_in[4];
    const float* Wo  = (const float*)d_in[23];
    const float* bo  = (const float*)d_in[24];

    float *q, *xr, *kvb, *v2, *xcat, *wt;
    cudaGetSymbolAddress((void**)&q, g_q);
    cudaGetSymbolAddress((void**)&xr, g_xr);
    cudaGetSymbolAddress((void**)&kvb, g_kv);
    cudaGetSymbolAddress((void**)&v2, g_v2);
    cudaGetSymbolAddress((void**)&xcat, g_xcat);
    cudaGetSymbolAddress((void**)&wt, g_wt);

    const int attn_smem = 4 * 64 * TLD * (int)sizeof(uint32_t);  // 73728 B
    cudaFuncSetAttribute(attn_tc_kernel, cudaFuncAttributeMaxDynamicSharedMemorySize,
                         attn_smem);

    const int M = B_ * N_;  // 18432

    gemm_tc_kernel<<<dim3((M + 127) / 128, 3), 256>>>(x, Wq, bq, q, M, C_, C_, C_);

    const int ks_arr[3] = {8, 4, 2};
    for (int br = 0; br < 3; br++) {
        const float* srw = (const float*)d_in[5 + br * 6 + 0];
        const float* srb = (const float*)d_in[5 + br * 6 + 1];
        const float* lng = (const float*)d_in[5 + br * 6 + 2];
        const float* lnb = (const float*)d_in[5 + br * 6 + 3];
        const float* lcw = (const float*)d_in[5 + br * 6 + 4];
        const float* lcb = (const float*)d_in[5 + br * 6 + 5];
        int ksz = ks_arr[br];
        int s = HW_ - ksz + 1;
        int n = s * s;
        int rows = B_ * n;

        wtrans_kernel<<<256, 256>>>(srw, wt, ksz);
        conv_tc_kernel<<<dim3((n + 127) / 128, 3, B_), 256>>>(x, wt, srb, xr, s, ksz);
        ln_gelu_kernel<<<(rows + 7) / 8, 256>>>(xr, lng, lnb, rows);
        gemm_tc_kernel<<<dim3((rows + 127) / 128, 2), 256>>>(xr, Wkv, bkv, kvb, rows, C_, C_, 128);
        dwconv_kernel<<<(rows * HD_ + 255) / 256, 256>>>(kvb, lcw, lcb, v2, s);
        attn_tc_kernel<<<dim3(N_ / 64, B_), 128, attn_smem>>>(q, kvb, v2, xcat, n, br);
    }

    gemm_tc_kernel<<<dim3((M + 127) / 128, 3), 256>>>(xcat, Wo, bo, (float*)d_out, M, C_, C_, C_);
}

// round 8
// speedup vs baseline: 2.3111x; 1.1238x over previous
#include <cuda_runtime.h>
#include <math.h>
#include <stdint.h>

#define B_    8
#define N_    2304
#define C_    192
#define HW_   48
#define HD_   64
#define NMAX_ 2209   // 47*47

// ---------------- scratch ----------------
__device__ float g_q[B_ * N_ * C_];
__device__ float g_xr[B_ * NMAX_ * C_];
__device__ float g_kv[B_ * NMAX_ * 128];
__device__ float g_v2[B_ * NMAX_ * HD_];
__device__ float g_xcat[B_ * N_ * C_];
__device__ float g_wt[C_ * C_ * 64];         // [kyx][ci][co], tf32-rounded
__device__ float g_xtf[B_ * N_ * C_];        // x, tf32-rounded
__device__ float g_wq[C_ * C_];              // tf32-rounded weights
__device__ float g_wkv[C_ * C_];
__device__ float g_wo[C_ * C_];

// ---------------- helpers ----------------
__device__ __forceinline__ uint32_t f2tf(float v) {
    uint32_t r;
    asm("cvt.rna.tf32.f32 %0, %1;" : "=r"(r) : "f"(v));
    return r;
}
__device__ __forceinline__ float roundtf(float v) { return __uint_as_float(f2tf(v)); }
__device__ __forceinline__ void mma_tf32(float* d, const uint32_t* a, const uint32_t* b) {
    asm volatile(
        "mma.sync.aligned.m16n8k8.row.col.f32.tf32.tf32.f32 "
        "{%0,%1,%2,%3}, {%4,%5,%6,%7}, {%8,%9}, {%0,%1,%2,%3};"
        : "+f"(d[0]), "+f"(d[1]), "+f"(d[2]), "+f"(d[3])
        : "r"(a[0]), "r"(a[1]), "r"(a[2]), "r"(a[3]), "r"(b[0]), "r"(b[1]));
}
__device__ __forceinline__ void cp_async16(uint32_t dst, const float* src, uint32_t ssize) {
    asm volatile("cp.async.cg.shared.global [%0], [%1], 16, %2;"
                 :: "r"(dst), "l"(src), "r"(ssize) : "memory");
}
__device__ __forceinline__ void cp_commit() {
    asm volatile("cp.async.commit_group;" ::: "memory");
}
__device__ __forceinline__ void cp_wait1() {
    asm volatile("cp.async.wait_group 1;" ::: "memory");
}
__device__ __forceinline__ void cp_wait0() {
    asm volatile("cp.async.wait_group 0;" ::: "memory");
}

// BK=32. A tile [128][36]: A-frag bank = (4*lr + lc) -> bijective, conflict-free.
// W tile [32][72]: B-frag bank = (8*lc + lr) -> bijective, conflict-free.
#define BK    32
#define ALD2  36
#define WLD   72
#define NSTAGE 3
#define A_STAGE (128 * ALD2)
#define W_STAGE (BK * WLD)
#define PIPE_BYTES (NSTAGE * (A_STAGE + W_STAGE) * 4)   // 82944

// =====================================================================================
// Elementwise tf32 pre-round
// =====================================================================================
__global__ void round_tf32_kernel(const float* __restrict__ in, float* __restrict__ out,
                                  int n)
{
    int i = blockIdx.x * blockDim.x + threadIdx.x;
    if (i < n) out[i] = roundtf(in[i]);
}

// =====================================================================================
// TF32 TC GEMM, BK=32, cp.async 3-stage. Inputs pre-rounded to tf32 values.
// Tiles 128x64. 256 thr = 8 warps (4m x 2n), warp tile 32x32.
// =====================================================================================
__global__ __launch_bounds__(256) void gemm_tc_kernel(
    const float* __restrict__ A, const float* __restrict__ W,
    const float* __restrict__ bias, float* __restrict__ out,
    int M, int K, int ldw, int ldc)
{
    extern __shared__ uint32_t sm[];
    uint32_t* As = sm;                       // [NSTAGE][128][ALD2]
    uint32_t* Ws = sm + NSTAGE * A_STAGE;    // [NSTAGE][BK][WLD]

    const int tid = threadIdx.x;
    const int warp = tid >> 5, lane = tid & 31;
    const int wm = warp & 3, wn = warp >> 2;
    const int lr = lane >> 2, lc = lane & 3;
    const int m0 = blockIdx.x * 128;
    const int n0 = blockIdx.y * 64;

    // prefetch mapping: A: 4 rows/thread, W: 2 rows/thread
    const int arow = tid >> 3;               // base row 0..31 (rows arow + i*32)
    const int ac4 = (tid & 7) * 4;           // col 0..28
    const int wrow = tid >> 4;               // 0..15 (rows wrow + i*16)
    const int wc4 = (tid & 15) * 4;

    const float* aPtr[4];
    uint32_t aSz[4];
#pragma unroll
    for (int i = 0; i < 4; i++) {
        int m = m0 + arow + i * 32;
        aSz[i] = (m < M) ? 16u : 0u;
        aPtr[i] = A + (size_t)((m < M) ? m : 0) * K + ac4;
    }
    const uint32_t asb = (uint32_t)__cvta_generic_to_shared(As);
    const uint32_t wsb = (uint32_t)__cvta_generic_to_shared(Ws);

    auto pf = [&](int kb, int s) {
        int k0 = kb * BK;
#pragma unroll
        for (int i = 0; i < 4; i++)
            cp_async16(asb + (uint32_t)(((s * 128 + arow + i * 32) * ALD2 + ac4) * 4),
                       aPtr[i] + k0, aSz[i]);
#pragma unroll
        for (int i = 0; i < 2; i++)
            cp_async16(wsb + (uint32_t)(((s * BK + wrow + i * 16) * WLD + wc4) * 4),
                       W + (size_t)(k0 + wrow + i * 16) * ldw + n0 + wc4, 16u);
    };

    float acc[2][4][4];
#pragma unroll
    for (int mi = 0; mi < 2; mi++)
#pragma unroll
        for (int ni = 0; ni < 4; ni++)
#pragma unroll
            for (int j = 0; j < 4; j++) acc[mi][ni][j] = 0.f;

    const int KB = K / BK;
    pf(0, 0); cp_commit();
    if (KB > 1) pf(1, 1);
    cp_commit();

    int s = 0;
    for (int kb = 0; kb < KB; kb++) {
        if (kb + 1 < KB) cp_wait1(); else cp_wait0();
        __syncthreads();
        if (kb + 2 < KB) pf(kb + 2, (s + 2) % NSTAGE);
        cp_commit();
        const uint32_t* as = As + s * A_STAGE;
        const uint32_t* ws = Ws + s * W_STAGE;
#pragma unroll
        for (int ks = 0; ks < BK; ks += 8) {
            uint32_t af[2][4];
#pragma unroll
            for (int mi = 0; mi < 2; mi++) {
                int rr = wm * 32 + mi * 16 + lr;
                af[mi][0] = as[rr * ALD2 + ks + lc];
                af[mi][1] = as[(rr + 8) * ALD2 + ks + lc];
                af[mi][2] = as[rr * ALD2 + ks + 4 + lc];
                af[mi][3] = as[(rr + 8) * ALD2 + ks + 4 + lc];
            }
            uint32_t bf[4][2];
#pragma unroll
            for (int ni = 0; ni < 4; ni++) {
                int cc = wn * 32 + ni * 8 + lr;
                bf[ni][0] = ws[(ks + lc) * WLD + cc];
                bf[ni][1] = ws[(ks + 4 + lc) * WLD + cc];
            }
#pragma unroll
            for (int mi = 0; mi < 2; mi++)
#pragma unroll
                for (int ni = 0; ni < 4; ni++) mma_tf32(acc[mi][ni], af[mi], bf[ni]);
        }
        s = (s + 1) % NSTAGE;
    }
#pragma unroll
    for (int mi = 0; mi < 2; mi++) {
        int row = m0 + wm * 32 + mi * 16 + lr;
#pragma unroll
        for (int ni = 0; ni < 4; ni++) {
            int col = n0 + wn * 32 + ni * 8 + lc * 2;
            float b0 = bias[col], b1 = bias[col + 1];
            if (row < M) {
                out[(size_t)row * ldc + col]     = acc[mi][ni][0] + b0;
                out[(size_t)row * ldc + col + 1] = acc[mi][ni][1] + b1;
            }
            if (row + 8 < M) {
                out[(size_t)(row + 8) * ldc + col]     = acc[mi][ni][2] + b0;
                out[(size_t)(row + 8) * ldc + col + 1] = acc[mi][ni][3] + b1;
            }
        }
    }
}

// =====================================================================================
// Weight transform + tf32 round: w[co][ci][ky][kx] -> wt[kyx][ci][co]
// =====================================================================================
__global__ void wtrans_kernel(const float* __restrict__ w, float* __restrict__ wt, int ksz)
{
    int k2 = ksz * ksz;
    int total = C_ * C_ * k2;
    for (int idx = blockIdx.x * blockDim.x + threadIdx.x; idx < total;
         idx += gridDim.x * blockDim.x) {
        int co = idx % C_;
        int rest = idx / C_;
        int ci = rest % C_;
        int kyx = rest / C_;
        wt[idx] = roundtf(w[((size_t)co * C_ + ci) * k2 + kyx]);
    }
}

// =====================================================================================
// SR conv as implicit GEMM, BK=32, cp.async 3-stage. kb -> (kyx, ci0); KB = ksz*ksz*6.
// =====================================================================================
__global__ __launch_bounds__(256) void conv_tc_kernel(
    const float* __restrict__ x, const float* __restrict__ wt,
    const float* __restrict__ bias, float* __restrict__ out,
    int s_, int ksz)
{
    extern __shared__ uint32_t sm[];
    uint32_t* As = sm;
    uint32_t* Ws = sm + NSTAGE * A_STAGE;

    const int tid = threadIdx.x;
    const int warp = tid >> 5, lane = tid & 31;
    const int wm = warp & 3, wn = warp >> 2;
    const int lr = lane >> 2, lc = lane & 3;
    const int b = blockIdx.z;
    const int n = s_ * s_;
    const int m0 = blockIdx.x * 128;
    const int n0 = blockIdx.y * 64;

    const int arow = tid >> 3;
    const int ac4 = (tid & 7) * 4;
    const int wrow = tid >> 4;
    const int wc4 = (tid & 15) * 4;

    int rowoff[4];
    uint32_t aSz[4];
#pragma unroll
    for (int i = 0; i < 4; i++) {
        int p = m0 + arow + i * 32;
        aSz[i] = (p < n) ? 16u : 0u;
        int pp = (p < n) ? p : 0;
        rowoff[i] = ((pp / s_) * HW_ + (pp % s_)) * C_;
    }
    const float* xb = x + (size_t)b * N_ * C_;

    const uint32_t asb = (uint32_t)__cvta_generic_to_shared(As);
    const uint32_t wsb = (uint32_t)__cvta_generic_to_shared(Ws);

    auto pf = [&](int kb, int st) {
        int kyx = kb / 6;
        int ci0 = (kb - kyx * 6) * BK;
        int ky = kyx / ksz, kx = kyx - ky * ksz;
        int koff = (ky * HW_ + kx) * C_ + ci0 + ac4;
#pragma unroll
        for (int i = 0; i < 4; i++)
            cp_async16(asb + (uint32_t)(((st * 128 + arow + i * 32) * ALD2 + ac4) * 4),
                       xb + rowoff[i] + koff, aSz[i]);
        const float* wp = wt + (size_t)kyx * C_ * C_ + (size_t)ci0 * C_ + n0 + wc4;
#pragma unroll
        for (int i = 0; i < 2; i++)
            cp_async16(wsb + (uint32_t)(((st * BK + wrow + i * 16) * WLD + wc4) * 4),
                       wp + (size_t)(wrow + i * 16) * C_, 16u);
    };

    float acc[2][4][4];
#pragma unroll
    for (int mi = 0; mi < 2; mi++)
#pragma unroll
        for (int ni = 0; ni < 4; ni++)
#pragma unroll
            for (int j = 0; j < 4; j++) acc[mi][ni][j] = 0.f;

    const int KB = ksz * ksz * 6;
    pf(0, 0); cp_commit();
    pf(1, 1); cp_commit();

    int st = 0;
    for (int kb = 0; kb < KB; kb++) {
        if (kb + 1 < KB) cp_wait1(); else cp_wait0();
        __syncthreads();
        if (kb + 2 < KB) pf(kb + 2, (st + 2) % NSTAGE);
        cp_commit();
        const uint32_t* as = As + st * A_STAGE;
        const uint32_t* ws = Ws + st * W_STAGE;
#pragma unroll
        for (int ks = 0; ks < BK; ks += 8) {
            uint32_t af[2][4];
#pragma unroll
            for (int mi = 0; mi < 2; mi++) {
                int rr = wm * 32 + mi * 16 + lr;
                af[mi][0] = as[rr * ALD2 + ks + lc];
                af[mi][1] = as[(rr + 8) * ALD2 + ks + lc];
                af[mi][2] = as[rr * ALD2 + ks + 4 + lc];
                af[mi][3] = as[(rr + 8) * ALD2 + ks + 4 + lc];
            }
            uint32_t bf[4][2];
#pragma unroll
            for (int ni = 0; ni < 4; ni++) {
                int cc = wn * 32 + ni * 8 + lr;
                bf[ni][0] = ws[(ks + lc) * WLD + cc];
                bf[ni][1] = ws[(ks + 4 + lc) * WLD + cc];
            }
#pragma unroll
            for (int mi = 0; mi < 2; mi++)
#pragma unroll
                for (int ni = 0; ni < 4; ni++) mma_tf32(acc[mi][ni], af[mi], bf[ni]);
        }
        st = (st + 1) % NSTAGE;
    }
#pragma unroll
    for (int mi = 0; mi < 2; mi++) {
        int row = m0 + wm * 32 + mi * 16 + lr;
#pragma unroll
        for (int ni = 0; ni < 4; ni++) {
            int col = n0 + wn * 32 + ni * 8 + lc * 2;
            float b0 = bias[col], b1 = bias[col + 1];
            if (row < n) {
                float* o = out + ((size_t)b * n + row) * C_ + col;
                o[0] = acc[mi][ni][0] + b0;
                o[1] = acc[mi][ni][1] + b1;
            }
            if (row + 8 < n) {
                float* o = out + ((size_t)b * n + row + 8) * C_ + col;
                o[0] = acc[mi][ni][2] + b0;
                o[1] = acc[mi][ni][3] + b1;
            }
        }
    }
}

// =====================================================================================
// Fused LayerNorm + exact GELU, output rounded to tf32 values. One warp per row.
// =====================================================================================
__global__ void ln_gelu_kernel(float* __restrict__ xr, const float* __restrict__ g,
                               const float* __restrict__ bb, int rows)
{
    int wid = (blockIdx.x * blockDim.x + threadIdx.x) >> 5;
    int lane = threadIdx.x & 31;
    if (wid >= rows) return;
    float* row = xr + (size_t)wid * C_;
    float s1 = 0.f, s2 = 0.f;
#pragma unroll
    for (int j = lane; j < C_; j += 32) {
        float v = row[j];
        s1 += v;
        s2 += v * v;
    }
#pragma unroll
    for (int o = 16; o; o >>= 1) {
        s1 += __shfl_xor_sync(0xffffffffu, s1, o);
        s2 += __shfl_xor_sync(0xffffffffu, s2, o);
    }
    float mu = s1 * (1.f / C_);
    float var = s2 * (1.f / C_) - mu * mu;
    float inv = rsqrtf(var + 1e-5f);
#pragma unroll
    for (int j = lane; j < C_; j += 32) {
        float v = (row[j] - mu) * inv * g[j] + bb[j];
        row[j] = roundtf(0.5f * v * (1.f + erff(v * 0.70710678118654752440f)));
    }
}

// =====================================================================================
// Depthwise 3x3 (pad 1) on V + residual
// =====================================================================================
__global__ void dwconv_kernel(const float* __restrict__ kv, const float* __restrict__ w,
                              const float* __restrict__ bias, float* __restrict__ v2, int s)
{
    int n = s * s;
    int total = B_ * n * HD_;
    int idx = blockIdx.x * blockDim.x + threadIdx.x;
    if (idx >= total) return;
    int hd = idx & 63;
    int p = (idx >> 6) % n;
    int b = idx / (n * 64);
    int y = p / s;
    int x0 = p - y * s;
    const float* vb = kv + (size_t)b * n * 128 + 64 + hd;
    float acc = bias[hd];
#pragma unroll
    for (int dy = -1; dy <= 1; dy++) {
#pragma unroll
        for (int dx = -1; dx <= 1; dx++) {
            int yy = y + dy, xx = x0 + dx;
            if (yy >= 0 && yy < s && xx >= 0 && xx < s)
                acc += w[hd * 9 + (dy + 1) * 3 + (dx + 1)] * vb[(size_t)(yy * s + xx) * 128];
        }
    }
    v2[idx] = acc + vb[(size_t)p * 128];
}

// =====================================================================================
// Tensor-core flash attention (tf32 MMA, fp32 softmax), dynamic smem (72 KB).
// Epilogue rounds xcat to tf32 values (it feeds only the O-projection GEMM).
// =====================================================================================
#define TLD 72
__global__ __launch_bounds__(128) void attn_tc_kernel(
    const float* __restrict__ q, const float* __restrict__ kv,
    const float* __restrict__ v2, float* __restrict__ xcat,
    int nkv, int head)
{
    extern __shared__ uint32_t smbuf[];
    uint32_t (*qs)[TLD]  = (uint32_t (*)[TLD])smbuf;
    uint32_t (*kst)[TLD] = (uint32_t (*)[TLD])(smbuf + 64 * TLD);
    uint32_t (*vs)[TLD]  = (uint32_t (*)[TLD])(smbuf + 2 * 64 * TLD);
    uint32_t (*ps)[TLD]  = (uint32_t (*)[TLD])(smbuf + 3 * 64 * TLD);

    const int tid = threadIdx.x;
    const int warp = tid >> 5, lane = tid & 31;
    const int wm = warp;
    const int lr = lane >> 2, lc = lane & 3;
    const int b = blockIdx.y;
    const int q0 = blockIdx.x * 64;
    const int rr = wm * 16 + lr;
    const float scale = 0.07216878364870322056f;  // 1/sqrt(192)

#pragma unroll
    for (int i = 0; i < 32; i++) {
        int e = tid + i * 128;
        int r = e >> 6, d = e & 63;
        qs[d][r] = f2tf(q[((size_t)b * N_ + q0 + r) * C_ + head * HD_ + d]);
    }

    float m_i[2], l_i[2], oacc[8][4];
    m_i[0] = m_i[1] = -1e30f;
    l_i[0] = l_i[1] = 0.f;
#pragma unroll
    for (int ni = 0; ni < 8; ni++)
#pragma unroll
        for (int j = 0; j < 4; j++) oacc[ni][j] = 0.f;

    __syncthreads();

    const int nchunks = (nkv + 63) >> 6;
    for (int c0 = 0; c0 < nchunks; c0++) {
        int base = c0 * 64;
        int cs = nkv - base;
        if (cs > 64) cs = 64;
#pragma unroll
        for (int i = 0; i < 32; i++) {
            int e = tid + i * 128;
            int r = e >> 6, d = e & 63;
            if (r < cs) {
                size_t kidx = (size_t)b * nkv + base + r;
                kst[d][r] = f2tf(kv[kidx * 128 + d]);
                vs[r][d]  = f2tf(v2[kidx * 64 + d]);
            } else {
                kst[d][r] = 0u;
                vs[r][d]  = 0u;
            }
        }
        __syncthreads();

        float sacc[8][4];
#pragma unroll
        for (int ni = 0; ni < 8; ni++)
#pragma unroll
            for (int j = 0; j < 4; j++) sacc[ni][j] = 0.f;
#pragma unroll
        for (int kk = 0; kk < 64; kk += 8) {
            uint32_t af[4];
            af[0] = qs[kk + lc][rr];
            af[1] = qs[kk + lc][rr + 8];
            af[2] = qs[kk + 4 + lc][rr];
            af[3] = qs[kk + 4 + lc][rr + 8];
#pragma unroll
            for (int ni = 0; ni < 8; ni++) {
                uint32_t bf[2];
                int cc = ni * 8 + lr;
                bf[0] = kst[kk + lc][cc];
                bf[1] = kst[kk + 4 + lc][cc];
                mma_tf32(sacc[ni], af, bf);
            }
        }

#pragma unroll
        for (int h = 0; h < 2; h++) {
            float mx = -1e30f;
#pragma unroll
            for (int ni = 0; ni < 8; ni++)
#pragma unroll
                for (int j = 0; j < 2; j++) {
                    float v = sacc[ni][2 * h + j] * scale;
                    if (ni * 8 + 2 * lc + j >= cs) v = -1e30f;
                    sacc[ni][2 * h + j] = v;
                    mx = fmaxf(mx, v);
                }
            mx = fmaxf(mx, __shfl_xor_sync(0xffffffffu, mx, 1));
            mx = fmaxf(mx, __shfl_xor_sync(0xffffffffu, mx, 2));
            float mnew = fmaxf(m_i[h], mx);
            float alpha = __expf(m_i[h] - mnew);
            float rs = 0.f;
#pragma unroll
            for (int ni = 0; ni < 8; ni++)
#pragma unroll
                for (int j = 0; j < 2; j++) {
                    float p = __expf(sacc[ni][2 * h + j] - mnew);
                    sacc[ni][2 * h + j] = p;
                    rs += p;
                }
            rs += __shfl_xor_sync(0xffffffffu, rs, 1);
            rs += __shfl_xor_sync(0xffffffffu, rs, 2);
            l_i[h] = l_i[h] * alpha + rs;
            m_i[h] = mnew;
#pragma unroll
            for (int ni = 0; ni < 8; ni++) {
                oacc[ni][2 * h]     *= alpha;
                oacc[ni][2 * h + 1] *= alpha;
            }
        }

#pragma unroll
        for (int ni = 0; ni < 8; ni++) {
            int c = ni * 8 + 2 * lc;
            ps[c][rr]         = f2tf(sacc[ni][0]);
            ps[c + 1][rr]     = f2tf(sacc[ni][1]);
            ps[c][rr + 8]     = f2tf(sacc[ni][2]);
            ps[c + 1][rr + 8] = f2tf(sacc[ni][3]);
        }
        __syncwarp();

#pragma unroll
        for (int kk = 0; kk < 64; kk += 8) {
            uint32_t af[4];
            af[0] = ps[kk + lc][rr];
            af[1] = ps[kk + lc][rr + 8];
            af[2] = ps[kk + 4 + lc][rr];
            af[3] = ps[kk + 4 + lc][rr + 8];
#pragma unroll
            for (int ni = 0; ni < 8; ni++) {
                uint32_t bf[2];
                int cc = ni * 8 + lr;
                bf[0] = vs[kk + lc][cc];
                bf[1] = vs[kk + 4 + lc][cc];
                mma_tf32(oacc[ni], af, bf);
            }
        }
        __syncthreads();
    }

    float inv0 = 1.f / l_i[0], inv1 = 1.f / l_i[1];
#pragma unroll
    for (int ni = 0; ni < 8; ni++) {
        int col = head * HD_ + ni * 8 + 2 * lc;
        size_t r0 = (size_t)b * N_ + q0 + rr;
        xcat[r0 * C_ + col]           = roundtf(oacc[ni][0] * inv0);
        xcat[r0 * C_ + col + 1]       = roundtf(oacc[ni][1] * inv0);
        xcat[(r0 + 8) * C_ + col]     = roundtf(oacc[ni][2] * inv1);
        xcat[(r0 + 8) * C_ + col + 1] = roundtf(oacc[ni][3] * inv1);
    }
}

// =====================================================================================
// Host orchestration
// =====================================================================================
extern "C" void kernel_launch(void* const* d_in, const int* in_sizes, int n_in,
                              void* d_out, int out_size)
{
    const float* x   = (const float*)d_in[0];
    const float* Wq  = (const float*)d_in[1];
    const float* bq  = (const float*)d_in[2];
    const float* Wkv = (const float*)d_in[3];
    const float* bkv = (const float*)d_in[4];
    const float* Wo  = (const float*)d_in[23];
    const float* bo  = (const float*)d_in[24];

    float *q, *xr, *kvb, *v2, *xcat, *wt, *xtf, *wq, *wkv, *wo;
    cudaGetSymbolAddress((void**)&q, g_q);
    cudaGetSymbolAddress((void**)&xr, g_xr);
    cudaGetSymbolAddress((void**)&kvb, g_kv);
    cudaGetSymbolAddress((void**)&v2, g_v2);
    cudaGetSymbolAddress((void**)&xcat, g_xcat);
    cudaGetSymbolAddress((void**)&wt, g_wt);
    cudaGetSymbolAddress((void**)&xtf, g_xtf);
    cudaGetSymbolAddress((void**)&wq, g_wq);
    cudaGetSymbolAddress((void**)&wkv, g_wkv);
    cudaGetSymbolAddress((void**)&wo, g_wo);

    const int attn_smem = 4 * 64 * TLD * (int)sizeof(uint32_t);  // 73728
    cudaFuncSetAttribute(attn_tc_kernel, cudaFuncAttributeMaxDynamicSharedMemorySize,
                         attn_smem);
    cudaFuncSetAttribute(gemm_tc_kernel, cudaFuncAttributeMaxDynamicSharedMemorySize,
                         PIPE_BYTES);
    cudaFuncSetAttribute(conv_tc_kernel, cudaFuncAttributeMaxDynamicSharedMemorySize,
                         PIPE_BYTES);

    const int M = B_ * N_;  // 18432
    const int NX = B_ * N_ * C_;

    // pre-round operands to tf32 values (idempotent under later cvt.rna)
    round_tf32_kernel<<<(NX + 255) / 256, 256>>>(x, xtf, NX);
    round_tf32_kernel<<<(C_ * C_ + 255) / 256, 256>>>(Wq, wq, C_ * C_);
    round_tf32_kernel<<<(C_ * C_ + 255) / 256, 256>>>(Wkv, wkv, C_ * C_);
    round_tf32_kernel<<<(C_ * C_ + 255) / 256, 256>>>(Wo, wo, C_ * C_);

    gemm_tc_kernel<<<dim3((M + 127) / 128, 3), 256, PIPE_BYTES>>>(
        xtf, wq, bq, q, M, C_, C_, C_);

    const int ks_arr[3] = {8, 4, 2};
    for (int br = 0; br < 3; br++) {
        const float* srw = (const float*)d_in[5 + br * 6 + 0];
        const float* srb = (const float*)d_in[5 + br * 6 + 1];
        const float* lng = (const float*)d_in[5 + br * 6 + 2];
        const float* lnb = (const float*)d_in[5 + br * 6 + 3];
        const float* lcw = (const float*)d_in[5 + br * 6 + 4];
        const float* lcb = (const float*)d_in[5 + br * 6 + 5];
        int ksz = ks_arr[br];
        int s = HW_ - ksz + 1;
        int n = s * s;
        int rows = B_ * n;

        wtrans_kernel<<<256, 256>>>(srw, wt, ksz);
        conv_tc_kernel<<<dim3((n + 127) / 128, 3, B_), 256, PIPE_BYTES>>>(
            xtf, wt, srb, xr, s, ksz);
        ln_gelu_kernel<<<(rows + 7) / 8, 256>>>(xr, lng, lnb, rows);
        gemm_tc_kernel<<<dim3((rows + 127) / 128, 2), 256, PIPE_BYTES>>>(
            xr, wkv, bkv, kvb, rows, C_, C_, 128);
        dwconv_kernel<<<(rows * HD_ + 255) / 256, 256>>>(kvb, lcw, lcb, v2, s);
        attn_tc_kernel<<<dim3(N_ / 64, B_), 128, attn_smem>>>(q, kvb, v2, xcat, n, br);
    }

    gemm_tc_kernel<<<dim3((M + 127) / 128, 3), 256, PIPE_BYTES>>>(
        xcat, wo, bo, (float*)d_out, M, C_, C_, C_);
}

// round 9
// speedup vs baseline: 2.8876x; 1.2495x over previous
#include <cuda_runtime.h>
#include <cuda_fp16.h>
#include <math.h>
#include <stdint.h>

#define B_    8
#define N_    2304
#define C_    192
#define HW_   48
#define HD_   64
#define NMAX_ 2209   // 47*47

// ---------------- scratch ----------------
__device__ float  g_q[B_ * N_ * C_];
__device__ float  g_xr[B_ * NMAX_ * C_];
__device__ float  g_kv[B_ * NMAX_ * 128];
__device__ float  g_v2[B_ * NMAX_ * HD_];
__device__ __half g_xh[B_ * N_ * C_];        // x in fp16
__device__ __half g_xrh[B_ * NMAX_ * C_];    // ln_gelu output in fp16
__device__ __half g_xcath[B_ * N_ * C_];     // attention output in fp16
__device__ __half g_wth[C_ * C_ * 64];       // conv weights [kyx][co][ci] fp16
__device__ __half g_wqh[C_ * C_];            // [n][k] fp16
__device__ __half g_wkvh[C_ * C_];
__device__ __half g_woh[C_ * C_];

// ---------------- helpers ----------------
__device__ __forceinline__ uint32_t f2tf(float v) {
    uint32_t r;
    asm("cvt.rna.tf32.f32 %0, %1;" : "=r"(r) : "f"(v));
    return r;
}
__device__ __forceinline__ void mma_tf32(float* d, const uint32_t* a, const uint32_t* b) {
    asm volatile(
        "mma.sync.aligned.m16n8k8.row.col.f32.tf32.tf32.f32 "
        "{%0,%1,%2,%3}, {%4,%5,%6,%7}, {%8,%9}, {%0,%1,%2,%3};"
        : "+f"(d[0]), "+f"(d[1]), "+f"(d[2]), "+f"(d[3])
        : "r"(a[0]), "r"(a[1]), "r"(a[2]), "r"(a[3]), "r"(b[0]), "r"(b[1]));
}
__device__ __forceinline__ void mma_f16(float* d, const uint32_t* a, const uint32_t* b) {
    asm volatile(
        "mma.sync.aligned.m16n8k16.row.col.f32.f16.f16.f32 "
        "{%0,%1,%2,%3}, {%4,%5,%6,%7}, {%8,%9}, {%0,%1,%2,%3};"
        : "+f"(d[0]), "+f"(d[1]), "+f"(d[2]), "+f"(d[3])
        : "r"(a[0]), "r"(a[1]), "r"(a[2]), "r"(a[3]), "r"(b[0]), "r"(b[1]));
}
__device__ __forceinline__ void cp_async16(uint32_t dst, const void* src, uint32_t ssize) {
    asm volatile("cp.async.cg.shared.global [%0], [%1], 16, %2;"
                 :: "r"(dst), "l"(src), "r"(ssize) : "memory");
}
__device__ __forceinline__ void cp_commit() {
    asm volatile("cp.async.commit_group;" ::: "memory");
}
__device__ __forceinline__ void cp_wait1() {
    asm volatile("cp.async.wait_group 1;" ::: "memory");
}
__device__ __forceinline__ void cp_wait0() {
    asm volatile("cp.async.wait_group 0;" ::: "memory");
}

// fp16 GEMM tiles: BK=32 halves. A [128 rows][20 words] (16 data + 4 pad),
// W [64 n-rows][20 words]. Frag LDS bank = (20*lr + lc) % 32 -> bijective.
#define BK     32
#define TW     20              // words per tile row
#define A_ST   (128 * TW)      // words per A stage
#define W_ST   (64 * TW)
#define PIPE_BYTES (3 * (A_ST + W_ST) * 4)   // 46080

// =====================================================================================
// Conversions
// =====================================================================================
__global__ void cvt_x_kernel(const float* __restrict__ in, __half* __restrict__ out, int n)
{
    int i = blockIdx.x * blockDim.x + threadIdx.x;
    if (i < n) out[i] = __float2half_rn(in[i]);
}

// Transpose + convert the three dense weights: Wh[n][k] = (half)W[k][n]
__global__ void cvt_w_kernel(const float* __restrict__ Wq, const float* __restrict__ Wkv,
                             const float* __restrict__ Wo, __half* __restrict__ wq,
                             __half* __restrict__ wkv, __half* __restrict__ wo)
{
    int i = blockIdx.x * blockDim.x + threadIdx.x;
    int total = 3 * C_ * C_;
    if (i >= total) return;
    int which = i / (C_ * C_);
    int r = i - which * (C_ * C_);
    int nn = r / C_, k = r - nn * C_;
    const float* src = (which == 0) ? Wq : (which == 1) ? Wkv : Wo;
    __half* dst = (which == 0) ? wq : (which == 1) ? wkv : wo;
    dst[nn * C_ + k] = __float2half_rn(src[(size_t)k * C_ + nn]);
}

// conv weights: w[co][ci][ky][kx] -> wth[kyx][co][ci] fp16
__global__ void wtrans_kernel(const float* __restrict__ w, __half* __restrict__ wt, int ksz)
{
    int k2 = ksz * ksz;
    int total = C_ * C_ * k2;
    for (int idx = blockIdx.x * blockDim.x + threadIdx.x; idx < total;
         idx += gridDim.x * blockDim.x) {
        int ci = idx % C_;
        int rest = idx / C_;
        int co = rest % C_;
        int kyx = rest / C_;
        wt[idx] = __float2half_rn(w[((size_t)co * C_ + ci) * k2 + kyx]);
    }
}

// =====================================================================================
// FP16 TC GEMM, BK=32, cp.async 3-stage. A [M][K] half, W [N][K] half.
// Tiles 128x64. 256 thr = 8 warps (4m x 2n), warp tile 32x32. fp32 accum/out.
// =====================================================================================
__global__ __launch_bounds__(256) void gemm_tc_kernel(
    const __half* __restrict__ A, const __half* __restrict__ W,
    const float* __restrict__ bias, float* __restrict__ out,
    int M, int K, int ldc)
{
    extern __shared__ uint32_t sm[];
    uint32_t* As = sm;                 // [3][128][TW]
    uint32_t* Ws = sm + 3 * A_ST;      // [3][64][TW]

    const int tid = threadIdx.x;
    const int warp = tid >> 5, lane = tid & 31;
    const int wm = warp & 3, wn = warp >> 2;
    const int lr = lane >> 2, lc = lane & 3;
    const int m0 = blockIdx.x * 128;
    const int n0 = blockIdx.y * 64;

    const int r6 = tid >> 2;           // 0..63
    const int chk = tid & 3;           // 16B chunk index

    const __half* aPtr[2];
    uint32_t aSz[2];
#pragma unroll
    for (int i = 0; i < 2; i++) {
        int m = m0 + r6 + i * 64;
        aSz[i] = (m < M) ? 16u : 0u;
        aPtr[i] = A + (size_t)((m < M) ? m : 0) * K + chk * 8;
    }
    const __half* wPtr = W + (size_t)(n0 + r6) * K + chk * 8;

    const uint32_t asb = (uint32_t)__cvta_generic_to_shared(As);
    const uint32_t wsb = (uint32_t)__cvta_generic_to_shared(Ws);

    auto pf = [&](int kb, int st) {
        int k0 = kb * BK;
#pragma unroll
        for (int i = 0; i < 2; i++)
            cp_async16(asb + (uint32_t)(((st * 128 + r6 + i * 64) * TW + chk * 4) * 4),
                       aPtr[i] + k0, aSz[i]);
        cp_async16(wsb + (uint32_t)(((st * 64 + r6) * TW + chk * 4) * 4), wPtr + k0, 16u);
    };

    float acc[2][4][4];
#pragma unroll
    for (int mi = 0; mi < 2; mi++)
#pragma unroll
        for (int ni = 0; ni < 4; ni++)
#pragma unroll
            for (int j = 0; j < 4; j++) acc[mi][ni][j] = 0.f;

    const int KB = K / BK;
    pf(0, 0); cp_commit();
    pf(1, 1); cp_commit();

    int st = 0;
    for (int kb = 0; kb < KB; kb++) {
        if (kb + 1 < KB) cp_wait1(); else cp_wait0();
        __syncthreads();
        if (kb + 2 < KB) pf(kb + 2, (st + 2) % 3);
        cp_commit();
        const uint32_t* as = As + st * A_ST;
        const uint32_t* ws = Ws + st * W_ST;
#pragma unroll
        for (int ks = 0; ks < 2; ks++) {      // two k16 steps
            int ksw = ks * 8;
            uint32_t af[2][4];
#pragma unroll
            for (int mi = 0; mi < 2; mi++) {
                int rr = wm * 32 + mi * 16 + lr;
                af[mi][0] = as[rr * TW + ksw + lc];
                af[mi][1] = as[(rr + 8) * TW + ksw + lc];
                af[mi][2] = as[rr * TW + ksw + 4 + lc];
                af[mi][3] = as[(rr + 8) * TW + ksw + 4 + lc];
            }
            uint32_t bf[4][2];
#pragma unroll
            for (int ni = 0; ni < 4; ni++) {
                int cc = wn * 32 + ni * 8 + lr;
                bf[ni][0] = ws[cc * TW + ksw + lc];
                bf[ni][1] = ws[cc * TW + ksw + 4 + lc];
            }
#pragma unroll
            for (int mi = 0; mi < 2; mi++)
#pragma unroll
                for (int ni = 0; ni < 4; ni++) mma_f16(acc[mi][ni], af[mi], bf[ni]);
        }
        st = (st + 1) % 3;
    }
#pragma unroll
    for (int mi = 0; mi < 2; mi++) {
        int row = m0 + wm * 32 + mi * 16 + lr;
#pragma unroll
        for (int ni = 0; ni < 4; ni++) {
            int col = n0 + wn * 32 + ni * 8 + lc * 2;
            float b0 = bias[col], b1 = bias[col + 1];
            if (row < M) {
                out[(size_t)row * ldc + col]     = acc[mi][ni][0] + b0;
                out[(size_t)row * ldc + col + 1] = acc[mi][ni][1] + b1;
            }
            if (row + 8 < M) {
                out[(size_t)(row + 8) * ldc + col]     = acc[mi][ni][2] + b0;
                out[(size_t)(row + 8) * ldc + col + 1] = acc[mi][ni][3] + b1;
            }
        }
    }
}

// =====================================================================================
// SR conv as implicit GEMM, fp16 MMA, BK=32, cp.async 3-stage. KB = ksz*ksz*6.
// =====================================================================================
__global__ __launch_bounds__(256) void conv_tc_kernel(
    const __half* __restrict__ x, const __half* __restrict__ wt,
    const float* __restrict__ bias, float* __restrict__ out,
    int s_, int ksz)
{
    extern __shared__ uint32_t sm[];
    uint32_t* As = sm;
    uint32_t* Ws = sm + 3 * A_ST;

    const int tid = threadIdx.x;
    const int warp = tid >> 5, lane = tid & 31;
    const int wm = warp & 3, wn = warp >> 2;
    const int lr = lane >> 2, lc = lane & 3;
    const int b = blockIdx.z;
    const int n = s_ * s_;
    const int m0 = blockIdx.x * 128;
    const int n0 = blockIdx.y * 64;

    const int r6 = tid >> 2;
    const int chk = tid & 3;

    int rowoff[2];
    uint32_t aSz[2];
#pragma unroll
    for (int i = 0; i < 2; i++) {
        int p = m0 + r6 + i * 64;
        aSz[i] = (p < n) ? 16u : 0u;
        int pp = (p < n) ? p : 0;
        rowoff[i] = ((pp / s_) * HW_ + (pp % s_)) * C_;
    }
    const __half* xb = x + (size_t)b * N_ * C_;

    const uint32_t asb = (uint32_t)__cvta_generic_to_shared(As);
    const uint32_t wsb = (uint32_t)__cvta_generic_to_shared(Ws);

    auto pf = [&](int kb, int st) {
        int kyx = kb / 6;
        int ci0 = (kb - kyx * 6) * BK;
        int ky = kyx / ksz, kx = kyx - ky * ksz;
        int koff = (ky * HW_ + kx) * C_ + ci0 + chk * 8;
#pragma unroll
        for (int i = 0; i < 2; i++)
            cp_async16(asb + (uint32_t)(((st * 128 + r6 + i * 64) * TW + chk * 4) * 4),
                       xb + rowoff[i] + koff, aSz[i]);
        cp_async16(wsb + (uint32_t)(((st * 64 + r6) * TW + chk * 4) * 4),
                   wt + (size_t)kyx * C_ * C_ + (size_t)(n0 + r6) * C_ + ci0 + chk * 8, 16u);
    };

    float acc[2][4][4];
#pragma unroll
    for (int mi = 0; mi < 2; mi++)
#pragma unroll
        for (int ni = 0; ni < 4; ni++)
#pragma unroll
            for (int j = 0; j < 4; j++) acc[mi][ni][j] = 0.f;

    const int KB = ksz * ksz * 6;
    pf(0, 0); cp_commit();
    pf(1, 1); cp_commit();

    int st = 0;
    for (int kb = 0; kb < KB; kb++) {
        if (kb + 1 < KB) cp_wait1(); else cp_wait0();
        __syncthreads();
        if (kb + 2 < KB) pf(kb + 2, (st + 2) % 3);
        cp_commit();
        const uint32_t* as = As + st * A_ST;
        const uint32_t* ws = Ws + st * W_ST;
#pragma unroll
        for (int ks = 0; ks < 2; ks++) {
            int ksw = ks * 8;
            uint32_t af[2][4];
#pragma unroll
            for (int mi = 0; mi < 2; mi++) {
                int rr = wm * 32 + mi * 16 + lr;
                af[mi][0] = as[rr * TW + ksw + lc];
                af[mi][1] = as[(rr + 8) * TW + ksw + lc];
                af[mi][2] = as[rr * TW + ksw + 4 + lc];
                af[mi][3] = as[(rr + 8) * TW + ksw + 4 + lc];
            }
            uint32_t bf[4][2];
#pragma unroll
            for (int ni = 0; ni < 4; ni++) {
                int cc = wn * 32 + ni * 8 + lr;
                bf[ni][0] = ws[cc * TW + ksw + lc];
                bf[ni][1] = ws[cc * TW + ksw + 4 + lc];
            }
#pragma unroll
            for (int mi = 0; mi < 2; mi++)
#pragma unroll
                for (int ni = 0; ni < 4; ni++) mma_f16(acc[mi][ni], af[mi], bf[ni]);
        }
        st = (st + 1) % 3;
    }
#pragma unroll
    for (int mi = 0; mi < 2; mi++) {
        int row = m0 + wm * 32 + mi * 16 + lr;
#pragma unroll
        for (int ni = 0; ni < 4; ni++) {
            int col = n0 + wn * 32 + ni * 8 + lc * 2;
            float b0 = bias[col], b1 = bias[col + 1];
            if (row < n) {
                float* o = out + ((size_t)b * n + row) * C_ + col;
                o[0] = acc[mi][ni][0] + b0;
                o[1] = acc[mi][ni][1] + b1;
            }
            if (row + 8 < n) {
                float* o = out + ((size_t)b * n + row + 8) * C_ + col;
                o[0] = acc[mi][ni][2] + b0;
                o[1] = acc[mi][ni][3] + b1;
            }
        }
    }
}

// =====================================================================================
// Fused LayerNorm + exact GELU; reads fp32 xr, writes fp16. One warp per row.
// =====================================================================================
__global__ void ln_gelu_kernel(const float* __restrict__ xr, __half* __restrict__ xrh,
                               const float* __restrict__ g, const float* __restrict__ bb,
                               int rows)
{
    int wid = (blockIdx.x * blockDim.x + threadIdx.x) >> 5;
    int lane = threadIdx.x & 31;
    if (wid >= rows) return;
    const float* row = xr + (size_t)wid * C_;
    __half* orow = xrh + (size_t)wid * C_;
    float s1 = 0.f, s2 = 0.f;
#pragma unroll
    for (int j = lane; j < C_; j += 32) {
        float v = row[j];
        s1 += v;
        s2 += v * v;
    }
#pragma unroll
    for (int o = 16; o; o >>= 1) {
        s1 += __shfl_xor_sync(0xffffffffu, s1, o);
        s2 += __shfl_xor_sync(0xffffffffu, s2, o);
    }
    float mu = s1 * (1.f / C_);
    float var = s2 * (1.f / C_) - mu * mu;
    float inv = rsqrtf(var + 1e-5f);
#pragma unroll
    for (int j = lane; j < C_; j += 32) {
        float v = (row[j] - mu) * inv * g[j] + bb[j];
        orow[j] = __float2half_rn(0.5f * v * (1.f + erff(v * 0.70710678118654752440f)));
    }
}

// =====================================================================================
// Depthwise 3x3 (pad 1) on V + residual (fp32)
// =====================================================================================
__global__ void dwconv_kernel(const float* __restrict__ kv, const float* __restrict__ w,
                              const float* __restrict__ bias, float* __restrict__ v2, int s)
{
    int n = s * s;
    int total = B_ * n * HD_;
    int idx = blockIdx.x * blockDim.x + threadIdx.x;
    if (idx >= total) return;
    int hd = idx & 63;
    int p = (idx >> 6) % n;
    int b = idx / (n * 64);
    int y = p / s;
    int x0 = p - y * s;
    const float* vb = kv + (size_t)b * n * 128 + 64 + hd;
    float acc = bias[hd];
#pragma unroll
    for (int dy = -1; dy <= 1; dy++) {
#pragma unroll
        for (int dx = -1; dx <= 1; dx++) {
            int yy = y + dy, xx = x0 + dx;
            if (yy >= 0 && yy < s && xx >= 0 && xx < s)
                acc += w[hd * 9 + (dy + 1) * 3 + (dx + 1)] * vb[(size_t)(yy * s + xx) * 128];
        }
    }
    v2[idx] = acc + vb[(size_t)p * 128];
}

// =====================================================================================
// Tensor-core flash attention (tf32 MMA, fp32 softmax), dynamic smem (72 KB).
// Epilogue writes fp16 to xcath (feeds the fp16 O-projection GEMM).
// =====================================================================================
#define TLD 72
__global__ __launch_bounds__(128) void attn_tc_kernel(
    const float* __restrict__ q, const float* __restrict__ kv,
    const float* __restrict__ v2, __half* __restrict__ xcath,
    int nkv, int head)
{
    extern __shared__ uint32_t smbuf[];
    uint32_t (*qs)[TLD]  = (uint32_t (*)[TLD])smbuf;
    uint32_t (*kst)[TLD] = (uint32_t (*)[TLD])(smbuf + 64 * TLD);
    uint32_t (*vs)[TLD]  = (uint32_t (*)[TLD])(smbuf + 2 * 64 * TLD);
    uint32_t (*ps)[TLD]  = (uint32_t (*)[TLD])(smbuf + 3 * 64 * TLD);

    const int tid = threadIdx.x;
    const int warp = tid >> 5, lane = tid & 31;
    const int wm = warp;
    const int lr = lane >> 2, lc = lane & 3;
    const int b = blockIdx.y;
    const int q0 = blockIdx.x * 64;
    const int rr = wm * 16 + lr;
    const float scale = 0.07216878364870322056f;  // 1/sqrt(192)

#pragma unroll
    for (int i = 0; i < 32; i++) {
        int e = tid + i * 128;
        int r = e >> 6, d = e & 63;
        qs[d][r] = f2tf(q[((size_t)b * N_ + q0 + r) * C_ + head * HD_ + d]);
    }

    float m_i[2], l_i[2], oacc[8][4];
    m_i[0] = m_i[1] = -1e30f;
    l_i[0] = l_i[1] = 0.f;
#pragma unroll
    for (int ni = 0; ni < 8; ni++)
#pragma unroll
        for (int j = 0; j < 4; j++) oacc[ni][j] = 0.f;

    __syncthreads();

    const int nchunks = (nkv + 63) >> 6;
    for (int c0 = 0; c0 < nchunks; c0++) {
        int base = c0 * 64;
        int cs = nkv - base;
        if (cs > 64) cs = 64;
#pragma unroll
        for (int i = 0; i < 32; i++) {
            int e = tid + i * 128;
            int r = e >> 6, d = e & 63;
            if (r < cs) {
                size_t kidx = (size_t)b * nkv + base + r;
                kst[d][r] = f2tf(kv[kidx * 128 + d]);
                vs[r][d]  = f2tf(v2[kidx * 64 + d]);
            } else {
                kst[d][r] = 0u;
                vs[r][d]  = 0u;
            }
        }
        __syncthreads();

        float sacc[8][4];
#pragma unroll
        for (int ni = 0; ni < 8; ni++)
#pragma unroll
            for (int j = 0; j < 4; j++) sacc[ni][j] = 0.f;
#pragma unroll
        for (int kk = 0; kk < 64; kk += 8) {
            uint32_t af[4];
            af[0] = qs[kk + lc][rr];
            af[1] = qs[kk + lc][rr + 8];
            af[2] = qs[kk + 4 + lc][rr];
            af[3] = qs[kk + 4 + lc][rr + 8];
#pragma unroll
            for (int ni = 0; ni < 8; ni++) {
                uint32_t bf[2];
                int cc = ni * 8 + lr;
                bf[0] = kst[kk + lc][cc];
                bf[1] = kst[kk + 4 + lc][cc];
                mma_tf32(sacc[ni], af, bf);
            }
        }

#pragma unroll
        for (int h = 0; h < 2; h++) {
            float mx = -1e30f;
#pragma unroll
            for (int ni = 0; ni < 8; ni++)
#pragma unroll
                for (int j = 0; j < 2; j++) {
                    float v = sacc[ni][2 * h + j] * scale;
                    if (ni * 8 + 2 * lc + j >= cs) v = -1e30f;
                    sacc[ni][2 * h + j] = v;
                    mx = fmaxf(mx, v);
                }
            mx = fmaxf(mx, __shfl_xor_sync(0xffffffffu, mx, 1));
            mx = fmaxf(mx, __shfl_xor_sync(0xffffffffu, mx, 2));
            float mnew = fmaxf(m_i[h], mx);
            float alpha = __expf(m_i[h] - mnew);
            float rs = 0.f;
#pragma unroll
            for (int ni = 0; ni < 8; ni++)
#pragma unroll
                for (int j = 0; j < 2; j++) {
                    float p = __expf(sacc[ni][2 * h + j] - mnew);
                    sacc[ni][2 * h + j] = p;
                    rs += p;
                }
            rs += __shfl_xor_sync(0xffffffffu, rs, 1);
            rs += __shfl_xor_sync(0xffffffffu, rs, 2);
            l_i[h] = l_i[h] * alpha + rs;
            m_i[h] = mnew;
#pragma unroll
            for (int ni = 0; ni < 8; ni++) {
                oacc[ni][2 * h]     *= alpha;
                oacc[ni][2 * h + 1] *= alpha;
            }
        }

#pragma unroll
        for (int ni = 0; ni < 8; ni++) {
            int c = ni * 8 + 2 * lc;
            ps[c][rr]         = f2tf(sacc[ni][0]);
            ps[c + 1][rr]     = f2tf(sacc[ni][1]);
            ps[c][rr + 8]     = f2tf(sacc[ni][2]);
            ps[c + 1][rr + 8] = f2tf(sacc[ni][3]);
        }
        __syncwarp();

#pragma unroll
        for (int kk = 0; kk < 64; kk += 8) {
            uint32_t af[4];
            af[0] = ps[kk + lc][rr];
            af[1] = ps[kk + lc][rr + 8];
            af[2] = ps[kk + 4 + lc][rr];
            af[3] = ps[kk + 4 + lc][rr + 8];
#pragma unroll
            for (int ni = 0; ni < 8; ni++) {
                uint32_t bf[2];
                int cc = ni * 8 + lr;
                bf[0] = vs[kk + lc][cc];
                bf[1] = vs[kk + 4 + lc][cc];
                mma_tf32(oacc[ni], af, bf);
            }
        }
        __syncthreads();
    }

    float inv0 = 1.f / l_i[0], inv1 = 1.f / l_i[1];
#pragma unroll
    for (int ni = 0; ni < 8; ni++) {
        int col = head * HD_ + ni * 8 + 2 * lc;
        size_t r0 = (size_t)b * N_ + q0 + rr;
        *(__half2*)(xcath + r0 * C_ + col) =
            __floats2half2_rn(oacc[ni][0] * inv0, oacc[ni][1] * inv0);
        *(__half2*)(xcath + (r0 + 8) * C_ + col) =
            __floats2half2_rn(oacc[ni][2] * inv1, oacc[ni][3] * inv1);
    }
}

// =====================================================================================
// Host orchestration. Launch order puts conv(b1) at 0-indexed launch 3 (the slot
// ncu empirically profiles) so the next round sees the dominant kernel.
// =====================================================================================
extern "C" void kernel_launch(void* const* d_in, const int* in_sizes, int n_in,
                              void* d_out, int out_size)
{
    const float* x   = (const float*)d_in[0];
    const float* Wq  = (const float*)d_in[1];
    const float* bq  = (const float*)d_in[2];
    const float* Wkv = (const float*)d_in[3];
    const float* bkv = (const float*)d_in[4];
    const float* Wo  = (const float*)d_in[23];
    const float* bo  = (const float*)d_in[24];

    float *q, *xr, *kvb, *v2;
    __half *xh, *xrh, *xcath, *wth, *wqh, *wkvh, *woh;
    cudaGetSymbolAddress((void**)&q, g_q);
    cudaGetSymbolAddress((void**)&xr, g_xr);
    cudaGetSymbolAddress((void**)&kvb, g_kv);
    cudaGetSymbolAddress((void**)&v2, g_v2);
    cudaGetSymbolAddress((void**)&xh, g_xh);
    cudaGetSymbolAddress((void**)&xrh, g_xrh);
    cudaGetSymbolAddress((void**)&xcath, g_xcath);
    cudaGetSymbolAddress((void**)&wth, g_wth);
    cudaGetSymbolAddress((void**)&wqh, g_wqh);
    cudaGetSymbolAddress((void**)&wkvh, g_wkvh);
    cudaGetSymbolAddress((void**)&woh, g_woh);

    const int attn_smem = 4 * 64 * TLD * (int)sizeof(uint32_t);  // 73728
    cudaFuncSetAttribute(attn_tc_kernel, cudaFuncAttributeMaxDynamicSharedMemorySize,
                         attn_smem);
    cudaFuncSetAttribute(gemm_tc_kernel, cudaFuncAttributeMaxDynamicSharedMemorySize,
                         PIPE_BYTES);
    cudaFuncSetAttribute(conv_tc_kernel, cudaFuncAttributeMaxDynamicSharedMemorySize,
                         PIPE_BYTES);

    const int M = B_ * N_;
    const int NX = B_ * N_ * C_;
    const int ks_arr[3] = {8, 4, 2};

    // launch 0: x -> fp16
    cvt_x_kernel<<<(NX + 255) / 256, 256>>>(x, xh, NX);
    // launch 1: dense weights -> transposed fp16
    cvt_w_kernel<<<(3 * C_ * C_ + 255) / 256, 256>>>(Wq, Wkv, Wo, wqh, wkvh, woh);
    // launch 2: conv weights branch 1
    wtrans_kernel<<<256, 256>>>((const float*)d_in[5], wth, 8);
    {
        // launch 3 (PROFILED): conv branch 1
        int s = HW_ - 8 + 1, n = s * s;
        conv_tc_kernel<<<dim3((n + 127) / 128, 3, B_), 256, PIPE_BYTES>>>(
            xh, wth, (const float*)d_in[6], xr, s, 8);
    }
    // launch 4: Q projection
    gemm_tc_kernel<<<dim3((M + 127) / 128, 3), 256, PIPE_BYTES>>>(
        xh, wqh, bq, q, M, C_, C_);

    for (int br = 0; br < 3; br++) {
        const float* srw = (const float*)d_in[5 + br * 6 + 0];
        const float* srb = (const float*)d_in[5 + br * 6 + 1];
        const float* lng = (const float*)d_in[5 + br * 6 + 2];
        const float* lnb = (const float*)d_in[5 + br * 6 + 3];
        const float* lcw = (const float*)d_in[5 + br * 6 + 4];
        const float* lcb = (const float*)d_in[5 + br * 6 + 5];
        int ksz = ks_arr[br];
        int s = HW_ - ksz + 1;
        int n = s * s;
        int rows = B_ * n;

        if (br > 0) {
            wtrans_kernel<<<256, 256>>>(srw, wth, ksz);
            conv_tc_kernel<<<dim3((n + 127) / 128, 3, B_), 256, PIPE_BYTES>>>(
                xh, wth, srb, xr, s, ksz);
        }
        ln_gelu_kernel<<<(rows + 7) / 8, 256>>>(xr, xrh, lng, lnb, rows);
        gemm_tc_kernel<<<dim3((rows + 127) / 128, 2), 256, PIPE_BYTES>>>(
            xrh, wkvh, bkv, kvb, rows, C_, 128);
        dwconv_kernel<<<(rows * HD_ + 255) / 256, 256>>>(kvb, lcw, lcb, v2, s);
        attn_tc_kernel<<<dim3(N_ / 64, B_), 128, attn_smem>>>(q, kvb, v2, xcath, n, br);
    }

    gemm_tc_kernel<<<dim3((M + 127) / 128, 3), 256, PIPE_BYTES>>>(
        xcath, woh, bo, (float*)d_out, M, C_, C_);
}

// round 10
// speedup vs baseline: 2.9754x; 1.0304x over previous
#include <cuda_runtime.h>
#include <cuda_fp16.h>
#include <math.h>
#include <stdint.h>

#define B_    8
#define N_    2304
#define C_    192
#define HW_   48
#define HD_   64
#define NMAX_ 2209   // 47*47

// ---------------- scratch ----------------
__device__ float  g_q[B_ * N_ * C_];
__device__ float  g_xr[B_ * NMAX_ * C_];
__device__ float  g_kv[B_ * NMAX_ * 128];
__device__ float  g_v2[B_ * NMAX_ * HD_];
__device__ __half g_xh[B_ * N_ * C_];
__device__ __half g_xrh[B_ * NMAX_ * C_];
__device__ __half g_xcath[B_ * N_ * C_];
__device__ __half g_wth[C_ * C_ * 64];       // [kyx][co][ci] fp16
__device__ __half g_wqh[C_ * C_];            // [n][k] fp16
__device__ __half g_wkvh[C_ * C_];
__device__ __half g_woh[C_ * C_];

// ---------------- helpers ----------------
__device__ __forceinline__ uint32_t f2tf(float v) {
    uint32_t r;
    asm("cvt.rna.tf32.f32 %0, %1;" : "=r"(r) : "f"(v));
    return r;
}
__device__ __forceinline__ void mma_tf32(float* d, const uint32_t* a, const uint32_t* b) {
    asm volatile(
        "mma.sync.aligned.m16n8k8.row.col.f32.tf32.tf32.f32 "
        "{%0,%1,%2,%3}, {%4,%5,%6,%7}, {%8,%9}, {%0,%1,%2,%3};"
        : "+f"(d[0]), "+f"(d[1]), "+f"(d[2]), "+f"(d[3])
        : "r"(a[0]), "r"(a[1]), "r"(a[2]), "r"(a[3]), "r"(b[0]), "r"(b[1]));
}
__device__ __forceinline__ void mma_f16(float* d, const uint32_t* a, const uint32_t* b) {
    asm volatile(
        "mma.sync.aligned.m16n8k16.row.col.f32.f16.f16.f32 "
        "{%0,%1,%2,%3}, {%4,%5,%6,%7}, {%8,%9}, {%0,%1,%2,%3};"
        : "+f"(d[0]), "+f"(d[1]), "+f"(d[2]), "+f"(d[3])
        : "r"(a[0]), "r"(a[1]), "r"(a[2]), "r"(a[3]), "r"(b[0]), "r"(b[1]));
}
__device__ __forceinline__ void cp_async16(uint32_t dst, const void* src, uint32_t ssize) {
    asm volatile("cp.async.cg.shared.global [%0], [%1], 16, %2;"
                 :: "r"(dst), "l"(src), "r"(ssize) : "memory");
}
__device__ __forceinline__ void cp_commit() {
    asm volatile("cp.async.commit_group;" ::: "memory");
}
__device__ __forceinline__ void cp_wait1() {
    asm volatile("cp.async.wait_group 1;" ::: "memory");
}
__device__ __forceinline__ void cp_wait0() {
    asm volatile("cp.async.wait_group 0;" ::: "memory");
}

#define BK     32
#define TW     20              // words per tile row (16 data + 4 pad)
// gemm tiles (unchanged from R9)
#define A_ST   (128 * TW)
#define W_ST   (64 * TW)
#define PIPE_BYTES (3 * (A_ST + W_ST) * 4)    // 46080
// conv tiles: block 256x64, 4 warps of 64x64
#define CA_ST  (256 * TW)
#define CW_ST  (64 * TW)
#define CPIPE_BYTES (3 * (CA_ST + CW_ST) * 4) // 76800

// =====================================================================================
// Conversions
// =====================================================================================
__global__ void cvt_x_kernel(const float* __restrict__ in, __half* __restrict__ out, int n)
{
    int i = blockIdx.x * blockDim.x + threadIdx.x;
    if (i < n) out[i] = __float2half_rn(in[i]);
}

__global__ void cvt_w_kernel(const float* __restrict__ Wq, const float* __restrict__ Wkv,
                             const float* __restrict__ Wo, __half* __restrict__ wq,
                             __half* __restrict__ wkv, __half* __restrict__ wo)
{
    int i = blockIdx.x * blockDim.x + threadIdx.x;
    int total = 3 * C_ * C_;
    if (i >= total) return;
    int which = i / (C_ * C_);
    int r = i - which * (C_ * C_);
    int nn = r / C_, k = r - nn * C_;
    const float* src = (which == 0) ? Wq : (which == 1) ? Wkv : Wo;
    __half* dst = (which == 0) ? wq : (which == 1) ? wkv : wo;
    dst[nn * C_ + k] = __float2half_rn(src[(size_t)k * C_ + nn]);
}

__global__ void wtrans_kernel(const float* __restrict__ w, __half* __restrict__ wt, int ksz)
{
    int k2 = ksz * ksz;
    int total = C_ * C_ * k2;
    for (int idx = blockIdx.x * blockDim.x + threadIdx.x; idx < total;
         idx += gridDim.x * blockDim.x) {
        int ci = idx % C_;
        int rest = idx / C_;
        int co = rest % C_;
        int kyx = rest / C_;
        wt[idx] = __float2half_rn(w[((size_t)co * C_ + ci) * k2 + kyx]);
    }
}

// =====================================================================================
// FP16 TC GEMM (unchanged from R9): tiles 128x64, 8 warps 32x32.
// =====================================================================================
__global__ __launch_bounds__(256) void gemm_tc_kernel(
    const __half* __restrict__ A, const __half* __restrict__ W,
    const float* __restrict__ bias, float* __restrict__ out,
    int M, int K, int ldc)
{
    extern __shared__ uint32_t sm[];
    uint32_t* As = sm;
    uint32_t* Ws = sm + 3 * A_ST;

    const int tid = threadIdx.x;
    const int warp = tid >> 5, lane = tid & 31;
    const int wm = warp & 3, wn = warp >> 2;
    const int lr = lane >> 2, lc = lane & 3;
    const int m0 = blockIdx.x * 128;
    const int n0 = blockIdx.y * 64;

    const int r6 = tid >> 2;
    const int chk = tid & 3;

    const __half* aPtr[2];
    uint32_t aSz[2];
#pragma unroll
    for (int i = 0; i < 2; i++) {
        int m = m0 + r6 + i * 64;
        aSz[i] = (m < M) ? 16u : 0u;
        aPtr[i] = A + (size_t)((m < M) ? m : 0) * K + chk * 8;
    }
    const __half* wPtr = W + (size_t)(n0 + r6) * K + chk * 8;

    const uint32_t asb = (uint32_t)__cvta_generic_to_shared(As);
    const uint32_t wsb = (uint32_t)__cvta_generic_to_shared(Ws);

    auto pf = [&](int kb, int st) {
        int k0 = kb * BK;
#pragma unroll
        for (int i = 0; i < 2; i++)
            cp_async16(asb + (uint32_t)(((st * 128 + r6 + i * 64) * TW + chk * 4) * 4),
                       aPtr[i] + k0, aSz[i]);
        cp_async16(wsb + (uint32_t)(((st * 64 + r6) * TW + chk * 4) * 4), wPtr + k0, 16u);
    };

    float acc[2][4][4];
#pragma unroll
    for (int mi = 0; mi < 2; mi++)
#pragma unroll
        for (int ni = 0; ni < 4; ni++)
#pragma unroll
            for (int j = 0; j < 4; j++) acc[mi][ni][j] = 0.f;

    const int KB = K / BK;
    pf(0, 0); cp_commit();
    pf(1, 1); cp_commit();

    int st = 0;
    for (int kb = 0; kb < KB; kb++) {
        if (kb + 1 < KB) cp_wait1(); else cp_wait0();
        __syncthreads();
        if (kb + 2 < KB) pf(kb + 2, (st + 2) % 3);
        cp_commit();
        const uint32_t* as = As + st * A_ST;
        const uint32_t* ws = Ws + st * W_ST;
#pragma unroll
        for (int ks = 0; ks < 2; ks++) {
            int ksw = ks * 8;
            uint32_t af[2][4];
#pragma unroll
            for (int mi = 0; mi < 2; mi++) {
                int rr = wm * 32 + mi * 16 + lr;
                af[mi][0] = as[rr * TW + ksw + lc];
                af[mi][1] = as[(rr + 8) * TW + ksw + lc];
                af[mi][2] = as[rr * TW + ksw + 4 + lc];
                af[mi][3] = as[(rr + 8) * TW + ksw + 4 + lc];
            }
            uint32_t bf[4][2];
#pragma unroll
            for (int ni = 0; ni < 4; ni++) {
                int cc = wn * 32 + ni * 8 + lr;
                bf[ni][0] = ws[cc * TW + ksw + lc];
                bf[ni][1] = ws[cc * TW + ksw + 4 + lc];
            }
#pragma unroll
            for (int mi = 0; mi < 2; mi++)
#pragma unroll
                for (int ni = 0; ni < 4; ni++) mma_f16(acc[mi][ni], af[mi], bf[ni]);
        }
        st = (st + 1) % 3;
    }
#pragma unroll
    for (int mi = 0; mi < 2; mi++) {
        int row = m0 + wm * 32 + mi * 16 + lr;
#pragma unroll
        for (int ni = 0; ni < 4; ni++) {
            int col = n0 + wn * 32 + ni * 8 + lc * 2;
            float b0 = bias[col], b1 = bias[col + 1];
            if (row < M) {
                out[(size_t)row * ldc + col]     = acc[mi][ni][0] + b0;
                out[(size_t)row * ldc + col + 1] = acc[mi][ni][1] + b1;
            }
            if (row + 8 < M) {
                out[(size_t)(row + 8) * ldc + col]     = acc[mi][ni][2] + b0;
                out[(size_t)(row + 8) * ldc + col + 1] = acc[mi][ni][3] + b1;
            }
        }
    }
}

// =====================================================================================
// SR conv implicit GEMM v2: block 256x64, 128 thr = 4 warps, warp tile 64x64.
// Halves smem traffic per MAC (0.0625 B/MAC) and LDS:MMA ratio (1:1).
// =====================================================================================
__global__ __launch_bounds__(128) void conv_tc_kernel(
    const __half* __restrict__ x, const __half* __restrict__ wt,
    const float* __restrict__ bias, float* __restrict__ out,
    int s_, int ksz)
{
    extern __shared__ uint32_t sm[];
    uint32_t* As = sm;                  // [3][256][TW]
    uint32_t* Ws = sm + 3 * CA_ST;      // [3][64][TW]

    const int tid = threadIdx.x;
    const int warp = tid >> 5, lane = tid & 31;
    const int wm = warp;                // 4 warps stacked on M
    const int lr = lane >> 2, lc = lane & 3;
    const int b = blockIdx.z;
    const int n = s_ * s_;
    const int m0 = blockIdx.x * 256;
    const int n0 = blockIdx.y * 64;

    const int prow = tid >> 2;          // 0..31
    const int chk = tid & 3;

    // A rows prow + i*32 (i=0..7); B rows prow + i*32 (i=0..1)
    int rowoff[8];
    uint32_t aSz[8];
#pragma unroll
    for (int i = 0; i < 8; i++) {
        int p = m0 + prow + i * 32;
        aSz[i] = (p < n) ? 16u : 0u;
        int pp = (p < n) ? p : 0;
        rowoff[i] = ((pp / s_) * HW_ + (pp % s_)) * C_;
    }
    const __half* xb = x + (size_t)b * N_ * C_;

    const uint32_t asb = (uint32_t)__cvta_generic_to_shared(As);
    const uint32_t wsb = (uint32_t)__cvta_generic_to_shared(Ws);

    auto pf = [&](int kb, int st) {
        int kyx = kb / 6;
        int ci0 = (kb - kyx * 6) * BK;
        int ky = kyx / ksz, kx = kyx - ky * ksz;
        int koff = (ky * HW_ + kx) * C_ + ci0 + chk * 8;
#pragma unroll
        for (int i = 0; i < 8; i++)
            cp_async16(asb + (uint32_t)(((st * 256 + prow + i * 32) * TW + chk * 4) * 4),
                       xb + rowoff[i] + koff, aSz[i]);
        const __half* wp = wt + (size_t)kyx * C_ * C_ + ci0 + chk * 8;
#pragma unroll
        for (int i = 0; i < 2; i++)
            cp_async16(wsb + (uint32_t)(((st * 64 + prow + i * 32) * TW + chk * 4) * 4),
                       wp + (size_t)(n0 + prow + i * 32) * C_, 16u);
    };

    float acc[4][8][4];
#pragma unroll
    for (int mi = 0; mi < 4; mi++)
#pragma unroll
        for (int ni = 0; ni < 8; ni++)
#pragma unroll
            for (int j = 0; j < 4; j++) acc[mi][ni][j] = 0.f;

    const int KB = ksz * ksz * 6;
    pf(0, 0); cp_commit();
    pf(1, 1); cp_commit();

    int st = 0;
    for (int kb = 0; kb < KB; kb++) {
        if (kb + 1 < KB) cp_wait1(); else cp_wait0();
        __syncthreads();
        if (kb + 2 < KB) pf(kb + 2, (st + 2) % 3);
        cp_commit();
        const uint32_t* as = As + st * CA_ST;
        const uint32_t* ws = Ws + st * CW_ST;
#pragma unroll
        for (int ks = 0; ks < 2; ks++) {
            int ksw = ks * 8;
            uint32_t af[4][4];
#pragma unroll
            for (int mi = 0; mi < 4; mi++) {
                int rr = wm * 64 + mi * 16 + lr;
                af[mi][0] = as[rr * TW + ksw + lc];
                af[mi][1] = as[(rr + 8) * TW + ksw + lc];
                af[mi][2] = as[rr * TW + ksw + 4 + lc];
                af[mi][3] = as[(rr + 8) * TW + ksw + 4 + lc];
            }
            uint32_t bf[8][2];
#pragma unroll
            for (int ni = 0; ni < 8; ni++) {
                int cc = ni * 8 + lr;
                bf[ni][0] = ws[cc * TW + ksw + lc];
                bf[ni][1] = ws[cc * TW + ksw + 4 + lc];
            }
#pragma unroll
            for (int mi = 0; mi < 4; mi++)
#pragma unroll
                for (int ni = 0; ni < 8; ni++) mma_f16(acc[mi][ni], af[mi], bf[ni]);
        }
        st = (st + 1) % 3;
    }
#pragma unroll
    for (int mi = 0; mi < 4; mi++) {
        int row = m0 + wm * 64 + mi * 16 + lr;
#pragma unroll
        for (int ni = 0; ni < 8; ni++) {
            int col = n0 + ni * 8 + lc * 2;
            float b0 = bias[col], b1 = bias[col + 1];
            if (row < n) {
                float* o = out + ((size_t)b * n + row) * C_ + col;
                o[0] = acc[mi][ni][0] + b0;
                o[1] = acc[mi][ni][1] + b1;
            }
            if (row + 8 < n) {
                float* o = out + ((size_t)b * n + row + 8) * C_ + col;
                o[0] = acc[mi][ni][2] + b0;
                o[1] = acc[mi][ni][3] + b1;
            }
        }
    }
}

// =====================================================================================
// Fused LayerNorm + exact GELU; reads fp32 xr, writes fp16. One warp per row.
// =====================================================================================
__global__ void ln_gelu_kernel(const float* __restrict__ xr, __half* __restrict__ xrh,
                               const float* __restrict__ g, const float* __restrict__ bb,
                               int rows)
{
    int wid = (blockIdx.x * blockDim.x + threadIdx.x) >> 5;
    int lane = threadIdx.x & 31;
    if (wid >= rows) return;
    const float* row = xr + (size_t)wid * C_;
    __half* orow = xrh + (size_t)wid * C_;
    float s1 = 0.f, s2 = 0.f;
#pragma unroll
    for (int j = lane; j < C_; j += 32) {
        float v = row[j];
        s1 += v;
        s2 += v * v;
    }
#pragma unroll
    for (int o = 16; o; o >>= 1) {
        s1 += __shfl_xor_sync(0xffffffffu, s1, o);
        s2 += __shfl_xor_sync(0xffffffffu, s2, o);
    }
    float mu = s1 * (1.f / C_);
    float var = s2 * (1.f / C_) - mu * mu;
    float inv = rsqrtf(var + 1e-5f);
#pragma unroll
    for (int j = lane; j < C_; j += 32) {
        float v = (row[j] - mu) * inv * g[j] + bb[j];
        orow[j] = __float2half_rn(0.5f * v * (1.f + erff(v * 0.70710678118654752440f)));
    }
}

// =====================================================================================
// Depthwise 3x3 (pad 1) on V + residual (fp32)
// =====================================================================================
__global__ void dwconv_kernel(const float* __restrict__ kv, const float* __restrict__ w,
                              const float* __restrict__ bias, float* __restrict__ v2, int s)
{
    int n = s * s;
    int total = B_ * n * HD_;
    int idx = blockIdx.x * blockDim.x + threadIdx.x;
    if (idx >= total) return;
    int hd = idx & 63;
    int p = (idx >> 6) % n;
    int b = idx / (n * 64);
    int y = p / s;
    int x0 = p - y * s;
    const float* vb = kv + (size_t)b * n * 128 + 64 + hd;
    float acc = bias[hd];
#pragma unroll
    for (int dy = -1; dy <= 1; dy++) {
#pragma unroll
        for (int dx = -1; dx <= 1; dx++) {
            int yy = y + dy, xx = x0 + dx;
            if (yy >= 0 && yy < s && xx >= 0 && xx < s)
                acc += w[hd * 9 + (dy + 1) * 3 + (dx + 1)] * vb[(size_t)(yy * s + xx) * 128];
        }
    }
    v2[idx] = acc + vb[(size_t)p * 128];
}

// =====================================================================================
// Tensor-core flash attention (tf32 MMA, fp32 softmax), dynamic smem (72 KB).
// =====================================================================================
#define TLD 72
__global__ __launch_bounds__(128) void attn_tc_kernel(
    const float* __restrict__ q, const float* __restrict__ kv,
    const float* __restrict__ v2, __half* __restrict__ xcath,
    int nkv, int head)
{
    extern __shared__ uint32_t smbuf[];
    uint32_t (*qs)[TLD]  = (uint32_t (*)[TLD])smbuf;
    uint32_t (*kst)[TLD] = (uint32_t (*)[TLD])(smbuf + 64 * TLD);
    uint32_t (*vs)[TLD]  = (uint32_t (*)[TLD])(smbuf + 2 * 64 * TLD);
    uint32_t (*ps)[TLD]  = (uint32_t (*)[TLD])(smbuf + 3 * 64 * TLD);

    const int tid = threadIdx.x;
    const int warp = tid >> 5, lane = tid & 31;
    const int wm = warp;
    const int lr = lane >> 2, lc = lane & 3;
    const int b = blockIdx.y;
    const int q0 = blockIdx.x * 64;
    const int rr = wm * 16 + lr;
    const float scale = 0.07216878364870322056f;

#pragma unroll
    for (int i = 0; i < 32; i++) {
        int e = tid + i * 128;
        int r = e >> 6, d = e & 63;
        qs[d][r] = f2tf(q[((size_t)b * N_ + q0 + r) * C_ + head * HD_ + d]);
    }

    float m_i[2], l_i[2], oacc[8][4];
    m_i[0] = m_i[1] = -1e30f;
    l_i[0] = l_i[1] = 0.f;
#pragma unroll
    for (int ni = 0; ni < 8; ni++)
#pragma unroll
        for (int j = 0; j < 4; j++) oacc[ni][j] = 0.f;

    __syncthreads();

    const int nchunks = (nkv + 63) >> 6;
    for (int c0 = 0; c0 < nchunks; c0++) {
        int base = c0 * 64;
        int cs = nkv - base;
        if (cs > 64) cs = 64;
#pragma unroll
        for (int i = 0; i < 32; i++) {
            int e = tid + i * 128;
            int r = e >> 6, d = e & 63;
            if (r < cs) {
                size_t kidx = (size_t)b * nkv + base + r;
                kst[d][r] = f2tf(kv[kidx * 128 + d]);
                vs[r][d]  = f2tf(v2[kidx * 64 + d]);
            } else {
                kst[d][r] = 0u;
                vs[r][d]  = 0u;
            }
        }
        __syncthreads();

        float sacc[8][4];
#pragma unroll
        for (int ni = 0; ni < 8; ni++)
#pragma unroll
            for (int j = 0; j < 4; j++) sacc[ni][j] = 0.f;
#pragma unroll
        for (int kk = 0; kk < 64; kk += 8) {
            uint32_t af[4];
            af[0] = qs[kk + lc][rr];
            af[1] = qs[kk + lc][rr + 8];
            af[2] = qs[kk + 4 + lc][rr];
            af[3] = qs[kk + 4 + lc][rr + 8];
#pragma unroll
            for (int ni = 0; ni < 8; ni++) {
                uint32_t bf[2];
                int cc = ni * 8 + lr;
                bf[0] = kst[kk + lc][cc];
                bf[1] = kst[kk + 4 + lc][cc];
                mma_tf32(sacc[ni], af, bf);
            }
        }

#pragma unroll
        for (int h = 0; h < 2; h++) {
            float mx = -1e30f;
#pragma unroll
            for (int ni = 0; ni < 8; ni++)
#pragma unroll
                for (int j = 0; j < 2; j++) {
                    float v = sacc[ni][2 * h + j] * scale;
                    if (ni * 8 + 2 * lc + j >= cs) v = -1e30f;
                    sacc[ni][2 * h + j] = v;
                    mx = fmaxf(mx, v);
                }
            mx = fmaxf(mx, __shfl_xor_sync(0xffffffffu, mx, 1));
            mx = fmaxf(mx, __shfl_xor_sync(0xffffffffu, mx, 2));
            float mnew = fmaxf(m_i[h], mx);
            float alpha = __expf(m_i[h] - mnew);
            float rs = 0.f;
#pragma unroll
            for (int ni = 0; ni < 8; ni++)
#pragma unroll
                for (int j = 0; j < 2; j++) {
                    float p = __expf(sacc[ni][2 * h + j] - mnew);
                    sacc[ni][2 * h + j] = p;
                    rs += p;
                }
            rs += __shfl_xor_sync(0xffffffffu, rs, 1);
            rs += __shfl_xor_sync(0xffffffffu, rs, 2);
            l_i[h] = l_i[h] * alpha + rs;
            m_i[h] = mnew;
#pragma unroll
            for (int ni = 0; ni < 8; ni++) {
                oacc[ni][2 * h]     *= alpha;
                oacc[ni][2 * h + 1] *= alpha;
            }
        }

#pragma unroll
        for (int ni = 0; ni < 8; ni++) {
            int c = ni * 8 + 2 * lc;
            ps[c][rr]         = f2tf(sacc[ni][0]);
            ps[c + 1][rr]     = f2tf(sacc[ni][1]);
            ps[c][rr + 8]     = f2tf(sacc[ni][2]);
            ps[c + 1][rr + 8] = f2tf(sacc[ni][3]);
        }
        __syncwarp();

#pragma unroll
        for (int kk = 0; kk < 64; kk += 8) {
            uint32_t af[4];
            af[0] = ps[kk + lc][rr];
            af[1] = ps[kk + lc][rr + 8];
            af[2] = ps[kk + 4 + lc][rr];
            af[3] = ps[kk + 4 + lc][rr + 8];
#pragma unroll
            for (int ni = 0; ni < 8; ni++) {
                uint32_t bf[2];
                int cc = ni * 8 + lr;
                bf[0] = vs[kk + lc][cc];
                bf[1] = vs[kk + 4 + lc][cc];
                mma_tf32(oacc[ni], af, bf);
            }
        }
        __syncthreads();
    }

    float inv0 = 1.f / l_i[0], inv1 = 1.f / l_i[1];
#pragma unroll
    for (int ni = 0; ni < 8; ni++) {
        int col = head * HD_ + ni * 8 + 2 * lc;
        size_t r0 = (size_t)b * N_ + q0 + rr;
        *(__half2*)(xcath + r0 * C_ + col) =
            __floats2half2_rn(oacc[ni][0] * inv0, oacc[ni][1] * inv0);
        *(__half2*)(xcath + (r0 + 8) * C_ + col) =
            __floats2half2_rn(oacc[ni][2] * inv1, oacc[ni][3] * inv1);
    }
}

// =====================================================================================
// Host orchestration (conv b1 kept at profiled launch index 3)
// =====================================================================================
extern "C" void kernel_launch(void* const* d_in, const int* in_sizes, int n_in,
                              void* d_out, int out_size)
{
    const float* x   = (const float*)d_in[0];
    const float* Wq  = (const float*)d_in[1];
    const float* bq  = (const float*)d_in[2];
    const float* Wkv = (const float*)d_in[3];
    const float* bkv = (const float*)d_in[4];
    const float* Wo  = (const float*)d_in[23];
    const float* bo  = (const float*)d_in[24];

    float *q, *xr, *kvb, *v2;
    __half *xh, *xrh, *xcath, *wth, *wqh, *wkvh, *woh;
    cudaGetSymbolAddress((void**)&q, g_q);
    cudaGetSymbolAddress((void**)&xr, g_xr);
    cudaGetSymbolAddress((void**)&kvb, g_kv);
    cudaGetSymbolAddress((void**)&v2, g_v2);
    cudaGetSymbolAddress((void**)&xh, g_xh);
    cudaGetSymbolAddress((void**)&xrh, g_xrh);
    cudaGetSymbolAddress((void**)&xcath, g_xcath);
    cudaGetSymbolAddress((void**)&wth, g_wth);
    cudaGetSymbolAddress((void**)&wqh, g_wqh);
    cudaGetSymbolAddress((void**)&wkvh, g_wkvh);
    cudaGetSymbolAddress((void**)&woh, g_woh);

    const int attn_smem = 4 * 64 * TLD * (int)sizeof(uint32_t);
    cudaFuncSetAttribute(attn_tc_kernel, cudaFuncAttributeMaxDynamicSharedMemorySize,
                         attn_smem);
    cudaFuncSetAttribute(gemm_tc_kernel, cudaFuncAttributeMaxDynamicSharedMemorySize,
                         PIPE_BYTES);
    cudaFuncSetAttribute(conv_tc_kernel, cudaFuncAttributeMaxDynamicSharedMemorySize,
                         CPIPE_BYTES);

    const int M = B_ * N_;
    const int NX = B_ * N_ * C_;
    const int ks_arr[3] = {8, 4, 2};

    cvt_x_kernel<<<(NX + 255) / 256, 256>>>(x, xh, NX);                         // 0
    cvt_w_kernel<<<(3 * C_ * C_ + 255) / 256, 256>>>(Wq, Wkv, Wo, wqh, wkvh, woh); // 1
    wtrans_kernel<<<256, 256>>>((const float*)d_in[5], wth, 8);                 // 2
    {
        int s = HW_ - 8 + 1, n = s * s;                                         // 3 (PROFILED)
        conv_tc_kernel<<<dim3((n + 255) / 256, 3, B_), 128, CPIPE_BYTES>>>(
            xh, wth, (const float*)d_in[6], xr, s, 8);
    }
    gemm_tc_kernel<<<dim3((M + 127) / 128, 3), 256, PIPE_BYTES>>>(              // 4
        xh, wqh, bq, q, M, C_, C_);

    for (int br = 0; br < 3; br++) {
        const float* srw = (const float*)d_in[5 + br * 6 + 0];
        const float* srb = (const float*)d_in[5 + br * 6 + 1];
        const float* lng = (const float*)d_in[5 + br * 6 + 2];
        const float* lnb = (const float*)d_in[5 + br * 6 + 3];
        const float* lcw = (const float*)d_in[5 + br * 6 + 4];
        const float* lcb = (const float*)d_in[5 + br * 6 + 5];
        int ksz = ks_arr[br];
        int s = HW_ - ksz + 1;
        int n = s * s;
        int rows = B_ * n;

        if (br > 0) {
            wtrans_kernel<<<256, 256>>>(srw, wth, ksz);
            conv_tc_kernel<<<dim3((n + 255) / 256, 3, B_), 128, CPIPE_BYTES>>>(
                xh, wth, srb, xr, s, ksz);
        }
        ln_gelu_kernel<<<(rows + 7) / 8, 256>>>(xr, xrh, lng, lnb, rows);
        gemm_tc_kernel<<<dim3((rows + 127) / 128, 2), 256, PIPE_BYTES>>>(
            xrh, wkvh, bkv, kvb, rows, C_, 128);
        dwconv_kernel<<<(rows * HD_ + 255) / 256, 256>>>(kvb, lcw, lcb, v2, s);
        attn_tc_kernel<<<dim3(N_ / 64, B_), 128, attn_smem>>>(q, kvb, v2, xcath, n, br);
    }

    gemm_tc_kernel<<<dim3((M + 127) / 128, 3), 256, PIPE_BYTES>>>(
        xcath, woh, bo, (float*)d_out, M, C_, C_);
}

// round 12
// speedup vs baseline: 3.0442x; 1.0232x over previous
#include <cuda_runtime.h>
#include <cuda_fp16.h>
#include <math.h>
#include <stdint.h>

#define B_    8
#define N_    2304
#define C_    192
#define HW_   48
#define HD_   64
#define NMAX_ 2209

// ---------------- scratch ----------------
__device__ float  g_q[B_ * N_ * C_];
__device__ float  g_xr[B_ * NMAX_ * C_];
__device__ float  g_kv[B_ * NMAX_ * 128];
__device__ float  g_v2[B_ * NMAX_ * HD_];
__device__ __half g_xh[B_ * N_ * C_];
__device__ __half g_xrh[B_ * NMAX_ * C_];
__device__ __half g_xcath[B_ * N_ * C_];
__device__ __half g_wth[C_ * C_ * 64];       // [kyx][co][ci] fp16
__device__ __half g_wqh[C_ * C_];
__device__ __half g_wkvh[C_ * C_];
__device__ __half g_woh[C_ * C_];

// ---------------- helpers ----------------
__device__ __forceinline__ uint32_t f2tf(float v) {
    uint32_t r;
    asm("cvt.rna.tf32.f32 %0, %1;" : "=r"(r) : "f"(v));
    return r;
}
__device__ __forceinline__ void mma_tf32(float* d, const uint32_t* a, const uint32_t* b) {
    asm volatile(
        "mma.sync.aligned.m16n8k8.row.col.f32.tf32.tf32.f32 "
        "{%0,%1,%2,%3}, {%4,%5,%6,%7}, {%8,%9}, {%0,%1,%2,%3};"
        : "+f"(d[0]), "+f"(d[1]), "+f"(d[2]), "+f"(d[3])
        : "r"(a[0]), "r"(a[1]), "r"(a[2]), "r"(a[3]), "r"(b[0]), "r"(b[1]));
}
__device__ __forceinline__ void mma_f16(float* d, const uint32_t* a, const uint32_t* b) {
    asm volatile(
        "mma.sync.aligned.m16n8k16.row.col.f32.f16.f16.f32 "
        "{%0,%1,%2,%3}, {%4,%5,%6,%7}, {%8,%9}, {%0,%1,%2,%3};"
        : "+f"(d[0]), "+f"(d[1]), "+f"(d[2]), "+f"(d[3])
        : "r"(a[0]), "r"(a[1]), "r"(a[2]), "r"(a[3]), "r"(b[0]), "r"(b[1]));
}
__device__ __forceinline__ void cp_async16(uint32_t dst, const void* src, uint32_t ssize) {
    asm volatile("cp.async.cg.shared.global [%0], [%1], 16, %2;"
                 :: "r"(dst), "l"(src), "r"(ssize) : "memory");
}
__device__ __forceinline__ void cp_commit() {
    asm volatile("cp.async.commit_group;" ::: "memory");
}
__device__ __forceinline__ void cp_wait1() {
    asm volatile("cp.async.wait_group 1;" ::: "memory");
}
__device__ __forceinline__ void cp_wait0() {
    asm volatile("cp.async.wait_group 0;" ::: "memory");
}

#define BK     32
#define TW     20
#define A_ST   (128 * TW)
#define W_ST   (64 * TW)
#define PIPE_BYTES (3 * (A_ST + W_ST) * 4)    // 46080

// =====================================================================================
// Conversions
// =====================================================================================
__global__ void cvt_x_kernel(const float* __restrict__ in, __half* __restrict__ out, int n)
{
    int i = blockIdx.x * blockDim.x + threadIdx.x;
    if (i < n) out[i] = __float2half_rn(in[i]);
}

__global__ void cvt_w_kernel(const float* __restrict__ Wq, const float* __restrict__ Wkv,
                             const float* __restrict__ Wo, __half* __restrict__ wq,
                             __half* __restrict__ wkv, __half* __restrict__ wo)
{
    int i = blockIdx.x * blockDim.x + threadIdx.x;
    int total = 3 * C_ * C_;
    if (i >= total) return;
    int which = i / (C_ * C_);
    int r = i - which * (C_ * C_);
    int nn = r / C_, k = r - nn * C_;
    const float* src = (which == 0) ? Wq : (which == 1) ? Wkv : Wo;
    __half* dst = (which == 0) ? wq : (which == 1) ? wkv : wo;
    dst[nn * C_ + k] = __float2half_rn(src[(size_t)k * C_ + nn]);
}

__global__ void wtrans_kernel(const float* __restrict__ w, __half* __restrict__ wt, int ksz)
{
    int k2 = ksz * ksz;
    int total = C_ * C_ * k2;
    for (int idx = blockIdx.x * blockDim.x + threadIdx.x; idx < total;
         idx += gridDim.x * blockDim.x) {
        int ci = idx % C_;
        int rest = idx / C_;
        int co = rest % C_;
        int kyx = rest / C_;
        wt[idx] = __float2half_rn(w[((size_t)co * C_ + ci) * k2 + kyx]);
    }
}

// =====================================================================================
// SR conv implicit GEMM v3: block 128x64, 128 thr = 4 warps (2m x 2n), warp 64x32.
// Low smem traffic (0.094 B/MAC) + small block -> 3-4 blocks/SM for latency hiding.
// =====================================================================================
__global__ __launch_bounds__(128) void conv_tc_kernel(
    const __half* __restrict__ x, const __half* __restrict__ wt,
    const float* __restrict__ bias, float* __restrict__ out,
    int s_, int ksz)
{
    extern __shared__ uint32_t sm[];
    uint32_t* As = sm;                  // [3][128][TW]
    uint32_t* Ws = sm + 3 * A_ST;       // [3][64][TW]

    const int tid = threadIdx.x;
    const int warp = tid >> 5, lane = tid & 31;
    const int wm = warp & 1, wn = warp >> 1;
    const int lr = lane >> 2, lc = lane & 3;
    const int b = blockIdx.z;
    const int n = s_ * s_;
    const int m0 = blockIdx.x * 128;
    const int n0 = blockIdx.y * 64;

    const int prow = tid >> 2;          // 0..31
    const int chk = tid & 3;

    int rowoff[4];
    uint32_t aSz[4];
#pragma unroll
    for (int i = 0; i < 4; i++) {
        int p = m0 + prow + i * 32;
        aSz[i] = (p < n) ? 16u : 0u;
        int pp = (p < n) ? p : 0;
        rowoff[i] = ((pp / s_) * HW_ + (pp % s_)) * C_;
    }
    const __half* xb = x + (size_t)b * N_ * C_;

    const uint32_t asb = (uint32_t)__cvta_generic_to_shared(As);
    const uint32_t wsb = (uint32_t)__cvta_generic_to_shared(Ws);

    auto pf = [&](int kb, int st) {
        int kyx = kb / 6;
        int ci0 = (kb - kyx * 6) * BK;
        int ky = kyx / ksz, kx = kyx - ky * ksz;
        int koff = (ky * HW_ + kx) * C_ + ci0 + chk * 8;
#pragma unroll
        for (int i = 0; i < 4; i++)
            cp_async16(asb + (uint32_t)(((st * 128 + prow + i * 32) * TW + chk * 4) * 4),
                       xb + rowoff[i] + koff, aSz[i]);
        const __half* wp = wt + (size_t)kyx * C_ * C_ + ci0;
#pragma unroll
        for (int i = 0; i < 2; i++) {
            int idx = tid + 128 * i;
            int row = idx >> 2, ch2 = idx & 3;
            cp_async16(wsb + (uint32_t)(((st * 64 + row) * TW + ch2 * 4) * 4),
                       wp + (size_t)(n0 + row) * C_ + ch2 * 8, 16u);
        }
    };

    float acc[4][4][4];
#pragma unroll
    for (int mi = 0; mi < 4; mi++)
#pragma unroll
        for (int ni = 0; ni < 4; ni++)
#pragma unroll
            for (int j = 0; j < 4; j++) acc[mi][ni][j] = 0.f;

    const int KB = ksz * ksz * 6;
    pf(0, 0); cp_commit();
    pf(1, 1); cp_commit();

    int st = 0;
    for (int kb = 0; kb < KB; kb++) {
        if (kb + 1 < KB) cp_wait1(); else cp_wait0();
        __syncthreads();
        if (kb + 2 < KB) pf(kb + 2, (st + 2) % 3);
        cp_commit();
        const uint32_t* as = As + st * A_ST;
        const uint32_t* ws = Ws + st * W_ST;
#pragma unroll
        for (int ks = 0; ks < 2; ks++) {
            int ksw = ks * 8;
            uint32_t af[4][4];
#pragma unroll
            for (int mi = 0; mi < 4; mi++) {
                int rr = wm * 64 + mi * 16 + lr;
                af[mi][0] = as[rr * TW + ksw + lc];
                af[mi][1] = as[(rr + 8) * TW + ksw + lc];
                af[mi][2] = as[rr * TW + ksw + 4 + lc];
                af[mi][3] = as[(rr + 8) * TW + ksw + 4 + lc];
            }
            uint32_t bf[4][2];
#pragma unroll
            for (int ni = 0; ni < 4; ni++) {
                int cc = wn * 32 + ni * 8 + lr;
                bf[ni][0] = ws[cc * TW + ksw + lc];
                bf[ni][1] = ws[cc * TW + ksw + 4 + lc];
            }
#pragma unroll
            for (int mi = 0; mi < 4; mi++)
#pragma unroll
                for (int ni = 0; ni < 4; ni++) mma_f16(acc[mi][ni], af[mi], bf[ni]);
        }
        st = (st + 1) % 3;
    }
#pragma unroll
    for (int mi = 0; mi < 4; mi++) {
        int row = m0 + wm * 64 + mi * 16 + lr;
#pragma unroll
        for (int ni = 0; ni < 4; ni++) {
            int col = n0 + wn * 32 + ni * 8 + lc * 2;
            float b0 = bias[col], b1 = bias[col + 1];
            if (row < n) {
                float* o = out + ((size_t)b * n + row) * C_ + col;
                o[0] = acc[mi][ni][0] + b0;
                o[1] = acc[mi][ni][1] + b1;
            }
            if (row + 8 < n) {
                float* o = out + ((size_t)b * n + row + 8) * C_ + col;
                o[0] = acc[mi][ni][2] + b0;
                o[1] = acc[mi][ni][3] + b1;
            }
        }
    }
}

// =====================================================================================
// FP16 TC GEMM (unchanged): tiles 128x64, 8 warps 32x32.
// =====================================================================================
__global__ __launch_bounds__(256) void gemm_tc_kernel(
    const __half* __restrict__ A, const __half* __restrict__ W,
    const float* __restrict__ bias, float* __restrict__ out,
    int M, int K, int ldc)
{
    extern __shared__ uint32_t sm[];
    uint32_t* As = sm;
    uint32_t* Ws = sm + 3 * A_ST;

    const int tid = threadIdx.x;
    const int warp = tid >> 5, lane = tid & 31;
    const int wm = warp & 3, wn = warp >> 2;
    const int lr = lane >> 2, lc = lane & 3;
    const int m0 = blockIdx.x * 128;
    const int n0 = blockIdx.y * 64;

    const int r6 = tid >> 2;
    const int chk = tid & 3;

    const __half* aPtr[2];
    uint32_t aSz[2];
#pragma unroll
    for (int i = 0; i < 2; i++) {
        int m = m0 + r6 + i * 64;
        aSz[i] = (m < M) ? 16u : 0u;
        aPtr[i] = A + (size_t)((m < M) ? m : 0) * K + chk * 8;
    }
    const __half* wPtr = W + (size_t)(n0 + r6) * K + chk * 8;

    const uint32_t asb = (uint32_t)__cvta_generic_to_shared(As);
    const uint32_t wsb = (uint32_t)__cvta_generic_to_shared(Ws);

    auto pf = [&](int kb, int st) {
        int k0 = kb * BK;
#pragma unroll
        for (int i = 0; i < 2; i++)
            cp_async16(asb + (uint32_t)(((st * 128 + r6 + i * 64) * TW + chk * 4) * 4),
                       aPtr[i] + k0, aSz[i]);
        cp_async16(wsb + (uint32_t)(((st * 64 + r6) * TW + chk * 4) * 4), wPtr + k0, 16u);
    };

    float acc[2][4][4];
#pragma unroll
    for (int mi = 0; mi < 2; mi++)
#pragma unroll
        for (int ni = 0; ni < 4; ni++)
#pragma unroll
            for (int j = 0; j < 4; j++) acc[mi][ni][j] = 0.f;

    const int KB = K / BK;
    pf(0, 0); cp_commit();
    pf(1, 1); cp_commit();

    int st = 0;
    for (int kb = 0; kb < KB; kb++) {
        if (kb + 1 < KB) cp_wait1(); else cp_wait0();
        __syncthreads();
        if (kb + 2 < KB) pf(kb + 2, (st + 2) % 3);
        cp_commit();
        const uint32_t* as = As + st * A_ST;
        const uint32_t* ws = Ws + st * W_ST;
#pragma unroll
        for (int ks = 0; ks < 2; ks++) {
            int ksw = ks * 8;
            uint32_t af[2][4];
#pragma unroll
            for (int mi = 0; mi < 2; mi++) {
                int rr = wm * 32 + mi * 16 + lr;
                af[mi][0] = as[rr * TW + ksw + lc];
                af[mi][1] = as[(rr + 8) * TW + ksw + lc];
                af[mi][2] = as[rr * TW + ksw + 4 + lc];
                af[mi][3] = as[(rr + 8) * TW + ksw + 4 + lc];
            }
            uint32_t bf[4][2];
#pragma unroll
            for (int ni = 0; ni < 4; ni++) {
                int cc = wn * 32 + ni * 8 + lr;
                bf[ni][0] = ws[cc * TW + ksw + lc];
                bf[ni][1] = ws[cc * TW + ksw + 4 + lc];
            }
#pragma unroll
            for (int mi = 0; mi < 2; mi++)
#pragma unroll
                for (int ni = 0; ni < 4; ni++) mma_f16(acc[mi][ni], af[mi], bf[ni]);
        }
        st = (st + 1) % 3;
    }
#pragma unroll
    for (int mi = 0; mi < 2; mi++) {
        int row = m0 + wm * 32 + mi * 16 + lr;
#pragma unroll
        for (int ni = 0; ni < 4; ni++) {
            int col = n0 + wn * 32 + ni * 8 + lc * 2;
            float b0 = bias[col], b1 = bias[col + 1];
            if (row < M) {
                out[(size_t)row * ldc + col]     = acc[mi][ni][0] + b0;
                out[(size_t)row * ldc + col + 1] = acc[mi][ni][1] + b1;
            }
            if (row + 8 < M) {
                out[(size_t)(row + 8) * ldc + col]     = acc[mi][ni][2] + b0;
                out[(size_t)(row + 8) * ldc + col + 1] = acc[mi][ni][3] + b1;
            }
        }
    }
}

// =====================================================================================
// Fused LayerNorm + exact GELU; reads fp32 xr, writes fp16. One warp per row.
// =====================================================================================
__global__ void ln_gelu_kernel(const float* __restrict__ xr, __half* __restrict__ xrh,
                               const float* __restrict__ g, const float* __restrict__ bb,
                               int rows)
{
    int wid = (blockIdx.x * blockDim.x + threadIdx.x) >> 5;
    int lane = threadIdx.x & 31;
    if (wid >= rows) return;
    const float* row = xr + (size_t)wid * C_;
    __half* orow = xrh + (size_t)wid * C_;
    float s1 = 0.f, s2 = 0.f;
#pragma unroll
    for (int j = lane; j < C_; j += 32) {
        float v = row[j];
        s1 += v;
        s2 += v * v;
    }
#pragma unroll
    for (int o = 16; o; o >>= 1) {
        s1 += __shfl_xor_sync(0xffffffffu, s1, o);
        s2 += __shfl_xor_sync(0xffffffffu, s2, o);
    }
    float mu = s1 * (1.f / C_);
    float var = s2 * (1.f / C_) - mu * mu;
    float inv = rsqrtf(var + 1e-5f);
#pragma unroll
    for (int j = lane; j < C_; j += 32) {
        float v = (row[j] - mu) * inv * g[j] + bb[j];
        orow[j] = __float2half_rn(0.5f * v * (1.f + erff(v * 0.70710678118654752440f)));
    }
}

// =====================================================================================
// Depthwise 3x3 (pad 1) on V + residual (fp32)
// =====================================================================================
__global__ void dwconv_kernel(const float* __restrict__ kv, const float* __restrict__ w,
                              const float* __restrict__ bias, float* __restrict__ v2, int s)
{
    int n = s * s;
    int total = B_ * n * HD_;
    int idx = blockIdx.x * blockDim.x + threadIdx.x;
    if (idx >= total) return;
    int hd = idx & 63;
    int p = (idx >> 6) % n;
    int b = idx / (n * 64);
    int y = p / s;
    int x0 = p - y * s;
    const float* vb = kv + (size_t)b * n * 128 + 64 + hd;
    float acc = bias[hd];
#pragma unroll
    for (int dy = -1; dy <= 1; dy++) {
#pragma unroll
        for (int dx = -1; dx <= 1; dx++) {
            int yy = y + dy, xx = x0 + dx;
            if (yy >= 0 && yy < s && xx >= 0 && xx < s)
                acc += w[hd * 9 + (dy + 1) * 3 + (dx + 1)] * vb[(size_t)(yy * s + xx) * 128];
        }
    }
    v2[idx] = acc + vb[(size_t)p * 128];
}

// =====================================================================================
// Tensor-core flash attention (tf32 MMA, fp32 softmax), dynamic smem (72 KB).
// =====================================================================================
#define TLD 72
__global__ __launch_bounds__(128) void attn_tc_kernel(
    const float* __restrict__ q, const float* __restrict__ kv,
    const float* __restrict__ v2, __half* __restrict__ xcath,
    int nkv, int head)
{
    extern __shared__ uint32_t smbuf[];
    uint32_t (*qs)[TLD]  = (uint32_t (*)[TLD])smbuf;
    uint32_t (*kst)[TLD] = (uint32_t (*)[TLD])(smbuf + 64 * TLD);
    uint32_t (*vs)[TLD]  = (uint32_t (*)[TLD])(smbuf + 2 * 64 * TLD);
    uint32_t (*ps)[TLD]  = (uint32_t (*)[TLD])(smbuf + 3 * 64 * TLD);

    const int tid = threadIdx.x;
    const int warp = tid >> 5, lane = tid & 31;
    const int wm = warp;
    const int lr = lane >> 2, lc = lane & 3;
    const int b = blockIdx.y;
    const int q0 = blockIdx.x * 64;
    const int rr = wm * 16 + lr;
    const float scale = 0.07216878364870322056f;

#pragma unroll
    for (int i = 0; i < 32; i++) {
        int e = tid + i * 128;
        int r = e >> 6, d = e & 63;
        qs[d][r] = f2tf(q[((size_t)b * N_ + q0 + r) * C_ + head * HD_ + d]);
    }

    float m_i[2], l_i[2], oacc[8][4];
    m_i[0] = m_i[1] = -1e30f;
    l_i[0] = l_i[1] = 0.f;
#pragma unroll
    for (int ni = 0; ni < 8; ni++)
#pragma unroll
        for (int j = 0; j < 4; j++) oacc[ni][j] = 0.f;

    __syncthreads();

    const int nchunks = (nkv + 63) >> 6;
    for (int c0 = 0; c0 < nchunks; c0++) {
        int base = c0 * 64;
        int cs = nkv - base;
        if (cs > 64) cs = 64;
#pragma unroll
        for (int i = 0; i < 32; i++) {
            int e = tid + i * 128;
            int r = e >> 6, d = e & 63;
            if (r < cs) {
                size_t kidx = (size_t)b * nkv + base + r;
                kst[d][r] = f2tf(kv[kidx * 128 + d]);
                vs[r][d]  = f2tf(v2[kidx * 64 + d]);
            } else {
                kst[d][r] = 0u;
                vs[r][d]  = 0u;
            }
        }
        __syncthreads();

        float sacc[8][4];
#pragma unroll
        for (int ni = 0; ni < 8; ni++)
#pragma unroll
            for (int j = 0; j < 4; j++) sacc[ni][j] = 0.f;
#pragma unroll
        for (int kk = 0; kk < 64; kk += 8) {
            uint32_t af[4];
            af[0] = qs[kk + lc][rr];
            af[1] = qs[kk + lc][rr + 8];
            af[2] = qs[kk + 4 + lc][rr];
            af[3] = qs[kk + 4 + lc][rr + 8];
#pragma unroll
            for (int ni = 0; ni < 8; ni++) {
                uint32_t bf[2];
                int cc = ni * 8 + lr;
                bf[0] = kst[kk + lc][cc];
                bf[1] = kst[kk + 4 + lc][cc];
                mma_tf32(sacc[ni], af, bf);
            }
        }

#pragma unroll
        for (int h = 0; h < 2; h++) {
            float mx = -1e30f;
#pragma unroll
            for (int ni = 0; ni < 8; ni++)
#pragma unroll
                for (int j = 0; j < 2; j++) {
                    float v = sacc[ni][2 * h + j] * scale;
                    if (ni * 8 + 2 * lc + j >= cs) v = -1e30f;
                    sacc[ni][2 * h + j] = v;
                    mx = fmaxf(mx, v);
                }
            mx = fmaxf(mx, __shfl_xor_sync(0xffffffffu, mx, 1));
            mx = fmaxf(mx, __shfl_xor_sync(0xffffffffu, mx, 2));
            float mnew = fmaxf(m_i[h], mx);
            float alpha = __expf(m_i[h] - mnew);
            float rs = 0.f;
#pragma unroll
            for (int ni = 0; ni < 8; ni++)
#pragma unroll
                for (int j = 0; j < 2; j++) {
                    float p = __expf(sacc[ni][2 * h + j] - mnew);
                    sacc[ni][2 * h + j] = p;
                    rs += p;
                }
            rs += __shfl_xor_sync(0xffffffffu, rs, 1);
            rs += __shfl_xor_sync(0xffffffffu, rs, 2);
            l_i[h] = l_i[h] * alpha + rs;
            m_i[h] = mnew;
#pragma unroll
            for (int ni = 0; ni < 8; ni++) {
                oacc[ni][2 * h]     *= alpha;
                oacc[ni][2 * h + 1] *= alpha;
            }
        }

#pragma unroll
        for (int ni = 0; ni < 8; ni++) {
            int c = ni * 8 + 2 * lc;
            ps[c][rr]         = f2tf(sacc[ni][0]);
            ps[c + 1][rr]     = f2tf(sacc[ni][1]);
            ps[c][rr + 8]     = f2tf(sacc[ni][2]);
            ps[c + 1][rr + 8] = f2tf(sacc[ni][3]);
        }
        __syncwarp();

#pragma unroll
        for (int kk = 0; kk < 64; kk += 8) {
            uint32_t af[4];
            af[0] = ps[kk + lc][rr];
            af[1] = ps[kk + lc][rr + 8];
            af[2] = ps[kk + 4 + lc][rr];
            af[3] = ps[kk + 4 + lc][rr + 8];
#pragma unroll
            for (int ni = 0; ni < 8; ni++) {
                uint32_t bf[2];
                int cc = ni * 8 + lr;
                bf[0] = vs[kk + lc][cc];
                bf[1] = vs[kk + 4 + lc][cc];
                mma_tf32(oacc[ni], af, bf);
            }
        }
        __syncthreads();
    }

    float inv0 = 1.f / l_i[0], inv1 = 1.f / l_i[1];
#pragma unroll
    for (int ni = 0; ni < 8; ni++) {
        int col = head * HD_ + ni * 8 + 2 * lc;
        size_t r0 = (size_t)b * N_ + q0 + rr;
        *(__half2*)(xcath + r0 * C_ + col) =
            __floats2half2_rn(oacc[ni][0] * inv0, oacc[ni][1] * inv0);
        *(__half2*)(xcath + (r0 + 8) * C_ + col) =
            __floats2half2_rn(oacc[ni][2] * inv1, oacc[ni][3] * inv1);
    }
}

// =====================================================================================
// Host orchestration (conv b1 kept at profiled launch index 3)
// =====================================================================================
extern "C" void kernel_launch(void* const* d_in, const int* in_sizes, int n_in,
                              void* d_out, int out_size)
{
    const float* x   = (const float*)d_in[0];
    const float* Wq  = (const float*)d_in[1];
    const float* bq  = (const float*)d_in[2];
    const float* Wkv = (const float*)d_in[3];
    const float* bkv = (const float*)d_in[4];
    const float* Wo  = (const float*)d_in[23];
    const float* bo  = (const float*)d_in[24];

    float *q, *xr, *kvb, *v2;
    __half *xh, *xrh, *xcath, *wth, *wqh, *wkvh, *woh;
    cudaGetSymbolAddress((void**)&q, g_q);
    cudaGetSymbolAddress((void**)&xr, g_xr);
    cudaGetSymbolAddress((void**)&kvb, g_kv);
    cudaGetSymbolAddress((void**)&v2, g_v2);
    cudaGetSymbolAddress((void**)&xh, g_xh);
    cudaGetSymbolAddress((void**)&xrh, g_xrh);
    cudaGetSymbolAddress((void**)&xcath, g_xcath);
    cudaGetSymbolAddress((void**)&wth, g_wth);
    cudaGetSymbolAddress((void**)&wqh, g_wqh);
    cudaGetSymbolAddress((void**)&wkvh, g_wkvh);
    cudaGetSymbolAddress((void**)&woh, g_woh);

    const int attn_smem = 4 * 64 * TLD * (int)sizeof(uint32_t);
    cudaFuncSetAttribute(attn_tc_kernel, cudaFuncAttributeMaxDynamicSharedMemorySize,
                         attn_smem);
    cudaFuncSetAttribute(gemm_tc_kernel, cudaFuncAttributeMaxDynamicSharedMemorySize,
                         PIPE_BYTES);
    cudaFuncSetAttribute(conv_tc_kernel, cudaFuncAttributeMaxDynamicSharedMemorySize,
                         PIPE_BYTES);

    const int M = B_ * N_;
    const int NX = B_ * N_ * C_;
    const int ks_arr[3] = {8, 4, 2};

    cvt_x_kernel<<<(NX + 255) / 256, 256>>>(x, xh, NX);                            // 0
    cvt_w_kernel<<<(3 * C_ * C_ + 255) / 256, 256>>>(Wq, Wkv, Wo, wqh, wkvh, woh); // 1
    wtrans_kernel<<<256, 256>>>((const float*)d_in[5], wth, 8);                    // 2
    {
        int s = HW_ - 8 + 1, n = s * s;                                            // 3 (PROFILED)
        conv_tc_kernel<<<dim3((n + 127) / 128, 3, B_), 128, PIPE_BYTES>>>(
            xh, wth, (const float*)d_in[6], xr, s, 8);
    }
    gemm_tc_kernel<<<dim3((M + 127) / 128, 3), 256, PIPE_BYTES>>>(                 // 4
        xh, wqh, bq, q, M, C_, C_);

    for (int br = 0; br < 3; br++) {
        const float* srw = (const float*)d_in[5 + br * 6 + 0];
        const float* srb = (const float*)d_in[5 + br * 6 + 1];
        const float* lng = (const float*)d_in[5 + br * 6 + 2];
        const float* lnb = (const float*)d_in[5 + br * 6 + 3];
        const float* lcw = (const float*)d_in[5 + br * 6 + 4];
        const float* lcb = (const float*)d_in[5 + br * 6 + 5];
        int ksz = ks_arr[br];
        int s = HW_ - ksz + 1;
        int n = s * s;
        int rows = B_ * n;

        if (br > 0) {
            wtrans_kernel<<<256, 256>>>(srw, wth, ksz);
            conv_tc_kernel<<<dim3((n + 127) / 128, 3, B_), 128, PIPE_BYTES>>>(
                xh, wth, srb, xr, s, ksz);
        }
        ln_gelu_kernel<<<(rows + 7) / 8, 256>>>(xr, xrh, lng, lnb, rows);
        gemm_tc_kernel<<<dim3((rows + 127) / 128, 2), 256, PIPE_BYTES>>>(
            xrh, wkvh, bkv, kvb, rows, C_, 128);
        dwconv_kernel<<<(rows * HD_ + 255) / 256, 256>>>(kvb, lcw, lcb, v2, s);
        attn_tc_kernel<<<dim3(N_ / 64, B_), 128, attn_smem>>>(q, kvb, v2, xcath, n, br);
    }

    gemm_tc_kernel<<<dim3((M + 127) / 128, 3), 256, PIPE_BYTES>>>(
        xcath, woh, bo, (float*)d_out, M, C_, C_);
}

// round 13
// speedup vs baseline: 3.8344x; 1.2596x over previous
#include <cuda_runtime.h>
#include <cuda_fp16.h>
#include <math.h>
#include <stdint.h>

#define B_    8
#define N_    2304
#define C_    192
#define HW_   48
#define HD_   64
// branch sizes: s=41,45,47 ; n=1681,2025,2209 ; rows per branch = 8n
#define NTOT_ 5915
#define RTOT_ (B_ * NTOT_)        // 47320 rows across all branches

// ---------------- scratch ----------------
__device__ float  g_q[B_ * N_ * C_];
__device__ float  g_xr[RTOT_ * C_];
__device__ float  g_kv[RTOT_ * 128];
__device__ float  g_v2[RTOT_ * HD_];
__device__ __half g_xh[B_ * N_ * C_];
__device__ __half g_xrh[RTOT_ * C_];
__device__ __half g_xcath[B_ * N_ * C_];
__device__ __half g_wth[C_ * C_ * 84];       // b1@0 (64 kyx), b2@64C^2 (16), b3@80C^2 (4)
__device__ __half g_wqh[C_ * C_];
__device__ __half g_wkvh[C_ * C_];
__device__ __half g_woh[C_ * C_];

// ---------------- helpers ----------------
__device__ __forceinline__ uint32_t f2tf(float v) {
    uint32_t r;
    asm("cvt.rna.tf32.f32 %0, %1;" : "=r"(r) : "f"(v));
    return r;
}
__device__ __forceinline__ void mma_tf32(float* d, const uint32_t* a, const uint32_t* b) {
    asm volatile(
        "mma.sync.aligned.m16n8k8.row.col.f32.tf32.tf32.f32 "
        "{%0,%1,%2,%3}, {%4,%5,%6,%7}, {%8,%9}, {%0,%1,%2,%3};"
        : "+f"(d[0]), "+f"(d[1]), "+f"(d[2]), "+f"(d[3])
        : "r"(a[0]), "r"(a[1]), "r"(a[2]), "r"(a[3]), "r"(b[0]), "r"(b[1]));
}
__device__ __forceinline__ void mma_f16(float* d, const uint32_t* a, const uint32_t* b) {
    asm volatile(
        "mma.sync.aligned.m16n8k16.row.col.f32.f16.f16.f32 "
        "{%0,%1,%2,%3}, {%4,%5,%6,%7}, {%8,%9}, {%0,%1,%2,%3};"
        : "+f"(d[0]), "+f"(d[1]), "+f"(d[2]), "+f"(d[3])
        : "r"(a[0]), "r"(a[1]), "r"(a[2]), "r"(a[3]), "r"(b[0]), "r"(b[1]));
}
__device__ __forceinline__ void cp_async16(uint32_t dst, const void* src, uint32_t ssize) {
    asm volatile("cp.async.cg.shared.global [%0], [%1], 16, %2;"
                 :: "r"(dst), "l"(src), "r"(ssize) : "memory");
}
__device__ __forceinline__ void cp_commit() {
    asm volatile("cp.async.commit_group;" ::: "memory");
}
__device__ __forceinline__ void cp_wait1() {
    asm volatile("cp.async.wait_group 1;" ::: "memory");
}
__device__ __forceinline__ void cp_wait0() {
    asm volatile("cp.async.wait_group 0;" ::: "memory");
}

#define BK     32
#define TW     20
#define A_ST   (128 * TW)
#define W_ST   (64 * TW)
#define PIPE_BYTES (3 * (A_ST + W_ST) * 4)    // 46080

// ---------------- batched-launch param structs ----------------
struct ConvP {
    int mb1, mb2;                 // block-prefix boundaries (14, 30)
    int s[3], k[3], w[3], o[3];   // spatial size, ksz, weight offset (halves), row offset
    const float* bias[3];
};
struct LnP {
    int r1, r2;                   // row-prefix boundaries
    const float *g[3], *b[3];
};
struct DwP {
    int e1, e2;                   // element-prefix boundaries
    int s[3], o[3];
    const float *w[3], *c[3];
};
struct AtP {
    int nkv[3], o[3];
};

// =====================================================================================
// Conversions
// =====================================================================================
__global__ void cvt_x_kernel(const float* __restrict__ in, __half* __restrict__ out, int n)
{
    int i = blockIdx.x * blockDim.x + threadIdx.x;
    if (i < n) out[i] = __float2half_rn(in[i]);
}

__global__ void cvt_w_kernel(const float* __restrict__ Wq, const float* __restrict__ Wkv,
                             const float* __restrict__ Wo, __half* __restrict__ wq,
                             __half* __restrict__ wkv, __half* __restrict__ wo)
{
    int i = blockIdx.x * blockDim.x + threadIdx.x;
    int total = 3 * C_ * C_;
    if (i >= total) return;
    int which = i / (C_ * C_);
    int r = i - which * (C_ * C_);
    int nn = r / C_, k = r - nn * C_;
    const float* src = (which == 0) ? Wq : (which == 1) ? Wkv : Wo;
    __half* dst = (which == 0) ? wq : (which == 1) ? wkv : wo;
    dst[nn * C_ + k] = __float2half_rn(src[(size_t)k * C_ + nn]);
}

// all conv weights: w[co][ci][ky][kx] -> wth[woff + kyx*C^2 + co*C + ci]
__global__ void wtrans_all_kernel(const float* __restrict__ w1, const float* __restrict__ w2,
                                  const float* __restrict__ w3, __half* __restrict__ wt)
{
    const int CC = C_ * C_;
    int total = 84 * CC;
    for (int idx = blockIdx.x * blockDim.x + threadIdx.x; idx < total;
         idx += gridDim.x * blockDim.x) {
        const float* src;
        int rel, k2;
        if (idx < 64 * CC)      { src = w1; rel = idx;           k2 = 64; }
        else if (idx < 80 * CC) { src = w2; rel = idx - 64 * CC; k2 = 16; }
        else                    { src = w3; rel = idx - 80 * CC; k2 = 4;  }
        int ci = rel % C_;
        int rest = rel / C_;
        int co = rest % C_;
        int kyx = rest / C_;
        wt[idx] = __float2half_rn(src[((size_t)co * C_ + ci) * k2 + kyx]);
    }
}

// =====================================================================================
// Batched SR conv implicit GEMM: all 3 branches in one launch.
// block 128x64, 128 thr = 4 warps (2m x 2n), warp 64x32. Branch from blockIdx.x prefix.
// =====================================================================================
__global__ __launch_bounds__(128) void conv_all_kernel(
    const __half* __restrict__ x, const __half* __restrict__ wtg,
    float* __restrict__ out, ConvP P)
{
    extern __shared__ uint32_t sm[];
    uint32_t* As = sm;
    uint32_t* Ws = sm + 3 * A_ST;

    const int tid = threadIdx.x;
    const int warp = tid >> 5, lane = tid & 31;
    const int wm = warp & 1, wn = warp >> 1;
    const int lr = lane >> 2, lc = lane & 3;
    const int b = blockIdx.z;
    const int n0 = blockIdx.y * 64;

    // branch lookup
    int bx = blockIdx.x;
    int br = (bx >= P.mb1) ? ((bx >= P.mb2) ? 2 : 1) : 0;
    int mblk = bx - ((br == 0) ? 0 : (br == 1) ? P.mb1 : P.mb2);
    const int s_ = P.s[br], ksz = P.k[br];
    const int n = s_ * s_;
    const int m0 = mblk * 128;
    const __half* wt = wtg + P.w[br];
    const float* bias = P.bias[br];
    float* ob = out + (size_t)(P.o[br]) * C_;

    const int prow = tid >> 2;
    const int chk = tid & 3;

    int rowoff[4];
    uint32_t aSz[4];
#pragma unroll
    for (int i = 0; i < 4; i++) {
        int p = m0 + prow + i * 32;
        aSz[i] = (p < n) ? 16u : 0u;
        int pp = (p < n) ? p : 0;
        rowoff[i] = ((pp / s_) * HW_ + (pp % s_)) * C_;
    }
    const __half* xb = x + (size_t)b * N_ * C_;

    const uint32_t asb = (uint32_t)__cvta_generic_to_shared(As);
    const uint32_t wsb = (uint32_t)__cvta_generic_to_shared(Ws);

    auto pf = [&](int kb, int st) {
        int kyx = kb / 6;
        int ci0 = (kb - kyx * 6) * BK;
        int ky = kyx / ksz, kx = kyx - ky * ksz;
        int koff = (ky * HW_ + kx) * C_ + ci0 + chk * 8;
#pragma unroll
        for (int i = 0; i < 4; i++)
            cp_async16(asb + (uint32_t)(((st * 128 + prow + i * 32) * TW + chk * 4) * 4),
                       xb + rowoff[i] + koff, aSz[i]);
        const __half* wp = wt + (size_t)kyx * C_ * C_ + ci0;
#pragma unroll
        for (int i = 0; i < 2; i++) {
            int idx = tid + 128 * i;
            int row = idx >> 2, ch2 = idx & 3;
            cp_async16(wsb + (uint32_t)(((st * 64 + row) * TW + ch2 * 4) * 4),
                       wp + (size_t)(n0 + row) * C_ + ch2 * 8, 16u);
        }
    };

    float acc[4][4][4];
#pragma unroll
    for (int mi = 0; mi < 4; mi++)
#pragma unroll
        for (int ni = 0; ni < 4; ni++)
#pragma unroll
            for (int j = 0; j < 4; j++) acc[mi][ni][j] = 0.f;

    const int KB = ksz * ksz * 6;
    pf(0, 0); cp_commit();
    pf(1, 1); cp_commit();

    int st = 0;
    for (int kb = 0; kb < KB; kb++) {
        if (kb + 1 < KB) cp_wait1(); else cp_wait0();
        __syncthreads();
        if (kb + 2 < KB) pf(kb + 2, (st + 2) % 3);
        cp_commit();
        const uint32_t* as = As + st * A_ST;
        const uint32_t* ws = Ws + st * W_ST;
#pragma unroll
        for (int ks = 0; ks < 2; ks++) {
            int ksw = ks * 8;
            uint32_t af[4][4];
#pragma unroll
            for (int mi = 0; mi < 4; mi++) {
                int rr = wm * 64 + mi * 16 + lr;
                af[mi][0] = as[rr * TW + ksw + lc];
                af[mi][1] = as[(rr + 8) * TW + ksw + lc];
                af[mi][2] = as[rr * TW + ksw + 4 + lc];
                af[mi][3] = as[(rr + 8) * TW + ksw + 4 + lc];
            }
            uint32_t bf[4][2];
#pragma unroll
            for (int ni = 0; ni < 4; ni++) {
                int cc = wn * 32 + ni * 8 + lr;
                bf[ni][0] = ws[cc * TW + ksw + lc];
                bf[ni][1] = ws[cc * TW + ksw + 4 + lc];
            }
#pragma unroll
            for (int mi = 0; mi < 4; mi++)
#pragma unroll
                for (int ni = 0; ni < 4; ni++) mma_f16(acc[mi][ni], af[mi], bf[ni]);
        }
        st = (st + 1) % 3;
    }
#pragma unroll
    for (int mi = 0; mi < 4; mi++) {
        int row = m0 + wm * 64 + mi * 16 + lr;
#pragma unroll
        for (int ni = 0; ni < 4; ni++) {
            int col = n0 + wn * 32 + ni * 8 + lc * 2;
            float b0 = bias[col], b1 = bias[col + 1];
            if (row < n) {
                float* o = ob + ((size_t)b * n + row) * C_ + col;
                o[0] = acc[mi][ni][0] + b0;
                o[1] = acc[mi][ni][1] + b1;
            }
            if (row + 8 < n) {
                float* o = ob + ((size_t)b * n + row + 8) * C_ + col;
                o[0] = acc[mi][ni][2] + b0;
                o[1] = acc[mi][ni][3] + b1;
            }
        }
    }
}

// =====================================================================================
// FP16 TC GEMM (unchanged): tiles 128x64, 8 warps 32x32.
// =====================================================================================
__global__ __launch_bounds__(256) void gemm_tc_kernel(
    const __half* __restrict__ A, const __half* __restrict__ W,
    const float* __restrict__ bias, float* __restrict__ out,
    int M, int K, int ldc)
{
    extern __shared__ uint32_t sm[];
    uint32_t* As = sm;
    uint32_t* Ws = sm + 3 * A_ST;

    const int tid = threadIdx.x;
    const int warp = tid >> 5, lane = tid & 31;
    const int wm = warp & 3, wn = warp >> 2;
    const int lr = lane >> 2, lc = lane & 3;
    const int m0 = blockIdx.x * 128;
    const int n0 = blockIdx.y * 64;

    const int r6 = tid >> 2;
    const int chk = tid & 3;

    const __half* aPtr[2];
    uint32_t aSz[2];
#pragma unroll
    for (int i = 0; i < 2; i++) {
        int m = m0 + r6 + i * 64;
        aSz[i] = (m < M) ? 16u : 0u;
        aPtr[i] = A + (size_t)((m < M) ? m : 0) * K + chk * 8;
    }
    const __half* wPtr = W + (size_t)(n0 + r6) * K + chk * 8;

    const uint32_t asb = (uint32_t)__cvta_generic_to_shared(As);
    const uint32_t wsb = (uint32_t)__cvta_generic_to_shared(Ws);

    auto pf = [&](int kb, int st) {
        int k0 = kb * BK;
#pragma unroll
        for (int i = 0; i < 2; i++)
            cp_async16(asb + (uint32_t)(((st * 128 + r6 + i * 64) * TW + chk * 4) * 4),
                       aPtr[i] + k0, aSz[i]);
        cp_async16(wsb + (uint32_t)(((st * 64 + r6) * TW + chk * 4) * 4), wPtr + k0, 16u);
    };

    float acc[2][4][4];
#pragma unroll
    for (int mi = 0; mi < 2; mi++)
#pragma unroll
        for (int ni = 0; ni < 4; ni++)
#pragma unroll
            for (int j = 0; j < 4; j++) acc[mi][ni][j] = 0.f;

    const int KB = K / BK;
    pf(0, 0); cp_commit();
    pf(1, 1); cp_commit();

    int st = 0;
    for (int kb = 0; kb < KB; kb++) {
        if (kb + 1 < KB) cp_wait1(); else cp_wait0();
        __syncthreads();
        if (kb + 2 < KB) pf(kb + 2, (st + 2) % 3);
        cp_commit();
        const uint32_t* as = As + st * A_ST;
        const uint32_t* ws = Ws + st * W_ST;
#pragma unroll
        for (int ks = 0; ks < 2; ks++) {
            int ksw = ks * 8;
            uint32_t af[2][4];
#pragma unroll
            for (int mi = 0; mi < 2; mi++) {
                int rr = wm * 32 + mi * 16 + lr;
                af[mi][0] = as[rr * TW + ksw + lc];
                af[mi][1] = as[(rr + 8) * TW + ksw + lc];
                af[mi][2] = as[rr * TW + ksw + 4 + lc];
                af[mi][3] = as[(rr + 8) * TW + ksw + 4 + lc];
            }
            uint32_t bf[4][2];
#pragma unroll
            for (int ni = 0; ni < 4; ni++) {
                int cc = wn * 32 + ni * 8 + lr;
                bf[ni][0] = ws[cc * TW + ksw + lc];
                bf[ni][1] = ws[cc * TW + ksw + 4 + lc];
            }
#pragma unroll
            for (int mi = 0; mi < 2; mi++)
#pragma unroll
                for (int ni = 0; ni < 4; ni++) mma_f16(acc[mi][ni], af[mi], bf[ni]);
        }
        st = (st + 1) % 3;
    }
#pragma unroll
    for (int mi = 0; mi < 2; mi++) {
        int row = m0 + wm * 32 + mi * 16 + lr;
#pragma unroll
        for (int ni = 0; ni < 4; ni++) {
            int col = n0 + wn * 32 + ni * 8 + lc * 2;
            float b0 = bias[col], b1 = bias[col + 1];
            if (row < M) {
                out[(size_t)row * ldc + col]     = acc[mi][ni][0] + b0;
                out[(size_t)row * ldc + col + 1] = acc[mi][ni][1] + b1;
            }
            if (row + 8 < M) {
                out[(size_t)(row + 8) * ldc + col]     = acc[mi][ni][2] + b0;
                out[(size_t)(row + 8) * ldc + col + 1] = acc[mi][ni][3] + b1;
            }
        }
    }
}

// =====================================================================================
// Batched LayerNorm + exact GELU over all branch rows. One warp per row.
// =====================================================================================
__global__ void ln_gelu_all_kernel(const float* __restrict__ xr, __half* __restrict__ xrh,
                                   LnP P, int rows)
{
    int wid = (blockIdx.x * blockDim.x + threadIdx.x) >> 5;
    int lane = threadIdx.x & 31;
    if (wid >= rows) return;
    int br = (wid >= P.r1) ? ((wid >= P.r2) ? 2 : 1) : 0;
    const float* g = P.g[br];
    const float* bb = P.b[br];
    const float* row = xr + (size_t)wid * C_;
    __half* orow = xrh + (size_t)wid * C_;
    float s1 = 0.f, s2 = 0.f;
#pragma unroll
    for (int j = lane; j < C_; j += 32) {
        float v = row[j];
        s1 += v;
        s2 += v * v;
    }
#pragma unroll
    for (int o = 16; o; o >>= 1) {
        s1 += __shfl_xor_sync(0xffffffffu, s1, o);
        s2 += __shfl_xor_sync(0xffffffffu, s2, o);
    }
    float mu = s1 * (1.f / C_);
    float var = s2 * (1.f / C_) - mu * mu;
    float inv = rsqrtf(var + 1e-5f);
#pragma unroll
    for (int j = lane; j < C_; j += 32) {
        float v = (row[j] - mu) * inv * g[j] + bb[j];
        orow[j] = __float2half_rn(0.5f * v * (1.f + erff(v * 0.70710678118654752440f)));
    }
}

// =====================================================================================
// Batched depthwise 3x3 + residual over all branches.
// =====================================================================================
__global__ void dwconv_all_kernel(const float* __restrict__ kv, float* __restrict__ v2,
                                  DwP P, int total)
{
    int idx = blockIdx.x * blockDim.x + threadIdx.x;
    if (idx >= total) return;
    int br = (idx >= P.e1) ? ((idx >= P.e2) ? 2 : 1) : 0;
    int local = idx - ((br == 0) ? 0 : (br == 1) ? P.e1 : P.e2);
    int s = P.s[br];
    int n = s * s;
    const float* w = P.w[br];
    const float* bias = P.c[br];
    int hd = local & 63;
    int p = (local >> 6) % n;
    int b = (local >> 6) / n;
    int y = p / s;
    int x0 = p - y * s;
    size_t base = (size_t)(P.o[br] + b * n);
    const float* vb = kv + base * 128 + 64 + hd;
    float acc = bias[hd];
#pragma unroll
    for (int dy = -1; dy <= 1; dy++) {
#pragma unroll
        for (int dx = -1; dx <= 1; dx++) {
            int yy = y + dy, xx = x0 + dx;
            if (yy >= 0 && yy < s && xx >= 0 && xx < s)
                acc += w[hd * 9 + (dy + 1) * 3 + (dx + 1)] * vb[(size_t)(yy * s + xx) * 128];
        }
    }
    v2[base * 64 + (size_t)p * 64 + hd] = acc + vb[(size_t)p * 128];
}

// =====================================================================================
// Batched flash attention: grid (qtiles, B, 3 heads). tf32 MMA, fp32 softmax.
// =====================================================================================
#define TLD 72
__global__ __launch_bounds__(128) void attn_all_kernel(
    const float* __restrict__ q, const float* __restrict__ kv,
    const float* __restrict__ v2, __half* __restrict__ xcath, AtP P)
{
    extern __shared__ uint32_t smbuf[];
    uint32_t (*qs)[TLD]  = (uint32_t (*)[TLD])smbuf;
    uint32_t (*kst)[TLD] = (uint32_t (*)[TLD])(smbuf + 64 * TLD);
    uint32_t (*vs)[TLD]  = (uint32_t (*)[TLD])(smbuf + 2 * 64 * TLD);
    uint32_t (*ps)[TLD]  = (uint32_t (*)[TLD])(smbuf + 3 * 64 * TLD);

    const int tid = threadIdx.x;
    const int warp = tid >> 5, lane = tid & 31;
    const int wm = warp;
    const int lr = lane >> 2, lc = lane & 3;
    const int b = blockIdx.y;
    const int head = blockIdx.z;
    const int q0 = blockIdx.x * 64;
    const int rr = wm * 16 + lr;
    const int nkv = P.nkv[head];
    const float* kvb = kv + (size_t)P.o[head] * 128;
    const float* v2b = v2 + (size_t)P.o[head] * 64;
    const float scale = 0.07216878364870322056f;

#pragma unroll
    for (int i = 0; i < 32; i++) {
        int e = tid + i * 128;
        int r = e >> 6, d = e & 63;
        qs[d][r] = f2tf(q[((size_t)b * N_ + q0 + r) * C_ + head * HD_ + d]);
    }

    float m_i[2], l_i[2], oacc[8][4];
    m_i[0] = m_i[1] = -1e30f;
    l_i[0] = l_i[1] = 0.f;
#pragma unroll
    for (int ni = 0; ni < 8; ni++)
#pragma unroll
        for (int j = 0; j < 4; j++) oacc[ni][j] = 0.f;

    __syncthreads();

    const int nchunks = (nkv + 63) >> 6;
    for (int c0 = 0; c0 < nchunks; c0++) {
        int base = c0 * 64;
        int cs = nkv - base;
        if (cs > 64) cs = 64;
#pragma unroll
        for (int i = 0; i < 32; i++) {
            int e = tid + i * 128;
            int r = e >> 6, d = e & 63;
            if (r < cs) {
                size_t kidx = (size_t)b * nkv + base + r;
                kst[d][r] = f2tf(kvb[kidx * 128 + d]);
                vs[r][d]  = f2tf(v2b[kidx * 64 + d]);
            } else {
                kst[d][r] = 0u;
                vs[r][d]  = 0u;
            }
        }
        __syncthreads();

        float sacc[8][4];
#pragma unroll
        for (int ni = 0; ni < 8; ni++)
#pragma unroll
            for (int j = 0; j < 4; j++) sacc[ni][j] = 0.f;
#pragma unroll
        for (int kk = 0; kk < 64; kk += 8) {
            uint32_t af[4];
            af[0] = qs[kk + lc][rr];
            af[1] = qs[kk + lc][rr + 8];
            af[2] = qs[kk + 4 + lc][rr];
            af[3] = qs[kk + 4 + lc][rr + 8];
#pragma unroll
            for (int ni = 0; ni < 8; ni++) {
                uint32_t bf[2];
                int cc = ni * 8 + lr;
                bf[0] = kst[kk + lc][cc];
                bf[1] = kst[kk + 4 + lc][cc];
                mma_tf32(sacc[ni], af, bf);
            }
        }

#pragma unroll
        for (int h = 0; h < 2; h++) {
            float mx = -1e30f;
#pragma unroll
            for (int ni = 0; ni < 8; ni++)
#pragma unroll
                for (int j = 0; j < 2; j++) {
                    float v = sacc[ni][2 * h + j] * scale;
                    if (ni * 8 + 2 * lc + j >= cs) v = -1e30f;
                    sacc[ni][2 * h + j] = v;
                    mx = fmaxf(mx, v);
                }
            mx = fmaxf(mx, __shfl_xor_sync(0xffffffffu, mx, 1));
            mx = fmaxf(mx, __shfl_xor_sync(0xffffffffu, mx, 2));
            float mnew = fmaxf(m_i[h], mx);
            float alpha = __expf(m_i[h] - mnew);
            float rs = 0.f;
#pragma unroll
            for (int ni = 0; ni < 8; ni++)
#pragma unroll
                for (int j = 0; j < 2; j++) {
                    float p = __expf(sacc[ni][2 * h + j] - mnew);
                    sacc[ni][2 * h + j] = p;
                    rs += p;
                }
            rs += __shfl_xor_sync(0xffffffffu, rs, 1);
            rs += __shfl_xor_sync(0xffffffffu, rs, 2);
            l_i[h] = l_i[h] * alpha + rs;
            m_i[h] = mnew;
#pragma unroll
            for (int ni = 0; ni < 8; ni++) {
                oacc[ni][2 * h]     *= alpha;
                oacc[ni][2 * h + 1] *= alpha;
            }
        }

#pragma unroll
        for (int ni = 0; ni < 8; ni++) {
            int c = ni * 8 + 2 * lc;
            ps[c][rr]         = f2tf(sacc[ni][0]);
            ps[c + 1][rr]     = f2tf(sacc[ni][1]);
            ps[c][rr + 8]     = f2tf(sacc[ni][2]);
            ps[c + 1][rr + 8] = f2tf(sacc[ni][3]);
        }
        __syncwarp();

#pragma unroll
        for (int kk = 0; kk < 64; kk += 8) {
            uint32_t af[4];
            af[0] = ps[kk + lc][rr];
            af[1] = ps[kk + lc][rr + 8];
            af[2] = ps[kk + 4 + lc][rr];
            af[3] = ps[kk + 4 + lc][rr + 8];
#pragma unroll
            for (int ni = 0; ni < 8; ni++) {
                uint32_t bf[2];
                int cc = ni * 8 + lr;
                bf[0] = vs[kk + lc][cc];
                bf[1] = vs[kk + 4 + lc][cc];
                mma_tf32(oacc[ni], af, bf);
            }
        }
        __syncthreads();
    }

    float inv0 = 1.f / l_i[0], inv1 = 1.f / l_i[1];
#pragma unroll
    for (int ni = 0; ni < 8; ni++) {
        int col = head * HD_ + ni * 8 + 2 * lc;
        size_t r0 = (size_t)b * N_ + q0 + rr;
        *(__half2*)(xcath + r0 * C_ + col) =
            __floats2half2_rn(oacc[ni][0] * inv0, oacc[ni][1] * inv0);
        *(__half2*)(xcath + (r0 + 8) * C_ + col) =
            __floats2half2_rn(oacc[ni][2] * inv1, oacc[ni][3] * inv1);
    }
}

// =====================================================================================
// Host orchestration: 10 big launches. conv_all at profiled launch index 3.
// =====================================================================================
extern "C" void kernel_launch(void* const* d_in, const int* in_sizes, int n_in,
                              void* d_out, int out_size)
{
    const float* x   = (const float*)d_in[0];
    const float* Wq  = (const float*)d_in[1];
    const float* bq  = (const float*)d_in[2];
    const float* Wkv = (const float*)d_in[3];
    const float* bkv = (const float*)d_in[4];
    const float* Wo  = (const float*)d_in[23];
    const float* bo  = (const float*)d_in[24];

    float *q, *xr, *kvb, *v2;
    __half *xh, *xrh, *xcath, *wth, *wqh, *wkvh, *woh;
    cudaGetSymbolAddress((void**)&q, g_q);
    cudaGetSymbolAddress((void**)&xr, g_xr);
    cudaGetSymbolAddress((void**)&kvb, g_kv);
    cudaGetSymbolAddress((void**)&v2, g_v2);
    cudaGetSymbolAddress((void**)&xh, g_xh);
    cudaGetSymbolAddress((void**)&xrh, g_xrh);
    cudaGetSymbolAddress((void**)&xcath, g_xcath);
    cudaGetSymbolAddress((void**)&wth, g_wth);
    cudaGetSymbolAddress((void**)&wqh, g_wqh);
    cudaGetSymbolAddress((void**)&wkvh, g_wkvh);
    cudaGetSymbolAddress((void**)&woh, g_woh);

    const int attn_smem = 4 * 64 * TLD * (int)sizeof(uint32_t);
    cudaFuncSetAttribute(attn_all_kernel, cudaFuncAttributeMaxDynamicSharedMemorySize,
                         attn_smem);
    cudaFuncSetAttribute(gemm_tc_kernel, cudaFuncAttributeMaxDynamicSharedMemorySize,
                         PIPE_BYTES);
    cudaFuncSetAttribute(conv_all_kernel, cudaFuncAttributeMaxDynamicSharedMemorySize,
                         PIPE_BYTES);

    const int M = B_ * N_;
    const int NX = B_ * N_ * C_;
    const int CC = C_ * C_;

    // branch geometry
    const int sA = 41, sB = 45, sC = 47;
    const int nA = sA * sA, nB = sB * sB, nC = sC * sC;   // 1681, 2025, 2209
    const int oA = 0, oB = B_ * nA, oC = B_ * (nA + nB);  // row offsets
    const int rows = RTOT_;                                // 47320

    ConvP cp;
    cp.mb1 = (nA + 127) / 128;                 // 14
    cp.mb2 = cp.mb1 + (nB + 127) / 128;        // 30
    int nblk = cp.mb2 + (nC + 127) / 128;      // 48
    cp.s[0] = sA; cp.s[1] = sB; cp.s[2] = sC;
    cp.k[0] = 8;  cp.k[1] = 4;  cp.k[2] = 2;
    cp.w[0] = 0;  cp.w[1] = 64 * CC; cp.w[2] = 80 * CC;
    cp.o[0] = oA; cp.o[1] = oB; cp.o[2] = oC;
    cp.bias[0] = (const float*)d_in[6];
    cp.bias[1] = (const float*)d_in[12];
    cp.bias[2] = (const float*)d_in[18];

    LnP lp;
    lp.r1 = oB; lp.r2 = oC;
    lp.g[0] = (const float*)d_in[7];  lp.b[0] = (const float*)d_in[8];
    lp.g[1] = (const float*)d_in[13]; lp.b[1] = (const float*)d_in[14];
    lp.g[2] = (const float*)d_in[19]; lp.b[2] = (const float*)d_in[20];

    DwP dp;
    dp.e1 = oB * 64; dp.e2 = oC * 64;
    dp.s[0] = sA; dp.s[1] = sB; dp.s[2] = sC;
    dp.o[0] = oA; dp.o[1] = oB; dp.o[2] = oC;
    dp.w[0] = (const float*)d_in[9];  dp.c[0] = (const float*)d_in[10];
    dp.w[1] = (const float*)d_in[15]; dp.c[1] = (const float*)d_in[16];
    dp.w[2] = (const float*)d_in[21]; dp.c[2] = (const float*)d_in[22];

    AtP ap;
    ap.nkv[0] = nA; ap.nkv[1] = nB; ap.nkv[2] = nC;
    ap.o[0] = oA; ap.o[1] = oB; ap.o[2] = oC;

    // 0: x -> fp16
    cvt_x_kernel<<<(NX + 255) / 256, 256>>>(x, xh, NX);
    // 1: dense weights
    cvt_w_kernel<<<(3 * CC + 255) / 256, 256>>>(Wq, Wkv, Wo, wqh, wkvh, woh);
    // 2: all conv weights
    wtrans_all_kernel<<<512, 256>>>((const float*)d_in[5], (const float*)d_in[11],
                                    (const float*)d_in[17], wth);
    // 3 (PROFILED): all SR convs
    conv_all_kernel<<<dim3(nblk, 3, B_), 128, PIPE_BYTES>>>(xh, wth, xr, cp);
    // 4: Q projection
    gemm_tc_kernel<<<dim3((M + 127) / 128, 3), 256, PIPE_BYTES>>>(
        xh, wqh, bq, q, M, C_, C_);
    // 5: LN+GELU all rows
    ln_gelu_all_kernel<<<(rows + 7) / 8, 256>>>(xr, xrh, lp, rows);
    // 6: KV projection, all branches in one GEMM
    gemm_tc_kernel<<<dim3((rows + 127) / 128, 2), 256, PIPE_BYTES>>>(
        xrh, wkvh, bkv, kvb, rows, C_, 128);
    // 7: depthwise conv all branches
    dwconv_all_kernel<<<(rows * 64 + 255) / 256, 256>>>(kvb, v2, dp, rows * 64);
    // 8: attention, all 3 heads
    attn_all_kernel<<<dim3(N_ / 64, B_, 3), 128, attn_smem>>>(q, kvb, v2, xcath, ap);
    // 9: output projection
    gemm_tc_kernel<<<dim3((M + 127) / 128, 3), 256, PIPE_BYTES>>>(
        xcath, woh, bo, (float*)d_out, M, C_, C_);
}

// round 15
// speedup vs baseline: 5.5761x; 1.4542x over previous
#include <cuda_runtime.h>
#include <cuda_fp16.h>
#include <math.h>
#include <stdint.h>

#define B_    8
#define N_    2304
#define C_    192
#define HW_   48
#define HD_   64
#define NTOT_ 5915
#define RTOT_ (B_ * NTOT_)        // 47320

// ---------------- scratch ----------------
__device__ float  g_q[B_ * N_ * C_];
__device__ float  g_xr[RTOT_ * C_];
__device__ float  g_kv[RTOT_ * 128];
__device__ float  g_v2t[HD_ * RTOT_];        // TRANSPOSED: [d][row]
__device__ __half g_xh[B_ * N_ * C_];
__device__ __half g_xrh[RTOT_ * C_];
__device__ __half g_xcath[B_ * N_ * C_];
__device__ __half g_wth[C_ * C_ * 84];
__device__ __half g_wqh[C_ * C_];
__device__ __half g_wkvh[C_ * C_];
__device__ __half g_woh[C_ * C_];

// ---------------- helpers ----------------
__device__ __forceinline__ void mma_f16(float* d, const uint32_t* a, const uint32_t* b) {
    asm volatile(
        "mma.sync.aligned.m16n8k16.row.col.f32.f16.f16.f32 "
        "{%0,%1,%2,%3}, {%4,%5,%6,%7}, {%8,%9}, {%0,%1,%2,%3};"
        : "+f"(d[0]), "+f"(d[1]), "+f"(d[2]), "+f"(d[3])
        : "r"(a[0]), "r"(a[1]), "r"(a[2]), "r"(a[3]), "r"(b[0]), "r"(b[1]));
}
__device__ __forceinline__ void cp_async16(uint32_t dst, const void* src, uint32_t ssize) {
    asm volatile("cp.async.cg.shared.global [%0], [%1], 16, %2;"
                 :: "r"(dst), "l"(src), "r"(ssize) : "memory");
}
__device__ __forceinline__ void cp_commit() {
    asm volatile("cp.async.commit_group;" ::: "memory");
}
__device__ __forceinline__ void cp_wait1() {
    asm volatile("cp.async.wait_group 1;" ::: "memory");
}
__device__ __forceinline__ void cp_wait0() {
    asm volatile("cp.async.wait_group 0;" ::: "memory");
}
__device__ __forceinline__ uint32_t packh2(float a, float b) {
    __half2 h = __floats2half2_rn(a, b);
    return *(uint32_t*)&h;
}

// gemm tiles (BK=32, unchanged)
#define BK     32
#define TW     20
#define A_ST   (128 * TW)
#define W_ST   (64 * TW)
#define PIPE_BYTES (3 * (A_ST + W_ST) * 4)    // 46080
// conv tiles: BK=64, 2 stages
#define CTW    36
#define CA_ST  (128 * CTW)
#define CW_ST  (64 * CTW)
#define CPIPE_BYTES (2 * (CA_ST + CW_ST) * 4) // 55296

struct ConvP {
    int mb1, mb2;
    int s[3], k[3], w[3], o[3];
    const float* bias[3];
};
struct LnP {
    int r1, r2;
    const float *g[3], *b[3];
};
struct DwP {
    int e1, e2;
    int s[3], o[3];
    const float *w[3], *c[3];
};
struct AtP {
    int nkv[3], o[3];
};

// =====================================================================================
// Conversions
// =====================================================================================
__global__ void cvt_x_kernel(const float* __restrict__ in, __half* __restrict__ out, int n)
{
    int i = blockIdx.x * blockDim.x + threadIdx.x;
    if (i < n) out[i] = __float2half_rn(in[i]);
}

__global__ void cvt_w_kernel(const float* __restrict__ Wq, const float* __restrict__ Wkv,
                             const float* __restrict__ Wo, __half* __restrict__ wq,
                             __half* __restrict__ wkv, __half* __restrict__ wo)
{
    int i = blockIdx.x * blockDim.x + threadIdx.x;
    int total = 3 * C_ * C_;
    if (i >= total) return;
    int which = i / (C_ * C_);
    int r = i - which * (C_ * C_);
    int nn = r / C_, k = r - nn * C_;
    const float* src = (which == 0) ? Wq : (which == 1) ? Wkv : Wo;
    __half* dst = (which == 0) ? wq : (which == 1) ? wkv : wo;
    dst[nn * C_ + k] = __float2half_rn(src[(size_t)k * C_ + nn]);
}

__global__ void wtrans_all_kernel(const float* __restrict__ w1, const float* __restrict__ w2,
                                  const float* __restrict__ w3, __half* __restrict__ wt)
{
    const int CC = C_ * C_;
    int total = 84 * CC;
    for (int idx = blockIdx.x * blockDim.x + threadIdx.x; idx < total;
         idx += gridDim.x * blockDim.x) {
        const float* src;
        int rel, k2;
        if (idx < 64 * CC)      { src = w1; rel = idx;           k2 = 64; }
        else if (idx < 80 * CC) { src = w2; rel = idx - 64 * CC; k2 = 16; }
        else                    { src = w3; rel = idx - 80 * CC; k2 = 4;  }
        int ci = rel % C_;
        int rest = rel / C_;
        int co = rest % C_;
        int kyx = rest / C_;
        wt[idx] = __float2half_rn(src[((size_t)co * C_ + ci) * k2 + kyx]);
    }
}

// =====================================================================================
// Batched SR conv: BK=64, 2-stage cp.async. block 128x64, 4 warps (2m x 2n) of 64x32.
// =====================================================================================
__global__ __launch_bounds__(128) void conv_all_kernel(
    const __half* __restrict__ x, const __half* __restrict__ wtg,
    float* __restrict__ out, ConvP P)
{
    extern __shared__ uint32_t sm[];
    uint32_t* As = sm;                  // [2][128][CTW]
    uint32_t* Ws = sm + 2 * CA_ST;      // [2][64][CTW]

    const int tid = threadIdx.x;
    const int warp = tid >> 5, lane = tid & 31;
    const int wm = warp & 1, wn = warp >> 1;
    const int lr = lane >> 2, lc = lane & 3;
    const int b = blockIdx.z;
    const int n0 = blockIdx.y * 64;

    int bx = blockIdx.x;
    int br = (bx >= P.mb1) ? ((bx >= P.mb2) ? 2 : 1) : 0;
    int mblk = bx - ((br == 0) ? 0 : (br == 1) ? P.mb1 : P.mb2);
    const int s_ = P.s[br], ksz = P.k[br];
    const int n = s_ * s_;
    const int m0 = mblk * 128;
    const __half* wt = wtg + P.w[br];
    const float* bias = P.bias[br];
    float* ob = out + (size_t)(P.o[br]) * C_;

    const int prow8 = tid >> 3;         // 0..15
    const int ch = tid & 7;             // 16B chunk within 64-half row

    int rowoff[8];
    uint32_t amask = 0;
#pragma unroll
    for (int i = 0; i < 8; i++) {
        int p = m0 + prow8 + i * 16;
        if (p < n) amask |= (1u << i);
        int pp = (p < n) ? p : 0;
        rowoff[i] = ((pp / s_) * HW_ + (pp % s_)) * C_;
    }
    const __half* xb = x + (size_t)b * N_ * C_;

    const uint32_t asb = (uint32_t)__cvta_generic_to_shared(As);
    const uint32_t wsb = (uint32_t)__cvta_generic_to_shared(Ws);

    auto pf = [&](int kb, int st) {
        int kyx = kb / 3;
        int ci0 = (kb - kyx * 3) * 64;
        int ky = kyx / ksz, kx = kyx - ky * ksz;
        int koff = (ky * HW_ + kx) * C_ + ci0 + ch * 8;
#pragma unroll
        for (int i = 0; i < 8; i++)
            cp_async16(asb + (uint32_t)(((st * 128 + prow8 + i * 16) * CTW + ch * 4) * 4),
                       xb + rowoff[i] + koff,
                       ((amask >> i) & 1u) ? 16u : 0u);
        const __half* wp = wt + (size_t)kyx * C_ * C_ + ci0 + ch * 8;
#pragma unroll
        for (int i = 0; i < 4; i++) {
            int row = prow8 + i * 16;
            cp_async16(wsb + (uint32_t)(((st * 64 + row) * CTW + ch * 4) * 4),
                       wp + (size_t)(n0 + row) * C_, 16u);
        }
    };

    float acc[4][4][4];
#pragma unroll
    for (int mi = 0; mi < 4; mi++)
#pragma unroll
        for (int ni = 0; ni < 4; ni++)
#pragma unroll
            for (int j = 0; j < 4; j++) acc[mi][ni][j] = 0.f;

    const int KB = ksz * ksz * 3;
    pf(0, 0); cp_commit();

    for (int kb = 0; kb < KB; kb++) {
        int st = kb & 1;
        cp_wait0();
        __syncthreads();
        if (kb + 1 < KB) pf(kb + 1, st ^ 1);
        cp_commit();
        const uint32_t* as = As + st * CA_ST;
        const uint32_t* ws = Ws + st * CW_ST;
#pragma unroll
        for (int ks = 0; ks < 4; ks++) {
            int ksw = ks * 8;
            uint32_t af[4][4];
#pragma unroll
            for (int mi = 0; mi < 4; mi++) {
                int rr = wm * 64 + mi * 16 + lr;
                af[mi][0] = as[rr * CTW + ksw + lc];
                af[mi][1] = as[(rr + 8) * CTW + ksw + lc];
                af[mi][2] = as[rr * CTW + ksw + 4 + lc];
                af[mi][3] = as[(rr + 8) * CTW + ksw + 4 + lc];
            }
            uint32_t bf[4][2];
#pragma unroll
            for (int ni = 0; ni < 4; ni++) {
                int cc = wn * 32 + ni * 8 + lr;
                bf[ni][0] = ws[cc * CTW + ksw + lc];
                bf[ni][1] = ws[cc * CTW + ksw + 4 + lc];
            }
#pragma unroll
            for (int mi = 0; mi < 4; mi++)
#pragma unroll
                for (int ni = 0; ni < 4; ni++) mma_f16(acc[mi][ni], af[mi], bf[ni]);
        }
    }
#pragma unroll
    for (int mi = 0; mi < 4; mi++) {
        int row = m0 + wm * 64 + mi * 16 + lr;
#pragma unroll
        for (int ni = 0; ni < 4; ni++) {
            int col = n0 + wn * 32 + ni * 8 + lc * 2;
            float b0 = bias[col], b1 = bias[col + 1];
            if (row < n) {
                float* o = ob + ((size_t)b * n + row) * C_ + col;
                o[0] = acc[mi][ni][0] + b0;
                o[1] = acc[mi][ni][1] + b1;
            }
            if (row + 8 < n) {
                float* o = ob + ((size_t)b * n + row + 8) * C_ + col;
                o[0] = acc[mi][ni][2] + b0;
                o[1] = acc[mi][ni][3] + b1;
            }
        }
    }
}

// =====================================================================================
// FP16 TC GEMM (unchanged): tiles 128x64, 8 warps 32x32.
// =====================================================================================
__global__ __launch_bounds__(256) void gemm_tc_kernel(
    const __half* __restrict__ A, const __half* __restrict__ W,
    const float* __restrict__ bias, float* __restrict__ out,
    int M, int K, int ldc)
{
    extern __shared__ uint32_t sm[];
    uint32_t* As = sm;
    uint32_t* Ws = sm + 3 * A_ST;

    const int tid = threadIdx.x;
    const int warp = tid >> 5, lane = tid & 31;
    const int wm = warp & 3, wn = warp >> 2;
    const int lr = lane >> 2, lc = lane & 3;
    const int m0 = blockIdx.x * 128;
    const int n0 = blockIdx.y * 64;

    const int r6 = tid >> 2;
    const int chk = tid & 3;

    const __half* aPtr[2];
    uint32_t aSz[2];
#pragma unroll
    for (int i = 0; i < 2; i++) {
        int m = m0 + r6 + i * 64;
        aSz[i] = (m < M) ? 16u : 0u;
        aPtr[i] = A + (size_t)((m < M) ? m : 0) * K + chk * 8;
    }
    const __half* wPtr = W + (size_t)(n0 + r6) * K + chk * 8;

    const uint32_t asb = (uint32_t)__cvta_generic_to_shared(As);
    const uint32_t wsb = (uint32_t)__cvta_generic_to_shared(Ws);

    auto pf = [&](int kb, int st) {
        int k0 = kb * BK;
#pragma unroll
        for (int i = 0; i < 2; i++)
            cp_async16(asb + (uint32_t)(((st * 128 + r6 + i * 64) * TW + chk * 4) * 4),
                       aPtr[i] + k0, aSz[i]);
        cp_async16(wsb + (uint32_t)(((st * 64 + r6) * TW + chk * 4) * 4), wPtr + k0, 16u);
    };

    float acc[2][4][4];
#pragma unroll
    for (int mi = 0; mi < 2; mi++)
#pragma unroll
        for (int ni = 0; ni < 4; ni++)
#pragma unroll
            for (int j = 0; j < 4; j++) acc[mi][ni][j] = 0.f;

    const int KB = K / BK;
    pf(0, 0); cp_commit();
    pf(1, 1); cp_commit();

    int st = 0;
    for (int kb = 0; kb < KB; kb++) {
        if (kb + 1 < KB) cp_wait1(); else cp_wait0();
        __syncthreads();
        if (kb + 2 < KB) pf(kb + 2, (st + 2) % 3);
        cp_commit();
        const uint32_t* as = As + st * A_ST;
        const uint32_t* ws = Ws + st * W_ST;
#pragma unroll
        for (int ks = 0; ks < 2; ks++) {
            int ksw = ks * 8;
            uint32_t af[2][4];
#pragma unroll
            for (int mi = 0; mi < 2; mi++) {
                int rr = wm * 32 + mi * 16 + lr;
                af[mi][0] = as[rr * TW + ksw + lc];
                af[mi][1] = as[(rr + 8) * TW + ksw + lc];
                af[mi][2] = as[rr * TW + ksw + 4 + lc];
                af[mi][3] = as[(rr + 8) * TW + ksw + 4 + lc];
            }
            uint32_t bf[4][2];
#pragma unroll
            for (int ni = 0; ni < 4; ni++) {
                int cc = wn * 32 + ni * 8 + lr;
                bf[ni][0] = ws[cc * TW + ksw + lc];
                bf[ni][1] = ws[cc * TW + ksw + 4 + lc];
            }
#pragma unroll
            for (int mi = 0; mi < 2; mi++)
#pragma unroll
                for (int ni = 0; ni < 4; ni++) mma_f16(acc[mi][ni], af[mi], bf[ni]);
        }
        st = (st + 1) % 3;
    }
#pragma unroll
    for (int mi = 0; mi < 2; mi++) {
        int row = m0 + wm * 32 + mi * 16 + lr;
#pragma unroll
        for (int ni = 0; ni < 4; ni++) {
            int col = n0 + wn * 32 + ni * 8 + lc * 2;
            float b0 = bias[col], b1 = bias[col + 1];
            if (row < M) {
                out[(size_t)row * ldc + col]     = acc[mi][ni][0] + b0;
                out[(size_t)row * ldc + col + 1] = acc[mi][ni][1] + b1;
            }
            if (row + 8 < M) {
                out[(size_t)(row + 8) * ldc + col]     = acc[mi][ni][2] + b0;
                out[(size_t)(row + 8) * ldc + col + 1] = acc[mi][ni][3] + b1;
            }
        }
    }
}

// =====================================================================================
// Batched LayerNorm + exact GELU. One warp per row.
// =====================================================================================
__global__ void ln_gelu_all_kernel(const float* __restrict__ xr, __half* __restrict__ xrh,
                                   LnP P, int rows)
{
    int wid = (blockIdx.x * blockDim.x + threadIdx.x) >> 5;
    int lane = threadIdx.x & 31;
    if (wid >= rows) return;
    int br = (wid >= P.r1) ? ((wid >= P.r2) ? 2 : 1) : 0;
    const float* g = P.g[br];
    const float* bb = P.b[br];
    const float* row = xr + (size_t)wid * C_;
    __half* orow = xrh + (size_t)wid * C_;
    float s1 = 0.f, s2 = 0.f;
#pragma unroll
    for (int j = lane; j < C_; j += 32) {
        float v = row[j];
        s1 += v;
        s2 += v * v;
    }
#pragma unroll
    for (int o = 16; o; o >>= 1) {
        s1 += __shfl_xor_sync(0xffffffffu, s1, o);
        s2 += __shfl_xor_sync(0xffffffffu, s2, o);
    }
    float mu = s1 * (1.f / C_);
    float var = s2 * (1.f / C_) - mu * mu;
    float inv = rsqrtf(var + 1e-5f);
#pragma unroll
    for (int j = lane; j < C_; j += 32) {
        float v = (row[j] - mu) * inv * g[j] + bb[j];
        orow[j] = __float2half_rn(0.5f * v * (1.f + erff(v * 0.70710678118654752440f)));
    }
}

// =====================================================================================
// Batched depthwise 3x3 + residual; writes TRANSPOSED v2t[d][row].
// =====================================================================================
__global__ void dwconv_all_kernel(const float* __restrict__ kv, float* __restrict__ v2t,
                                  DwP P, int total)
{
    int idx = blockIdx.x * blockDim.x + threadIdx.x;
    if (idx >= total) return;
    int br = (idx >= P.e1) ? ((idx >= P.e2) ? 2 : 1) : 0;
    int local = idx - ((br == 0) ? 0 : (br == 1) ? P.e1 : P.e2);
    int s = P.s[br];
    int n = s * s;
    const float* w = P.w[br];
    const float* bias = P.c[br];
    int hd = local & 63;
    int p = (local >> 6) % n;
    int b = (local >> 6) / n;
    int y = p / s;
    int x0 = p - y * s;
    size_t base = (size_t)(P.o[br] + b * n);
    const float* vb = kv + base * 128 + 64 + hd;
    float acc = bias[hd];
#pragma unroll
    for (int dy = -1; dy <= 1; dy++) {
#pragma unroll
        for (int dx = -1; dx <= 1; dx++) {
            int yy = y + dy, xx = x0 + dx;
            if (yy >= 0 && yy < s && xx >= 0 && xx < s)
                acc += w[hd * 9 + (dy + 1) * 3 + (dx + 1)] * vb[(size_t)(yy * s + xx) * 128];
        }
    }
    v2t[(size_t)hd * RTOT_ + base + p] = acc + vb[(size_t)p * 128];
}

// =====================================================================================
// Batched flash attention, FULL FP16 MMA (m16n8k16), fp32 softmax/accum.
// Static smem: qs/kst [row|key][72 halves d-major], vs [d][72 halves key-major],
// ps [row][72 halves key-major]. All stride 36 words -> conflict-free frags.
// =====================================================================================
__global__ __launch_bounds__(128) void attn_all_kernel(
    const float* __restrict__ q, const float* __restrict__ kv,
    const float* __restrict__ v2t, __half* __restrict__ xcath, AtP P)
{
    __shared__ uint32_t qsw[64 * 36];
    __shared__ uint32_t kstw[64 * 36];
    __shared__ uint32_t vsw[64 * 36];
    __shared__ uint32_t psw[64 * 36];

    const int tid = threadIdx.x;
    const int warp = tid >> 5, lane = tid & 31;
    const int wm = warp;
    const int lr = lane >> 2, lc = lane & 3;
    const int b = blockIdx.y;
    const int head = blockIdx.z;
    const int q0 = blockIdx.x * 64;
    const int rr = wm * 16 + lr;
    const int nkv = P.nkv[head];
    const float* kvb = kv + (size_t)P.o[head] * 128;
    const float scale = 0.07216878364870322056f;  // 1/sqrt(192)

    // Q tile: rows q0..q0+63, 32 words of packed d
#pragma unroll
    for (int i = 0; i < 16; i++) {
        int e = tid + i * 128;
        int r = e >> 5, w = e & 31;
        const float* qp = q + ((size_t)b * N_ + q0 + r) * C_ + head * HD_ + 2 * w;
        float2 f = *(const float2*)qp;
        qsw[r * 36 + w] = packh2(f.x, f.y);
    }

    float m_i[2], l_i[2], oacc[8][4];
    m_i[0] = m_i[1] = -1e30f;
    l_i[0] = l_i[1] = 0.f;
#pragma unroll
    for (int ni = 0; ni < 8; ni++)
#pragma unroll
        for (int j = 0; j < 4; j++) oacc[ni][j] = 0.f;

    __syncthreads();

    const int nchunks = (nkv + 63) >> 6;
    for (int c0 = 0; c0 < nchunks; c0++) {
        int base = c0 * 64;
        int cs = nkv - base;
        if (cs > 64) cs = 64;
        // K: [key][d packed]
#pragma unroll
        for (int i = 0; i < 16; i++) {
            int e = tid + i * 128;
            int r = e >> 5, w = e & 31;
            uint32_t v = 0u;
            if (r < cs) {
                const float* kp = kvb + ((size_t)b * nkv + base + r) * 128 + 2 * w;
                float2 f = *(const float2*)kp;
                v = packh2(f.x, f.y);
            }
            kstw[r * 36 + w] = v;
        }
        // V: [d][key packed] from transposed v2t (scalar loads: parity of base varies)
        {
            const float* v2d = v2t + (size_t)P.o[head] + (size_t)b * nkv + base;
#pragma unroll
            for (int i = 0; i < 16; i++) {
                int e = tid + i * 128;
                int d = e >> 5, w = e & 31;
                int k0 = 2 * w, k1 = 2 * w + 1;
                const float* vp = v2d + (size_t)d * RTOT_;
                float f0 = (k0 < cs) ? vp[k0] : 0.f;
                float f1 = (k1 < cs) ? vp[k1] : 0.f;
                vsw[d * 36 + w] = packh2(f0, f1);
            }
        }
        __syncthreads();

        // S = Q @ K^T : 4 k16-steps
        float sacc[8][4];
#pragma unroll
        for (int ni = 0; ni < 8; ni++)
#pragma unroll
            for (int j = 0; j < 4; j++) sacc[ni][j] = 0.f;
#pragma unroll
        for (int ks = 0; ks < 4; ks++) {
            int ksw = ks * 8;
            uint32_t af[4];
            af[0] = qsw[rr * 36 + ksw + lc];
            af[1] = qsw[(rr + 8) * 36 + ksw + lc];
            af[2] = qsw[rr * 36 + ksw + 4 + lc];
            af[3] = qsw[(rr + 8) * 36 + ksw + 4 + lc];
#pragma unroll
            for (int ni = 0; ni < 8; ni++) {
                int cc = ni * 8 + lr;
                uint32_t bf[2];
                bf[0] = kstw[cc * 36 + ksw + lc];
                bf[1] = kstw[cc * 36 + ksw + 4 + lc];
                mma_f16(sacc[ni], af, bf);
            }
        }

        // online softmax (rows rr and rr+8)
#pragma unroll
        for (int h = 0; h < 2; h++) {
            float mx = -1e30f;
#pragma unroll
            for (int ni = 0; ni < 8; ni++)
#pragma unroll
                for (int j = 0; j < 2; j++) {
                    float v = sacc[ni][2 * h + j] * scale;
                    if (ni * 8 + 2 * lc + j >= cs) v = -1e30f;
                    sacc[ni][2 * h + j] = v;
                    mx = fmaxf(mx, v);
                }
            mx = fmaxf(mx, __shfl_xor_sync(0xffffffffu, mx, 1));
            mx = fmaxf(mx, __shfl_xor_sync(0xffffffffu, mx, 2));
            float mnew = fmaxf(m_i[h], mx);
            float alpha = __expf(m_i[h] - mnew);
            float rs = 0.f;
#pragma unroll
            for (int ni = 0; ni < 8; ni++)
#pragma unroll
                for (int j = 0; j < 2; j++) {
                    float p = __expf(sacc[ni][2 * h + j] - mnew);
                    sacc[ni][2 * h + j] = p;
                    rs += p;
                }
            rs += __shfl_xor_sync(0xffffffffu, rs, 1);
            rs += __shfl_xor_sync(0xffffffffu, rs, 2);
            l_i[h] = l_i[h] * alpha + rs;
            m_i[h] = mnew;
#pragma unroll
            for (int ni = 0; ni < 8; ni++) {
                oacc[ni][2 * h]     *= alpha;
                oacc[ni][2 * h + 1] *= alpha;
            }
        }

        // P -> smem as packed half2 (A operand of P@V); warp-private rows
#pragma unroll
        for (int ni = 0; ni < 8; ni++) {
            int wdx = ni * 4 + lc;
            psw[rr * 36 + wdx]       = packh2(sacc[ni][0], sacc[ni][1]);
            psw[(rr + 8) * 36 + wdx] = packh2(sacc[ni][2], sacc[ni][3]);
        }
        __syncwarp();

        // O += P @ V : 4 k16-steps over keys
#pragma unroll
        for (int ks = 0; ks < 4; ks++) {
            int ksw = ks * 8;
            uint32_t af[4];
            af[0] = psw[rr * 36 + ksw + lc];
            af[1] = psw[(rr + 8) * 36 + ksw + lc];
            af[2] = psw[rr * 36 + ksw + 4 + lc];
            af[3] = psw[(rr + 8) * 36 + ksw + 4 + lc];
#pragma unroll
            for (int ni = 0; ni < 8; ni++) {
                int cc = ni * 8 + lr;
                uint32_t bf[2];
                bf[0] = vsw[cc * 36 + ksw + lc];
                bf[1] = vsw[cc * 36 + ksw + 4 + lc];
                mma_f16(oacc[ni], af, bf);
            }
        }
        __syncthreads();
    }

    float inv0 = 1.f / l_i[0], inv1 = 1.f / l_i[1];
#pragma unroll
    for (int ni = 0; ni < 8; ni++) {
        int col = head * HD_ + ni * 8 + 2 * lc;
        size_t r0 = (size_t)b * N_ + q0 + rr;
        *(__half2*)(xcath + r0 * C_ + col) =
            __floats2half2_rn(oacc[ni][0] * inv0, oacc[ni][1] * inv0);
        *(__half2*)(xcath + (r0 + 8) * C_ + col) =
            __floats2half2_rn(oacc[ni][2] * inv1, oacc[ni][3] * inv1);
    }
}

// =====================================================================================
// Host orchestration: conv_all at profiled launch index 3.
// =====================================================================================
extern "C" void kernel_launch(void* const* d_in, const int* in_sizes, int n_in,
                              void* d_out, int out_size)
{
    const float* x   = (const float*)d_in[0];
    const float* Wq  = (const float*)d_in[1];
    const float* bq  = (const float*)d_in[2];
    const float* Wkv = (const float*)d_in[3];
    const float* bkv = (const float*)d_in[4];
    const float* Wo  = (const float*)d_in[23];
    const float* bo  = (const float*)d_in[24];

    float *q, *xr, *kvb, *v2t;
    __half *xh, *xrh, *xcath, *wth, *wqh, *wkvh, *woh;
    cudaGetSymbolAddress((void**)&q, g_q);
    cudaGetSymbolAddress((void**)&xr, g_xr);
    cudaGetSymbolAddress((void**)&kvb, g_kv);
    cudaGetSymbolAddress((void**)&v2t, g_v2t);
    cudaGetSymbolAddress((void**)&xh, g_xh);
    cudaGetSymbolAddress((void**)&xrh, g_xrh);
    cudaGetSymbolAddress((void**)&xcath, g_xcath);
    cudaGetSymbolAddress((void**)&wth, g_wth);
    cudaGetSymbolAddress((void**)&wqh, g_wqh);
    cudaGetSymbolAddress((void**)&wkvh, g_wkvh);
    cudaGetSymbolAddress((void**)&woh, g_woh);

    cudaFuncSetAttribute(gemm_tc_kernel, cudaFuncAttributeMaxDynamicSharedMemorySize,
                         PIPE_BYTES);
    cudaFuncSetAttribute(conv_all_kernel, cudaFuncAttributeMaxDynamicSharedMemorySize,
                         CPIPE_BYTES);

    const int M = B_ * N_;
    const int NX = B_ * N_ * C_;
    const int CC = C_ * C_;

    const int sA = 41, sB = 45, sC = 47;
    const int nA = sA * sA, nB = sB * sB, nC = sC * sC;
    const int oA = 0, oB = B_ * nA, oC = B_ * (nA + nB);
    const int rows = RTOT_;

    ConvP cp;
    cp.mb1 = (nA + 127) / 128;
    cp.mb2 = cp.mb1 + (nB + 127) / 128;
    int nblk = cp.mb2 + (nC + 127) / 128;
    cp.s[0] = sA; cp.s[1] = sB; cp.s[2] = sC;
    cp.k[0] = 8;  cp.k[1] = 4;  cp.k[2] = 2;
    cp.w[0] = 0;  cp.w[1] = 64 * CC; cp.w[2] = 80 * CC;
    cp.o[0] = oA; cp.o[1] = oB; cp.o[2] = oC;
    cp.bias[0] = (const float*)d_in[6];
    cp.bias[1] = (const float*)d_in[12];
    cp.bias[2] = (const float*)d_in[18];

    LnP lp;
    lp.r1 = oB; lp.r2 = oC;
    lp.g[0] = (const float*)d_in[7];  lp.b[0] = (const float*)d_in[8];
    lp.g[1] = (const float*)d_in[13]; lp.b[1] = (const float*)d_in[14];
    lp.g[2] = (const float*)d_in[19]; lp.b[2] = (const float*)d_in[20];

    DwP dp;
    dp.e1 = oB * 64; dp.e2 = oC * 64;
    dp.s[0] = sA; dp.s[1] = sB; dp.s[2] = sC;
    dp.o[0] = oA; dp.o[1] = oB; dp.o[2] = oC;
    dp.w[0] = (const float*)d_in[9];  dp.c[0] = (const float*)d_in[10];
    dp.w[1] = (const float*)d_in[15]; dp.c[1] = (const float*)d_in[16];
    dp.w[2] = (const float*)d_in[21]; dp.c[2] = (const float*)d_in[22];

    AtP ap;
    ap.nkv[0] = nA; ap.nkv[1] = nB; ap.nkv[2] = nC;
    ap.o[0] = oA; ap.o[1] = oB; ap.o[2] = oC;

    // 0
    cvt_x_kernel<<<(NX + 255) / 256, 256>>>(x, xh, NX);
    // 1
    cvt_w_kernel<<<(3 * CC + 255) / 256, 256>>>(Wq, Wkv, Wo, wqh, wkvh, woh);
    // 2
    wtrans_all_kernel<<<512, 256>>>((const float*)d_in[5], (const float*)d_in[11],
                                    (const float*)d_in[17], wth);
    // 3 (PROFILED): all SR convs
    conv_all_kernel<<<dim3(nblk, 3, B_), 128, CPIPE_BYTES>>>(xh, wth, xr, cp);
    // 4
    gemm_tc_kernel<<<dim3((M + 127) / 128, 3), 256, PIPE_BYTES>>>(
        xh, wqh, bq, q, M, C_, C_);
    // 5
    ln_gelu_all_kernel<<<(rows + 7) / 8, 256>>>(xr, xrh, lp, rows);
    // 6
    gemm_tc_kernel<<<dim3((rows + 127) / 128, 2), 256, PIPE_BYTES>>>(
        xrh, wkvh, bkv, kvb, rows, C_, 128);
    // 7
    dwconv_all_kernel<<<(rows * 64 + 255) / 256, 256>>>(kvb, v2t, dp, rows * 64);
    // 8
    attn_all_kernel<<<dim3(N_ / 64, B_, 3), 128>>>(q, kvb, v2t, xcath, ap);
    // 9
    gemm_tc_kernel<<<dim3((M + 127) / 128, 3), 256, PIPE_BYTES>>>(
        xcath, woh, bo, (float*)d_out, M, C_, C_);
}